// round 11
// baseline (speedup 1.0000x reference)
#include <cuda_runtime.h>
#include <cuda_bf16.h>
#include <math.h>

// ---------------------------------------------------------------------------
// FPGNN forward. R11:
//  - big GEMMs (Wh, Wx): 1x tf32 mma.sync
//  - attn1/attn2: tf32 mma with 32-col B-chunks (smem 55KB -> 4 CTAs/SM)
//  - tail GEMMs: exact fp32 FFMA2, 64x64 tiles
// ---------------------------------------------------------------------------

#define Bq 512
#define Nn 128
#define F_IN 133
#define NHEADS 8
#define NHID 64
#define HID 512
#define FP_DIM 1489
#define TASKS 12

typedef unsigned long long u64;
typedef unsigned int u32;

__device__ __forceinline__ u64 pack2(float lo, float hi) {
    u64 r; asm("mov.b64 %0, {%1,%2};" : "=l"(r) : "f"(lo), "f"(hi)); return r;
}
__device__ __forceinline__ u64 dup2(float v) { return pack2(v, v); }
__device__ __forceinline__ void fma2(u64& d, u64 a, u64 b) {
    asm("fma.rn.f32x2 %0, %1, %2, %0;" : "+l"(d) : "l"(a), "l"(b));
}
__device__ __forceinline__ float2 upk2(u64 v) {
    float2 r; asm("mov.b64 {%0,%1}, %2;" : "=f"(r.x), "=f"(r.y) : "l"(v)); return r;
}
__device__ __forceinline__ u32 to_tf32(float f) {
    u32 r; asm("cvt.rna.tf32.f32 %0, %1;" : "=r"(r) : "f"(f)); return r;
}
__device__ __forceinline__ void mma_tf32(float* d, const u32* a, const u32* b) {
    asm volatile(
        "mma.sync.aligned.m16n8k8.row.col.f32.tf32.tf32.f32 "
        "{%0,%1,%2,%3}, {%4,%5,%6,%7}, {%8,%9}, {%0,%1,%2,%3};\n"
        : "+f"(d[0]), "+f"(d[1]), "+f"(d[2]), "+f"(d[3])
        : "r"(a[0]), "r"(a[1]), "r"(a[2]), "r"(a[3]), "r"(b[0]), "r"(b[1]));
}
__device__ __forceinline__ float elu1(float v) {
    return v > 0.f ? v : (__expf(v) - 1.f);
}

// ---- scratch (device globals; no allocation allowed) ----
__device__ float g_Wcat[F_IN * HID];
__device__ float g_Wh[(size_t)Bq * Nn * HID];
__device__ float g_s1[Bq * NHEADS * Nn];
__device__ float g_s2[Bq * NHEADS * Nn];
__device__ float g_x[(size_t)Bq * Nn * HID];
__device__ float g_Wx[(size_t)Bq * Nn * HID];
__device__ float g_t1[Bq * Nn];
__device__ float g_t2[Bq * Nn];
__device__ float g_gatp[Bq * 2 * HID];
__device__ float g_gat[Bq * HID];
__device__ float g_fpnh[Bq * HID];
__device__ float g_fpn[Bq * HID];
__device__ float g_buf1[Bq * HID];
__device__ float g_buf2[Bq * HID];

// ---------------------------------------------------------------------------
// 1x tf32 GEMM (fast path, big GEMMs). Validated R8.
// flags: 1 = bias, 2 = relu, 4 = accumulate
// ---------------------------------------------------------------------------
#define SA_STRIDE 20
#define SB_STRIDE 136

__global__ __launch_bounds__(256) void sgemm_tc_kernel(
    const float* __restrict__ A, const float* __restrict__ B,
    const float* __restrict__ bias, float* __restrict__ C,
    int M, int N, int K, int flags)
{
    __shared__ u32 sA[2][128 * SA_STRIDE];
    __shared__ u32 sB[2][16 * SB_STRIDE];

    int tid = threadIdx.x;
    int warp = tid >> 5, lane = tid & 31;
    int wr = warp >> 2, wc = warp & 3;
    int bm = blockIdx.y * 128;
    int bn = blockIdx.x * 128;
    int lr4 = lane >> 2, lc4 = lane & 3;

    float acc[4][4][4];
#pragma unroll
    for (int mt = 0; mt < 4; mt++)
#pragma unroll
        for (int nt = 0; nt < 4; nt++)
#pragma unroll
            for (int i = 0; i < 4; i++) acc[mt][nt][i] = 0.f;

    const int Ktiles = (K + 15) / 16;
    int aRow0 = tid >> 2,         aK0 = (tid & 3) * 4;
    int aRow1 = (tid + 256) >> 2, aK1 = ((tid + 256) & 3) * 4;
    int bK0 = tid >> 5,           bN0 = (tid & 31) * 4;
    int bK1 = (tid + 256) >> 5,   bN1 = ((tid + 256) & 31) * 4;

    float ar[2][4], br[2][4];
    {
#pragma unroll
        for (int i = 0; i < 4; i++) {
            int k = aK0 + i;
            ar[0][i] = (k < K) ? A[(size_t)(bm + aRow0) * K + k] : 0.f;
            k = aK1 + i;
            ar[1][i] = (k < K) ? A[(size_t)(bm + aRow1) * K + k] : 0.f;
        }
        if (bK0 < K) *(float4*)br[0] = *(const float4*)(B + (size_t)bK0 * N + bn + bN0);
        else { br[0][0] = br[0][1] = br[0][2] = br[0][3] = 0.f; }
        if (bK1 < K) *(float4*)br[1] = *(const float4*)(B + (size_t)bK1 * N + bn + bN1);
        else { br[1][0] = br[1][1] = br[1][2] = br[1][3] = 0.f; }
    }
#pragma unroll
    for (int i = 0; i < 4; i++) {
        sA[0][aRow0 * SA_STRIDE + aK0 + i] = to_tf32(ar[0][i]);
        sA[0][aRow1 * SA_STRIDE + aK1 + i] = to_tf32(ar[1][i]);
        sB[0][bK0 * SB_STRIDE + bN0 + i] = to_tf32(br[0][i]);
        sB[0][bK1 * SB_STRIDE + bN1 + i] = to_tf32(br[1][i]);
    }
    __syncthreads();

    int buf = 0;
    for (int t = 0; t < Ktiles; t++) {
        bool has_next = (t + 1 < Ktiles);
        if (has_next) {
            int k0 = (t + 1) * 16;
#pragma unroll
            for (int i = 0; i < 4; i++) {
                int k = k0 + aK0 + i;
                ar[0][i] = (k < K) ? A[(size_t)(bm + aRow0) * K + k] : 0.f;
                k = k0 + aK1 + i;
                ar[1][i] = (k < K) ? A[(size_t)(bm + aRow1) * K + k] : 0.f;
            }
            int k = k0 + bK0;
            if (k < K) *(float4*)br[0] = *(const float4*)(B + (size_t)k * N + bn + bN0);
            else { br[0][0] = br[0][1] = br[0][2] = br[0][3] = 0.f; }
            k = k0 + bK1;
            if (k < K) *(float4*)br[1] = *(const float4*)(B + (size_t)k * N + bn + bN1);
            else { br[1][0] = br[1][1] = br[1][2] = br[1][3] = 0.f; }
        }

        const u32* cA = sA[buf];
        const u32* cB = sB[buf];
#pragma unroll
        for (int kk = 0; kk < 16; kk += 8) {
            u32 afr[4][4], bfr[4][2];
#pragma unroll
            for (int mt = 0; mt < 4; mt++) {
                int r0 = wr * 64 + mt * 16 + lr4;
                int c0 = kk + lc4;
                afr[mt][0] = cA[r0 * SA_STRIDE + c0];
                afr[mt][1] = cA[(r0 + 8) * SA_STRIDE + c0];
                afr[mt][2] = cA[r0 * SA_STRIDE + c0 + 4];
                afr[mt][3] = cA[(r0 + 8) * SA_STRIDE + c0 + 4];
            }
#pragma unroll
            for (int nt = 0; nt < 4; nt++) {
                int col = wc * 32 + nt * 8 + lr4;
                bfr[nt][0] = cB[(kk + lc4) * SB_STRIDE + col];
                bfr[nt][1] = cB[(kk + lc4 + 4) * SB_STRIDE + col];
            }
#pragma unroll
            for (int mt = 0; mt < 4; mt++)
#pragma unroll
                for (int nt = 0; nt < 4; nt++)
                    mma_tf32(acc[mt][nt], afr[mt], bfr[nt]);
        }

        if (has_next) {
#pragma unroll
            for (int i = 0; i < 4; i++) {
                sA[buf ^ 1][aRow0 * SA_STRIDE + aK0 + i] = to_tf32(ar[0][i]);
                sA[buf ^ 1][aRow1 * SA_STRIDE + aK1 + i] = to_tf32(ar[1][i]);
                sB[buf ^ 1][bK0 * SB_STRIDE + bN0 + i] = to_tf32(br[0][i]);
                sB[buf ^ 1][bK1 * SB_STRIDE + bN1 + i] = to_tf32(br[1][i]);
            }
        }
        __syncthreads();
        buf ^= 1;
    }

#pragma unroll
    for (int mt = 0; mt < 4; mt++) {
#pragma unroll
        for (int nt = 0; nt < 4; nt++) {
            int col = bn + wc * 32 + nt * 8 + lc4 * 2;
#pragma unroll
            for (int half = 0; half < 2; half++) {
                int row = bm + wr * 64 + mt * 16 + lr4 + half * 8;
                float2 v = make_float2(acc[mt][nt][half * 2],
                                       acc[mt][nt][half * 2 + 1]);
                if (flags & 4) {
                    float2 c = *(const float2*)&C[(size_t)row * N + col];
                    v.x += c.x; v.y += c.y;
                }
                if (flags & 1) { v.x += bias[col]; v.y += bias[col + 1]; }
                if (flags & 2) { v.x = fmaxf(v.x, 0.f); v.y = fmaxf(v.y, 0.f); }
                *(float2*)&C[(size_t)row * N + col] = v;
            }
        }
    }
}

// ---------------------------------------------------------------------------
// Tail fp32 GEMM (exact): BM=BN=64, BK=16, 256 threads. Validated R10.
// ---------------------------------------------------------------------------
__global__ __launch_bounds__(256) void tail_gemm_kernel(
    const float* __restrict__ A, const float* __restrict__ B,
    const float* __restrict__ bias, float* __restrict__ C,
    int M, int N, int K, int flags)
{
    __shared__ float As[2][16][64];
    __shared__ float Bs[2][16][64];

    int tid = threadIdx.x;
    int bm = blockIdx.y * 64;
    int bn = blockIdx.x * 64;
    int tx = tid & 15;
    int ty = tid >> 4;

    int aRow = tid >> 2, aK = (tid & 3) * 4;
    int bK = tid >> 4, bN = (tid & 15) * 4;

    u64 acc[4][2];
#pragma unroll
    for (int i = 0; i < 4; i++) { acc[i][0] = 0ull; acc[i][1] = 0ull; }

    const int Ktiles = (K + 15) / 16;
    const float* Arow = A + (size_t)(bm + aRow) * K;

    {
#pragma unroll
        for (int i = 0; i < 4; i++) {
            int k = aK + i;
            As[0][aK + i][aRow] = (k < K) ? Arow[k] : 0.f;
        }
        float4 v = make_float4(0.f, 0.f, 0.f, 0.f);
        if (bK < K) v = *(const float4*)(B + (size_t)bK * N + bn + bN);
        *(float4*)&Bs[0][bK][bN] = v;
    }
    __syncthreads();

    int buf = 0;
    for (int t = 0; t < Ktiles; t++) {
        float ap[4];
        float4 bp = make_float4(0.f, 0.f, 0.f, 0.f);
        bool has_next = (t + 1 < Ktiles);
        if (has_next) {
            int k0 = (t + 1) * 16;
#pragma unroll
            for (int i = 0; i < 4; i++) {
                int k = k0 + aK + i;
                ap[i] = (k < K) ? Arow[k] : 0.f;
            }
            int k = k0 + bK;
            if (k < K) bp = *(const float4*)(B + (size_t)k * N + bn + bN);
        }

#pragma unroll
        for (int kk = 0; kk < 16; kk++) {
            u64 b0 = *(const u64*)&Bs[buf][kk][tx * 4];
            u64 b1 = *(const u64*)&Bs[buf][kk][tx * 4 + 2];
            float a0 = As[buf][kk][ty * 4];
            float a1 = As[buf][kk][ty * 4 + 1];
            float a2 = As[buf][kk][ty * 4 + 2];
            float a3 = As[buf][kk][ty * 4 + 3];
            u64 d0 = dup2(a0), d1 = dup2(a1), d2 = dup2(a2), d3 = dup2(a3);
            fma2(acc[0][0], d0, b0); fma2(acc[0][1], d0, b1);
            fma2(acc[1][0], d1, b0); fma2(acc[1][1], d1, b1);
            fma2(acc[2][0], d2, b0); fma2(acc[2][1], d2, b1);
            fma2(acc[3][0], d3, b0); fma2(acc[3][1], d3, b1);
        }

        if (has_next) {
#pragma unroll
            for (int i = 0; i < 4; i++) As[buf ^ 1][aK + i][aRow] = ap[i];
            *(float4*)&Bs[buf ^ 1][bK][bN] = bp;
        }
        __syncthreads();
        buf ^= 1;
    }

#pragma unroll
    for (int i = 0; i < 4; i++) {
        int row = bm + ty * 4 + i;
#pragma unroll
        for (int j = 0; j < 2; j++) {
            int col = bn + tx * 4 + j * 2;
            float2 v = upk2(acc[i][j]);
            if (flags & 4) {
                float2 c = *(const float2*)&C[(size_t)row * N + col];
                v.x += c.x; v.y += c.y;
            }
            if (flags & 1) { v.x += bias[col]; v.y += bias[col + 1]; }
            if (flags & 2) { v.x = fmaxf(v.x, 0.f); v.y = fmaxf(v.y, 0.f); }
            *(float2*)&C[(size_t)row * N + col] = v;
        }
    }
}

// ---------------------------------------------------------------------------
__global__ void wcat_kernel(const float* __restrict__ W_heads)
{
    int idx = blockIdx.x * blockDim.x + threadIdx.x;
    if (idx >= NHEADS * F_IN * NHID) return;
    int h = idx / (F_IN * NHID);
    int rem = idx - h * (F_IN * NHID);
    int f = rem / NHID;
    int d = rem - f * NHID;
    g_Wcat[f * HID + h * NHID + d] = W_heads[idx];
}

// ---------------------------------------------------------------------------
__global__ __launch_bounds__(256) void s12_kernel(
    const float* __restrict__ a1, const float* __restrict__ a2)
{
    int gw = (blockIdx.x * blockDim.x + threadIdx.x) >> 5;
    int lane = threadIdx.x & 31;
    if (gw >= Bq * NHEADS * Nn) return;
    int n  = gw & 127;
    int hh = (gw >> 7) & 7;
    int b  = gw >> 10;
    const float* row = g_Wh + ((size_t)b * Nn + n) * HID + hh * NHID;
    const float* av1 = a1 + hh * NHID;
    const float* av2 = a2 + hh * NHID;
    float x0 = row[lane], x1 = row[lane + 32];
    float r1 = x0 * av1[lane] + x1 * av1[lane + 32];
    float r2 = x0 * av2[lane] + x1 * av2[lane + 32];
#pragma unroll
    for (int o = 16; o; o >>= 1) {
        r1 += __shfl_xor_sync(0xffffffffu, r1, o);
        r2 += __shfl_xor_sync(0xffffffffu, r2, o);
    }
    if (lane == 0) {
        int o = (b * NHEADS + hh) * Nn + n;
        g_s1[o] = r1;
        g_s2[o] = r2;
    }
}

// ---------------------------------------------------------------------------
__global__ __launch_bounds__(256) void t12_kernel(
    const float* __restrict__ a1, const float* __restrict__ a2)
{
    int gw = (blockIdx.x * blockDim.x + threadIdx.x) >> 5;
    int lane = threadIdx.x & 31;
    if (gw >= Bq * Nn) return;
    const float* row = g_Wx + (size_t)gw * HID;
    float r1 = 0.f, r2 = 0.f;
#pragma unroll
    for (int c0 = 0; c0 < HID; c0 += 128) {
        float4 v = *(const float4*)(row + c0 + lane * 4);
        float4 w1 = *(const float4*)(a1 + c0 + lane * 4);
        float4 w2 = *(const float4*)(a2 + c0 + lane * 4);
        r1 += v.x * w1.x + v.y * w1.y + v.z * w1.z + v.w * w1.w;
        r2 += v.x * w2.x + v.y * w2.y + v.z * w2.z + v.w * w2.w;
    }
#pragma unroll
    for (int o = 16; o; o >>= 1) {
        r1 += __shfl_xor_sync(0xffffffffu, r1, o);
        r2 += __shfl_xor_sync(0xffffffffu, r2, o);
    }
    if (lane == 0) { g_t1[gw] = r1; g_t2[gw] = r2; }
}

// ---------------------------------------------------------------------------
// attn1 (tf32 mma, 32-col B-chunks): block = (bh, half). 64 att rows.
// smem: sWh [128][40] (per chunk) + sAtt [64][132] + ss1/ss2 = 55.0 KB
// -> 4 CTAs/SM. Bank checks: B-frag bank = (8*lc4 + col) % 32 distinct;
// A-frag bank = (4*lr4 + lc4) distinct.
// ---------------------------------------------------------------------------
#define WCH_STR 40
#define AT_STR 132

__global__ __launch_bounds__(256) void attn1_kernel(
    const float* __restrict__ ae_heads, const int* __restrict__ adj,
    const float* __restrict__ edge)
{
    extern __shared__ u32 smu[];
    u32* sWh  = smu;                        // 128*40
    u32* sAtt = smu + 128 * WCH_STR;        // 64*132
    float* ss1 = (float*)(smu + 128 * WCH_STR + 64 * AT_STR);  // 64
    float* ss2 = ss1 + 64;                                      // 128

    int tid = threadIdx.x;
    int blk = blockIdx.x;
    int hb = blk & 1;
    int bh = blk >> 1;
    int hh = bh & 7, b = bh >> 3;
    int i0 = hb * 64;
    float ae = ae_heads[hh];

    if (tid < 64)  ss1[tid] = g_s1[bh * Nn + i0 + tid];
    if (tid < 128) ss2[tid] = g_s2[bh * Nn + tid];
    __syncthreads();

    int warp = tid >> 5, lane = tid & 31;
    for (int i = warp; i < 64; i += 8) {
        int row = i0 + i;
        float4 ef = ((const float4*)(edge + ((size_t)b * Nn + row) * Nn))[lane];
        int4  av  = ((const int4*)(adj  + ((size_t)b * Nn + row) * Nn))[lane];
        float si = ss1[i];
        int j0 = lane * 4;
        float v0 = si + ss2[j0 + 0] + ef.x * ae; v0 = v0 >= 0.f ? v0 : 0.2f * v0; v0 = av.x > 0 ? v0 : -9e15f;
        float v1 = si + ss2[j0 + 1] + ef.y * ae; v1 = v1 >= 0.f ? v1 : 0.2f * v1; v1 = av.y > 0 ? v1 : -9e15f;
        float v2 = si + ss2[j0 + 2] + ef.z * ae; v2 = v2 >= 0.f ? v2 : 0.2f * v2; v2 = av.z > 0 ? v2 : -9e15f;
        float v3 = si + ss2[j0 + 3] + ef.w * ae; v3 = v3 >= 0.f ? v3 : 0.2f * v3; v3 = av.w > 0 ? v3 : -9e15f;
        float m = fmaxf(fmaxf(v0, v1), fmaxf(v2, v3));
#pragma unroll
        for (int o = 16; o; o >>= 1) m = fmaxf(m, __shfl_xor_sync(0xffffffffu, m, o));
        float e0 = __expf(v0 - m), e1 = __expf(v1 - m), e2 = __expf(v2 - m), e3 = __expf(v3 - m);
        float s = e0 + e1 + e2 + e3;
#pragma unroll
        for (int o = 16; o; o >>= 1) s += __shfl_xor_sync(0xffffffffu, s, o);
        float inv = 1.f / s;
        uint4 o4;
        o4.x = to_tf32(e0 * inv); o4.y = to_tf32(e1 * inv);
        o4.z = to_tf32(e2 * inv); o4.w = to_tf32(e3 * inv);
        *(uint4*)&sAtt[i * AT_STR + lane * 4] = o4;
    }

    int wr = warp >> 2, wc = warp & 3;      // 2 x 4; warp tile 32(M) x 8(N)
    int lr4 = lane >> 2, lc4 = lane & 3;

    const float* whp = g_Wh + (size_t)b * Nn * HID + hh * NHID;

#pragma unroll
    for (int ch = 0; ch < 2; ch++) {
        __syncthreads();   // guards sAtt (ch=0) and sWh reuse (ch=1)
        // load Wh chunk [128 x 32] as tf32
        for (int i = tid; i < 128 * 8; i += 256) {
            int r = i >> 3, c = (i & 7) * 4;
            float4 v = *(const float4*)(whp + (size_t)r * HID + ch * 32 + c);
            uint4 t;
            t.x = to_tf32(v.x); t.y = to_tf32(v.y);
            t.z = to_tf32(v.z); t.w = to_tf32(v.w);
            *(uint4*)&sWh[r * WCH_STR + c] = t;
        }
        __syncthreads();

        float acc[2][4];
#pragma unroll
        for (int mt = 0; mt < 2; mt++)
#pragma unroll
            for (int i = 0; i < 4; i++) acc[mt][i] = 0.f;

#pragma unroll
        for (int kk = 0; kk < 128; kk += 8) {
            u32 afr[2][4], bfr[2];
#pragma unroll
            for (int mt = 0; mt < 2; mt++) {
                int r0 = wr * 32 + mt * 16 + lr4;
                int c0 = kk + lc4;
                afr[mt][0] = sAtt[r0 * AT_STR + c0];
                afr[mt][1] = sAtt[(r0 + 8) * AT_STR + c0];
                afr[mt][2] = sAtt[r0 * AT_STR + c0 + 4];
                afr[mt][3] = sAtt[(r0 + 8) * AT_STR + c0 + 4];
            }
            {
                int col = wc * 8 + lr4;
                bfr[0] = sWh[(kk + lc4) * WCH_STR + col];
                bfr[1] = sWh[(kk + lc4 + 4) * WCH_STR + col];
            }
#pragma unroll
            for (int mt = 0; mt < 2; mt++)
                mma_tf32(acc[mt], afr[mt], bfr);
        }

        // ELU + store g_x[b, i, hh*64 + ch*32 + col]
#pragma unroll
        for (int mt = 0; mt < 2; mt++) {
            int col = ch * 32 + wc * 8 + lc4 * 2;
#pragma unroll
            for (int half = 0; half < 2; half++) {
                int i = i0 + wr * 32 + mt * 16 + lr4 + half * 8;
                float2 v;
                v.x = elu1(acc[mt][half * 2]);
                v.y = elu1(acc[mt][half * 2 + 1]);
                *(float2*)(g_x + ((size_t)b * Nn + i) * HID + hh * NHID + col) = v;
            }
        }
    }
}

// ---------------------------------------------------------------------------
// attn2 (tf32 mma, 32-col chunks + ELU + col sums): block = (b, half).
// smem: sAtt [64][132] + sWx [128][40] + st1/st2/scratch = 55.5 KB -> 4 CTAs.
// ---------------------------------------------------------------------------
__global__ __launch_bounds__(256) void attn2_kernel(
    const float* __restrict__ ae_out, const int* __restrict__ adj,
    const float* __restrict__ edge)
{
    extern __shared__ u32 smu[];
    u32* sAtt = smu;                        // 64*132
    u32* sWx  = smu + 64 * AT_STR;          // 128*40
    float* st1 = (float*)(smu + 64 * AT_STR + 128 * WCH_STR);  // 64
    float* st2 = st1 + 64;                                      // 128
    float* scratch = st2 + 128;                                 // 64 (2 x 32)

    int tid = threadIdx.x;
    int blk = blockIdx.x;
    int hb = blk & 1;
    int b = blk >> 1;
    int i0 = hb * 64;
    float ae = ae_out[0];

    if (tid < 64)  st1[tid] = g_t1[b * Nn + i0 + tid];
    if (tid < 128) st2[tid] = g_t2[b * Nn + tid];
    __syncthreads();

    int warp = tid >> 5, lane = tid & 31;
    for (int i = warp; i < 64; i += 8) {
        int row = i0 + i;
        float4 ef = ((const float4*)(edge + ((size_t)b * Nn + row) * Nn))[lane];
        int4  av  = ((const int4*)(adj  + ((size_t)b * Nn + row) * Nn))[lane];
        float si = st1[i];
        int j0 = lane * 4;
        float v0 = si + st2[j0 + 0] + ef.x * ae; v0 = v0 >= 0.f ? v0 : 0.2f * v0; v0 = av.x > 0 ? v0 : -9e15f;
        float v1 = si + st2[j0 + 1] + ef.y * ae; v1 = v1 >= 0.f ? v1 : 0.2f * v1; v1 = av.y > 0 ? v1 : -9e15f;
        float v2 = si + st2[j0 + 2] + ef.z * ae; v2 = v2 >= 0.f ? v2 : 0.2f * v2; v2 = av.z > 0 ? v2 : -9e15f;
        float v3 = si + st2[j0 + 3] + ef.w * ae; v3 = v3 >= 0.f ? v3 : 0.2f * v3; v3 = av.w > 0 ? v3 : -9e15f;
        float m = fmaxf(fmaxf(v0, v1), fmaxf(v2, v3));
#pragma unroll
        for (int o = 16; o; o >>= 1) m = fmaxf(m, __shfl_xor_sync(0xffffffffu, m, o));
        float e0 = __expf(v0 - m), e1 = __expf(v1 - m), e2 = __expf(v2 - m), e3 = __expf(v3 - m);
        float s = e0 + e1 + e2 + e3;
#pragma unroll
        for (int o = 16; o; o >>= 1) s += __shfl_xor_sync(0xffffffffu, s, o);
        float inv = 1.f / s;
        uint4 o4;
        o4.x = to_tf32(e0 * inv); o4.y = to_tf32(e1 * inv);
        o4.z = to_tf32(e2 * inv); o4.w = to_tf32(e3 * inv);
        *(uint4*)&sAtt[i * AT_STR + lane * 4] = o4;
    }

    int wr = warp >> 2, wc = warp & 3;
    int lr4 = lane >> 2, lc4 = lane & 3;

    for (int ch = 0; ch < 16; ch++) {
        __syncthreads();   // guards sAtt (ch=0) and sWx/scratch reuse
        // load Wx chunk [128 x 32] as tf32
        const float* wp = g_Wx + (size_t)b * Nn * HID + ch * 32;
        for (int i = tid; i < 128 * 8; i += 256) {
            int r = i >> 3, c = (i & 7) * 4;
            float4 v = *(const float4*)(wp + (size_t)r * HID + c);
            uint4 t;
            t.x = to_tf32(v.x); t.y = to_tf32(v.y);
            t.z = to_tf32(v.z); t.w = to_tf32(v.w);
            *(uint4*)&sWx[r * WCH_STR + c] = t;
        }
        __syncthreads();

        float acc[2][4];
#pragma unroll
        for (int mt = 0; mt < 2; mt++)
#pragma unroll
            for (int i = 0; i < 4; i++) acc[mt][i] = 0.f;

#pragma unroll
        for (int kk = 0; kk < 128; kk += 8) {
            u32 afr[2][4], bfr[2];
#pragma unroll
            for (int mt = 0; mt < 2; mt++) {
                int r0 = wr * 32 + mt * 16 + lr4;
                int c0 = kk + lc4;
                afr[mt][0] = sAtt[r0 * AT_STR + c0];
                afr[mt][1] = sAtt[(r0 + 8) * AT_STR + c0];
                afr[mt][2] = sAtt[r0 * AT_STR + c0 + 4];
                afr[mt][3] = sAtt[(r0 + 8) * AT_STR + c0 + 4];
            }
            {
                int col = wc * 8 + lr4;
                bfr[0] = sWx[(kk + lc4) * WCH_STR + col];
                bfr[1] = sWx[(kk + lc4 + 4) * WCH_STR + col];
            }
#pragma unroll
            for (int mt = 0; mt < 2; mt++)
                mma_tf32(acc[mt], afr[mt], bfr);
        }

        // ELU + per-thread column sums (this thread's 4 rows, 2 cols)
        float cs0 = 0.f, cs1 = 0.f;
#pragma unroll
        for (int mt = 0; mt < 2; mt++) {
            cs0 += elu1(acc[mt][0]) + elu1(acc[mt][2]);
            cs1 += elu1(acc[mt][1]) + elu1(acc[mt][3]);
        }
        // reduce over lr4 (8 lanes: xor 4, 8, 16)
#pragma unroll
        for (int o = 4; o <= 16; o <<= 1) {
            cs0 += __shfl_xor_sync(0xffffffffu, cs0, o);
            cs1 += __shfl_xor_sync(0xffffffffu, cs1, o);
        }
        if (lr4 == 0) {
            int col = wc * 8 + lc4 * 2;
            scratch[wr * 32 + col]     = cs0;
            scratch[wr * 32 + col + 1] = cs1;
        }
        __syncthreads();
        if (tid < 32)
            g_gatp[((size_t)b * 2 + hb) * HID + ch * 32 + tid] =
                scratch[tid] + scratch[32 + tid];
    }
}

// ---------------------------------------------------------------------------
__global__ void gat_reduce_kernel()
{
    int idx = blockIdx.x * blockDim.x + threadIdx.x;
    if (idx >= Bq * HID) return;
    int b = idx >> 9, c = idx & 511;
    g_gat[idx] = (g_gatp[((size_t)b * 2) * HID + c] +
                  g_gatp[((size_t)b * 2 + 1) * HID + c]) * (1.f / 128.f);
}

// ---------------------------------------------------------------------------
__global__ void final_kernel(const float* __restrict__ X,
                             const float* __restrict__ W,
                             const float* __restrict__ bias,
                             float* __restrict__ out)
{
    int idx = blockIdx.x * blockDim.x + threadIdx.x;
    if (idx >= Bq * TASKS) return;
    int b = idx / TASKS, t = idx - b * TASKS;
    const float* x = X + (size_t)b * HID;
    float s = bias[t];
    for (int d = 0; d < HID; d++) s += x[d] * W[d * TASKS + t];
    out[idx] = s;
}

// ---------------------------------------------------------------------------
extern "C" void kernel_launch(void* const* d_in, const int* in_sizes, int n_in,
                              void* d_out, int out_size)
{
    const float* h        = (const float*)d_in[0];
    const int*   adj      = (const int*)d_in[1];
    const float* edge     = (const float*)d_in[2];
    const float* fp       = (const float*)d_in[3];
    const float* W_heads  = (const float*)d_in[4];
    const float* a1_heads = (const float*)d_in[5];
    const float* a2_heads = (const float*)d_in[6];
    const float* ae_heads = (const float*)d_in[7];
    const float* W_out    = (const float*)d_in[8];
    const float* a1_out   = (const float*)d_in[9];
    const float* a2_out   = (const float*)d_in[10];
    const float* ae_out   = (const float*)d_in[11];
    const float* fc1_w    = (const float*)d_in[12];
    const float* fc1_b    = (const float*)d_in[13];
    const float* fc2_w    = (const float*)d_in[14];
    const float* fc2_b    = (const float*)d_in[15];
    const float* q_w      = (const float*)d_in[16];
    const float* q_b      = (const float*)d_in[17];
    // k_w (18), k_b (19) unused: softmax over size-1 axis == 1 -> fused = q+v
    const float* v_w      = (const float*)d_in[20];
    const float* v_b      = (const float*)d_in[21];
    const float* o_w      = (const float*)d_in[22];
    const float* o_b      = (const float*)d_in[23];
    const float* ffn1_w   = (const float*)d_in[24];
    const float* ffn1_b   = (const float*)d_in[25];
    const float* ffn2_w   = (const float*)d_in[26];
    const float* ffn2_b   = (const float*)d_in[27];
    float* out = (float*)d_out;

    float *Wh, *x, *gat, *fpnh, *fpn, *buf1, *buf2, *Wx, *Wcat;
    cudaGetSymbolAddress((void**)&Wh, g_Wh);
    cudaGetSymbolAddress((void**)&x, g_x);
    cudaGetSymbolAddress((void**)&Wx, g_Wx);
    cudaGetSymbolAddress((void**)&gat, g_gat);
    cudaGetSymbolAddress((void**)&fpnh, g_fpnh);
    cudaGetSymbolAddress((void**)&fpn, g_fpn);
    cudaGetSymbolAddress((void**)&buf1, g_buf1);
    cudaGetSymbolAddress((void**)&buf2, g_buf2);
    cudaGetSymbolAddress((void**)&Wcat, g_Wcat);

    const int ATT1_SMEM = (128 * WCH_STR + 64 * AT_STR + 192) * 4;   // 55040
    const int ATT2_SMEM = (64 * AT_STR + 128 * WCH_STR + 256) * 4;   // 55296
    cudaFuncSetAttribute(attn1_kernel, cudaFuncAttributeMaxDynamicSharedMemorySize, ATT1_SMEM);
    cudaFuncSetAttribute(attn2_kernel, cudaFuncAttributeMaxDynamicSharedMemorySize, ATT2_SMEM);

    const int M1 = Bq * Nn;  // 65536

    // 1. Wcat transpose
    wcat_kernel<<<(NHEADS * F_IN * NHID + 255) / 256, 256>>>(W_heads);

    // 2. Wh = h @ Wcat  (fast tf32)
    {
        dim3 grid(HID / 128, M1 / 128);
        sgemm_tc_kernel<<<grid, 256>>>(h, Wcat, nullptr, Wh, M1, HID, F_IN, 0);
    }

    // 3. s1/s2
    s12_kernel<<<(Bq * NHEADS * Nn * 32) / 256, 256>>>(a1_heads, a2_heads);

    // 4. attn1 (tf32 mma, chunked, 4 CTAs/SM)
    attn1_kernel<<<Bq * NHEADS * 2, 256, ATT1_SMEM>>>(ae_heads, adj, edge);

    // 5. Wx = x @ W_out (fast tf32)
    {
        dim3 grid(HID / 128, M1 / 128);
        sgemm_tc_kernel<<<grid, 256>>>(x, W_out, nullptr, Wx, M1, HID, HID, 0);
    }

    // 6. t1/t2
    t12_kernel<<<(Bq * Nn * 32) / 256, 256>>>(a1_out, a2_out);

    // 7. attn2 (tf32 mma, chunked) + mean reduce
    attn2_kernel<<<Bq * 2, 256, ATT2_SMEM>>>(ae_out, adj, edge);
    gat_reduce_kernel<<<(Bq * HID + 255) / 256, 256>>>();

    // 8. FPN (exact fp32 tails)
    {
        dim3 grid(HID / 64, Bq / 64);
        tail_gemm_kernel<<<grid, 256>>>(fp, fc1_w, fc1_b, fpnh, Bq, HID, FP_DIM, 1 | 2);
        tail_gemm_kernel<<<grid, 256>>>(fpnh, fc2_w, fc2_b, fpn, Bq, HID, HID, 1);
    }

    // 9. fusion + FFN (exact fp32 tails)
    {
        dim3 grid(HID / 64, Bq / 64);
        tail_gemm_kernel<<<grid, 256>>>(gat, q_w, q_b, buf1, Bq, HID, HID, 1);
        tail_gemm_kernel<<<grid, 256>>>(fpn, v_w, v_b, buf1, Bq, HID, HID, 1 | 4);
        tail_gemm_kernel<<<grid, 256>>>(buf1, o_w, o_b, buf2, Bq, HID, HID, 1 | 2);
        tail_gemm_kernel<<<grid, 256>>>(buf2, ffn1_w, ffn1_b, buf1, Bq, HID, HID, 1 | 2);
    }

    // 10. final projection
    final_kernel<<<(Bq * TASKS + 255) / 256, 256>>>(buf1, ffn2_w, ffn2_b, out);
}

// round 12
// speedup vs baseline: 1.0336x; 1.0336x over previous
#include <cuda_runtime.h>
#include <cuda_bf16.h>
#include <math.h>

// ---------------------------------------------------------------------------
// FPGNN forward. R12:
//  - big GEMMs (Wh, Wx): 1x tf32 mma.sync
//  - attn1: tf32 mma, 32-col chunks (55KB smem -> 4 CTAs/SM)   [R11, won]
//  - attn2: tf32 mma, 64-col chunks (72KB smem -> 3 CTAs/SM)   [R10, won]
//  - tail GEMMs: exact fp32 FFMA2, 64x64 tiles
// ---------------------------------------------------------------------------

#define Bq 512
#define Nn 128
#define F_IN 133
#define NHEADS 8
#define NHID 64
#define HID 512
#define FP_DIM 1489
#define TASKS 12

typedef unsigned long long u64;
typedef unsigned int u32;

__device__ __forceinline__ u64 pack2(float lo, float hi) {
    u64 r; asm("mov.b64 %0, {%1,%2};" : "=l"(r) : "f"(lo), "f"(hi)); return r;
}
__device__ __forceinline__ u64 dup2(float v) { return pack2(v, v); }
__device__ __forceinline__ void fma2(u64& d, u64 a, u64 b) {
    asm("fma.rn.f32x2 %0, %1, %2, %0;" : "+l"(d) : "l"(a), "l"(b));
}
__device__ __forceinline__ float2 upk2(u64 v) {
    float2 r; asm("mov.b64 {%0,%1}, %2;" : "=f"(r.x), "=f"(r.y) : "l"(v)); return r;
}
__device__ __forceinline__ u32 to_tf32(float f) {
    u32 r; asm("cvt.rna.tf32.f32 %0, %1;" : "=r"(r) : "f"(f)); return r;
}
__device__ __forceinline__ void mma_tf32(float* d, const u32* a, const u32* b) {
    asm volatile(
        "mma.sync.aligned.m16n8k8.row.col.f32.tf32.tf32.f32 "
        "{%0,%1,%2,%3}, {%4,%5,%6,%7}, {%8,%9}, {%0,%1,%2,%3};\n"
        : "+f"(d[0]), "+f"(d[1]), "+f"(d[2]), "+f"(d[3])
        : "r"(a[0]), "r"(a[1]), "r"(a[2]), "r"(a[3]), "r"(b[0]), "r"(b[1]));
}
__device__ __forceinline__ float elu1(float v) {
    return v > 0.f ? v : (__expf(v) - 1.f);
}

// ---- scratch (device globals; no allocation allowed) ----
__device__ float g_Wcat[F_IN * HID];
__device__ float g_Wh[(size_t)Bq * Nn * HID];
__device__ float g_s1[Bq * NHEADS * Nn];
__device__ float g_s2[Bq * NHEADS * Nn];
__device__ float g_x[(size_t)Bq * Nn * HID];
__device__ float g_Wx[(size_t)Bq * Nn * HID];
__device__ float g_t1[Bq * Nn];
__device__ float g_t2[Bq * Nn];
__device__ float g_gatp[Bq * 2 * HID];
__device__ float g_gat[Bq * HID];
__device__ float g_fpnh[Bq * HID];
__device__ float g_fpn[Bq * HID];
__device__ float g_buf1[Bq * HID];
__device__ float g_buf2[Bq * HID];

// ---------------------------------------------------------------------------
// 1x tf32 GEMM (fast path, big GEMMs). Validated R8.
// flags: 1 = bias, 2 = relu, 4 = accumulate
// ---------------------------------------------------------------------------
#define SA_STRIDE 20
#define SB_STRIDE 136

__global__ __launch_bounds__(256) void sgemm_tc_kernel(
    const float* __restrict__ A, const float* __restrict__ B,
    const float* __restrict__ bias, float* __restrict__ C,
    int M, int N, int K, int flags)
{
    __shared__ u32 sA[2][128 * SA_STRIDE];
    __shared__ u32 sB[2][16 * SB_STRIDE];

    int tid = threadIdx.x;
    int warp = tid >> 5, lane = tid & 31;
    int wr = warp >> 2, wc = warp & 3;
    int bm = blockIdx.y * 128;
    int bn = blockIdx.x * 128;
    int lr4 = lane >> 2, lc4 = lane & 3;

    float acc[4][4][4];
#pragma unroll
    for (int mt = 0; mt < 4; mt++)
#pragma unroll
        for (int nt = 0; nt < 4; nt++)
#pragma unroll
            for (int i = 0; i < 4; i++) acc[mt][nt][i] = 0.f;

    const int Ktiles = (K + 15) / 16;
    int aRow0 = tid >> 2,         aK0 = (tid & 3) * 4;
    int aRow1 = (tid + 256) >> 2, aK1 = ((tid + 256) & 3) * 4;
    int bK0 = tid >> 5,           bN0 = (tid & 31) * 4;
    int bK1 = (tid + 256) >> 5,   bN1 = ((tid + 256) & 31) * 4;

    float ar[2][4], br[2][4];
    {
#pragma unroll
        for (int i = 0; i < 4; i++) {
            int k = aK0 + i;
            ar[0][i] = (k < K) ? A[(size_t)(bm + aRow0) * K + k] : 0.f;
            k = aK1 + i;
            ar[1][i] = (k < K) ? A[(size_t)(bm + aRow1) * K + k] : 0.f;
        }
        if (bK0 < K) *(float4*)br[0] = *(const float4*)(B + (size_t)bK0 * N + bn + bN0);
        else { br[0][0] = br[0][1] = br[0][2] = br[0][3] = 0.f; }
        if (bK1 < K) *(float4*)br[1] = *(const float4*)(B + (size_t)bK1 * N + bn + bN1);
        else { br[1][0] = br[1][1] = br[1][2] = br[1][3] = 0.f; }
    }
#pragma unroll
    for (int i = 0; i < 4; i++) {
        sA[0][aRow0 * SA_STRIDE + aK0 + i] = to_tf32(ar[0][i]);
        sA[0][aRow1 * SA_STRIDE + aK1 + i] = to_tf32(ar[1][i]);
        sB[0][bK0 * SB_STRIDE + bN0 + i] = to_tf32(br[0][i]);
        sB[0][bK1 * SB_STRIDE + bN1 + i] = to_tf32(br[1][i]);
    }
    __syncthreads();

    int buf = 0;
    for (int t = 0; t < Ktiles; t++) {
        bool has_next = (t + 1 < Ktiles);
        if (has_next) {
            int k0 = (t + 1) * 16;
#pragma unroll
            for (int i = 0; i < 4; i++) {
                int k = k0 + aK0 + i;
                ar[0][i] = (k < K) ? A[(size_t)(bm + aRow0) * K + k] : 0.f;
                k = k0 + aK1 + i;
                ar[1][i] = (k < K) ? A[(size_t)(bm + aRow1) * K + k] : 0.f;
            }
            int k = k0 + bK0;
            if (k < K) *(float4*)br[0] = *(const float4*)(B + (size_t)k * N + bn + bN0);
            else { br[0][0] = br[0][1] = br[0][2] = br[0][3] = 0.f; }
            k = k0 + bK1;
            if (k < K) *(float4*)br[1] = *(const float4*)(B + (size_t)k * N + bn + bN1);
            else { br[1][0] = br[1][1] = br[1][2] = br[1][3] = 0.f; }
        }

        const u32* cA = sA[buf];
        const u32* cB = sB[buf];
#pragma unroll
        for (int kk = 0; kk < 16; kk += 8) {
            u32 afr[4][4], bfr[4][2];
#pragma unroll
            for (int mt = 0; mt < 4; mt++) {
                int r0 = wr * 64 + mt * 16 + lr4;
                int c0 = kk + lc4;
                afr[mt][0] = cA[r0 * SA_STRIDE + c0];
                afr[mt][1] = cA[(r0 + 8) * SA_STRIDE + c0];
                afr[mt][2] = cA[r0 * SA_STRIDE + c0 + 4];
                afr[mt][3] = cA[(r0 + 8) * SA_STRIDE + c0 + 4];
            }
#pragma unroll
            for (int nt = 0; nt < 4; nt++) {
                int col = wc * 32 + nt * 8 + lr4;
                bfr[nt][0] = cB[(kk + lc4) * SB_STRIDE + col];
                bfr[nt][1] = cB[(kk + lc4 + 4) * SB_STRIDE + col];
            }
#pragma unroll
            for (int mt = 0; mt < 4; mt++)
#pragma unroll
                for (int nt = 0; nt < 4; nt++)
                    mma_tf32(acc[mt][nt], afr[mt], bfr[nt]);
        }

        if (has_next) {
#pragma unroll
            for (int i = 0; i < 4; i++) {
                sA[buf ^ 1][aRow0 * SA_STRIDE + aK0 + i] = to_tf32(ar[0][i]);
                sA[buf ^ 1][aRow1 * SA_STRIDE + aK1 + i] = to_tf32(ar[1][i]);
                sB[buf ^ 1][bK0 * SB_STRIDE + bN0 + i] = to_tf32(br[0][i]);
                sB[buf ^ 1][bK1 * SB_STRIDE + bN1 + i] = to_tf32(br[1][i]);
            }
        }
        __syncthreads();
        buf ^= 1;
    }

#pragma unroll
    for (int mt = 0; mt < 4; mt++) {
#pragma unroll
        for (int nt = 0; nt < 4; nt++) {
            int col = bn + wc * 32 + nt * 8 + lc4 * 2;
#pragma unroll
            for (int half = 0; half < 2; half++) {
                int row = bm + wr * 64 + mt * 16 + lr4 + half * 8;
                float2 v = make_float2(acc[mt][nt][half * 2],
                                       acc[mt][nt][half * 2 + 1]);
                if (flags & 4) {
                    float2 c = *(const float2*)&C[(size_t)row * N + col];
                    v.x += c.x; v.y += c.y;
                }
                if (flags & 1) { v.x += bias[col]; v.y += bias[col + 1]; }
                if (flags & 2) { v.x = fmaxf(v.x, 0.f); v.y = fmaxf(v.y, 0.f); }
                *(float2*)&C[(size_t)row * N + col] = v;
            }
        }
    }
}

// ---------------------------------------------------------------------------
// Tail fp32 GEMM (exact): BM=BN=64, BK=16, 256 threads. Validated R10.
// ---------------------------------------------------------------------------
__global__ __launch_bounds__(256) void tail_gemm_kernel(
    const float* __restrict__ A, const float* __restrict__ B,
    const float* __restrict__ bias, float* __restrict__ C,
    int M, int N, int K, int flags)
{
    __shared__ float As[2][16][64];
    __shared__ float Bs[2][16][64];

    int tid = threadIdx.x;
    int bm = blockIdx.y * 64;
    int bn = blockIdx.x * 64;
    int tx = tid & 15;
    int ty = tid >> 4;

    int aRow = tid >> 2, aK = (tid & 3) * 4;
    int bK = tid >> 4, bN = (tid & 15) * 4;

    u64 acc[4][2];
#pragma unroll
    for (int i = 0; i < 4; i++) { acc[i][0] = 0ull; acc[i][1] = 0ull; }

    const int Ktiles = (K + 15) / 16;
    const float* Arow = A + (size_t)(bm + aRow) * K;

    {
#pragma unroll
        for (int i = 0; i < 4; i++) {
            int k = aK + i;
            As[0][aK + i][aRow] = (k < K) ? Arow[k] : 0.f;
        }
        float4 v = make_float4(0.f, 0.f, 0.f, 0.f);
        if (bK < K) v = *(const float4*)(B + (size_t)bK * N + bn + bN);
        *(float4*)&Bs[0][bK][bN] = v;
    }
    __syncthreads();

    int buf = 0;
    for (int t = 0; t < Ktiles; t++) {
        float ap[4];
        float4 bp = make_float4(0.f, 0.f, 0.f, 0.f);
        bool has_next = (t + 1 < Ktiles);
        if (has_next) {
            int k0 = (t + 1) * 16;
#pragma unroll
            for (int i = 0; i < 4; i++) {
                int k = k0 + aK + i;
                ap[i] = (k < K) ? Arow[k] : 0.f;
            }
            int k = k0 + bK;
            if (k < K) bp = *(const float4*)(B + (size_t)k * N + bn + bN);
        }

#pragma unroll
        for (int kk = 0; kk < 16; kk++) {
            u64 b0 = *(const u64*)&Bs[buf][kk][tx * 4];
            u64 b1 = *(const u64*)&Bs[buf][kk][tx * 4 + 2];
            float a0 = As[buf][kk][ty * 4];
            float a1 = As[buf][kk][ty * 4 + 1];
            float a2 = As[buf][kk][ty * 4 + 2];
            float a3 = As[buf][kk][ty * 4 + 3];
            u64 d0 = dup2(a0), d1 = dup2(a1), d2 = dup2(a2), d3 = dup2(a3);
            fma2(acc[0][0], d0, b0); fma2(acc[0][1], d0, b1);
            fma2(acc[1][0], d1, b0); fma2(acc[1][1], d1, b1);
            fma2(acc[2][0], d2, b0); fma2(acc[2][1], d2, b1);
            fma2(acc[3][0], d3, b0); fma2(acc[3][1], d3, b1);
        }

        if (has_next) {
#pragma unroll
            for (int i = 0; i < 4; i++) As[buf ^ 1][aK + i][aRow] = ap[i];
            *(float4*)&Bs[buf ^ 1][bK][bN] = bp;
        }
        __syncthreads();
        buf ^= 1;
    }

#pragma unroll
    for (int i = 0; i < 4; i++) {
        int row = bm + ty * 4 + i;
#pragma unroll
        for (int j = 0; j < 2; j++) {
            int col = bn + tx * 4 + j * 2;
            float2 v = upk2(acc[i][j]);
            if (flags & 4) {
                float2 c = *(const float2*)&C[(size_t)row * N + col];
                v.x += c.x; v.y += c.y;
            }
            if (flags & 1) { v.x += bias[col]; v.y += bias[col + 1]; }
            if (flags & 2) { v.x = fmaxf(v.x, 0.f); v.y = fmaxf(v.y, 0.f); }
            *(float2*)&C[(size_t)row * N + col] = v;
        }
    }
}

// ---------------------------------------------------------------------------
__global__ void wcat_kernel(const float* __restrict__ W_heads)
{
    int idx = blockIdx.x * blockDim.x + threadIdx.x;
    if (idx >= NHEADS * F_IN * NHID) return;
    int h = idx / (F_IN * NHID);
    int rem = idx - h * (F_IN * NHID);
    int f = rem / NHID;
    int d = rem - f * NHID;
    g_Wcat[f * HID + h * NHID + d] = W_heads[idx];
}

// ---------------------------------------------------------------------------
__global__ __launch_bounds__(256) void s12_kernel(
    const float* __restrict__ a1, const float* __restrict__ a2)
{
    int gw = (blockIdx.x * blockDim.x + threadIdx.x) >> 5;
    int lane = threadIdx.x & 31;
    if (gw >= Bq * NHEADS * Nn) return;
    int n  = gw & 127;
    int hh = (gw >> 7) & 7;
    int b  = gw >> 10;
    const float* row = g_Wh + ((size_t)b * Nn + n) * HID + hh * NHID;
    const float* av1 = a1 + hh * NHID;
    const float* av2 = a2 + hh * NHID;
    float x0 = row[lane], x1 = row[lane + 32];
    float r1 = x0 * av1[lane] + x1 * av1[lane + 32];
    float r2 = x0 * av2[lane] + x1 * av2[lane + 32];
#pragma unroll
    for (int o = 16; o; o >>= 1) {
        r1 += __shfl_xor_sync(0xffffffffu, r1, o);
        r2 += __shfl_xor_sync(0xffffffffu, r2, o);
    }
    if (lane == 0) {
        int o = (b * NHEADS + hh) * Nn + n;
        g_s1[o] = r1;
        g_s2[o] = r2;
    }
}

// ---------------------------------------------------------------------------
__global__ __launch_bounds__(256) void t12_kernel(
    const float* __restrict__ a1, const float* __restrict__ a2)
{
    int gw = (blockIdx.x * blockDim.x + threadIdx.x) >> 5;
    int lane = threadIdx.x & 31;
    if (gw >= Bq * Nn) return;
    const float* row = g_Wx + (size_t)gw * HID;
    float r1 = 0.f, r2 = 0.f;
#pragma unroll
    for (int c0 = 0; c0 < HID; c0 += 128) {
        float4 v = *(const float4*)(row + c0 + lane * 4);
        float4 w1 = *(const float4*)(a1 + c0 + lane * 4);
        float4 w2 = *(const float4*)(a2 + c0 + lane * 4);
        r1 += v.x * w1.x + v.y * w1.y + v.z * w1.z + v.w * w1.w;
        r2 += v.x * w2.x + v.y * w2.y + v.z * w2.z + v.w * w2.w;
    }
#pragma unroll
    for (int o = 16; o; o >>= 1) {
        r1 += __shfl_xor_sync(0xffffffffu, r1, o);
        r2 += __shfl_xor_sync(0xffffffffu, r2, o);
    }
    if (lane == 0) { g_t1[gw] = r1; g_t2[gw] = r2; }
}

// ---------------------------------------------------------------------------
// attn1 (tf32 mma, 32-col B-chunks): R11 form, 55 KB -> 4 CTAs/SM.
// ---------------------------------------------------------------------------
#define WCH_STR 40
#define W64_STR 72
#define AT_STR 132

__global__ __launch_bounds__(256) void attn1_kernel(
    const float* __restrict__ ae_heads, const int* __restrict__ adj,
    const float* __restrict__ edge)
{
    extern __shared__ u32 smu[];
    u32* sWh  = smu;                        // 128*40
    u32* sAtt = smu + 128 * WCH_STR;        // 64*132
    float* ss1 = (float*)(smu + 128 * WCH_STR + 64 * AT_STR);  // 64
    float* ss2 = ss1 + 64;                                      // 128

    int tid = threadIdx.x;
    int blk = blockIdx.x;
    int hb = blk & 1;
    int bh = blk >> 1;
    int hh = bh & 7, b = bh >> 3;
    int i0 = hb * 64;
    float ae = ae_heads[hh];

    if (tid < 64)  ss1[tid] = g_s1[bh * Nn + i0 + tid];
    if (tid < 128) ss2[tid] = g_s2[bh * Nn + tid];
    __syncthreads();

    int warp = tid >> 5, lane = tid & 31;
    for (int i = warp; i < 64; i += 8) {
        int row = i0 + i;
        float4 ef = ((const float4*)(edge + ((size_t)b * Nn + row) * Nn))[lane];
        int4  av  = ((const int4*)(adj  + ((size_t)b * Nn + row) * Nn))[lane];
        float si = ss1[i];
        int j0 = lane * 4;
        float v0 = si + ss2[j0 + 0] + ef.x * ae; v0 = v0 >= 0.f ? v0 : 0.2f * v0; v0 = av.x > 0 ? v0 : -9e15f;
        float v1 = si + ss2[j0 + 1] + ef.y * ae; v1 = v1 >= 0.f ? v1 : 0.2f * v1; v1 = av.y > 0 ? v1 : -9e15f;
        float v2 = si + ss2[j0 + 2] + ef.z * ae; v2 = v2 >= 0.f ? v2 : 0.2f * v2; v2 = av.z > 0 ? v2 : -9e15f;
        float v3 = si + ss2[j0 + 3] + ef.w * ae; v3 = v3 >= 0.f ? v3 : 0.2f * v3; v3 = av.w > 0 ? v3 : -9e15f;
        float m = fmaxf(fmaxf(v0, v1), fmaxf(v2, v3));
#pragma unroll
        for (int o = 16; o; o >>= 1) m = fmaxf(m, __shfl_xor_sync(0xffffffffu, m, o));
        float e0 = __expf(v0 - m), e1 = __expf(v1 - m), e2 = __expf(v2 - m), e3 = __expf(v3 - m);
        float s = e0 + e1 + e2 + e3;
#pragma unroll
        for (int o = 16; o; o >>= 1) s += __shfl_xor_sync(0xffffffffu, s, o);
        float inv = 1.f / s;
        uint4 o4;
        o4.x = to_tf32(e0 * inv); o4.y = to_tf32(e1 * inv);
        o4.z = to_tf32(e2 * inv); o4.w = to_tf32(e3 * inv);
        *(uint4*)&sAtt[i * AT_STR + lane * 4] = o4;
    }

    int wr = warp >> 2, wc = warp & 3;      // 2 x 4; warp tile 32(M) x 8(N)
    int lr4 = lane >> 2, lc4 = lane & 3;

    const float* whp = g_Wh + (size_t)b * Nn * HID + hh * NHID;

#pragma unroll
    for (int ch = 0; ch < 2; ch++) {
        __syncthreads();
        for (int i = tid; i < 128 * 8; i += 256) {
            int r = i >> 3, c = (i & 7) * 4;
            float4 v = *(const float4*)(whp + (size_t)r * HID + ch * 32 + c);
            uint4 t;
            t.x = to_tf32(v.x); t.y = to_tf32(v.y);
            t.z = to_tf32(v.z); t.w = to_tf32(v.w);
            *(uint4*)&sWh[r * WCH_STR + c] = t;
        }
        __syncthreads();

        float acc[2][4];
#pragma unroll
        for (int mt = 0; mt < 2; mt++)
#pragma unroll
            for (int i = 0; i < 4; i++) acc[mt][i] = 0.f;

#pragma unroll
        for (int kk = 0; kk < 128; kk += 8) {
            u32 afr[2][4], bfr[2];
#pragma unroll
            for (int mt = 0; mt < 2; mt++) {
                int r0 = wr * 32 + mt * 16 + lr4;
                int c0 = kk + lc4;
                afr[mt][0] = sAtt[r0 * AT_STR + c0];
                afr[mt][1] = sAtt[(r0 + 8) * AT_STR + c0];
                afr[mt][2] = sAtt[r0 * AT_STR + c0 + 4];
                afr[mt][3] = sAtt[(r0 + 8) * AT_STR + c0 + 4];
            }
            {
                int col = wc * 8 + lr4;
                bfr[0] = sWh[(kk + lc4) * WCH_STR + col];
                bfr[1] = sWh[(kk + lc4 + 4) * WCH_STR + col];
            }
#pragma unroll
            for (int mt = 0; mt < 2; mt++)
                mma_tf32(acc[mt], afr[mt], bfr);
        }

#pragma unroll
        for (int mt = 0; mt < 2; mt++) {
            int col = ch * 32 + wc * 8 + lc4 * 2;
#pragma unroll
            for (int half = 0; half < 2; half++) {
                int i = i0 + wr * 32 + mt * 16 + lr4 + half * 8;
                float2 v;
                v.x = elu1(acc[mt][half * 2]);
                v.y = elu1(acc[mt][half * 2 + 1]);
                *(float2*)(g_x + ((size_t)b * Nn + i) * HID + hh * NHID + col) = v;
            }
        }
    }
}

// ---------------------------------------------------------------------------
// attn2 (tf32 mma, 64-col chunks + ELU + col sums): R10 form, 72 KB, 3 CTAs.
// ---------------------------------------------------------------------------
__global__ __launch_bounds__(256) void attn2_kernel(
    const float* __restrict__ ae_out, const int* __restrict__ adj,
    const float* __restrict__ edge)
{
    extern __shared__ u32 smu[];
    u32* sAtt = smu;                       // 64*132
    u32* sWx  = smu + 64 * AT_STR;         // 128*72
    float* st1 = (float*)(smu + 64 * AT_STR + 128 * W64_STR);  // 64
    float* st2 = st1 + 64;                                      // 128
    float* scratch = st2 + 128;                                 // 128

    int tid = threadIdx.x;
    int blk = blockIdx.x;
    int hb = blk & 1;
    int b = blk >> 1;
    int i0 = hb * 64;
    float ae = ae_out[0];

    if (tid < 64)  st1[tid] = g_t1[b * Nn + i0 + tid];
    if (tid < 128) st2[tid] = g_t2[b * Nn + tid];
    __syncthreads();

    int warp = tid >> 5, lane = tid & 31;
    for (int i = warp; i < 64; i += 8) {
        int row = i0 + i;
        float4 ef = ((const float4*)(edge + ((size_t)b * Nn + row) * Nn))[lane];
        int4  av  = ((const int4*)(adj  + ((size_t)b * Nn + row) * Nn))[lane];
        float si = st1[i];
        int j0 = lane * 4;
        float v0 = si + st2[j0 + 0] + ef.x * ae; v0 = v0 >= 0.f ? v0 : 0.2f * v0; v0 = av.x > 0 ? v0 : -9e15f;
        float v1 = si + st2[j0 + 1] + ef.y * ae; v1 = v1 >= 0.f ? v1 : 0.2f * v1; v1 = av.y > 0 ? v1 : -9e15f;
        float v2 = si + st2[j0 + 2] + ef.z * ae; v2 = v2 >= 0.f ? v2 : 0.2f * v2; v2 = av.z > 0 ? v2 : -9e15f;
        float v3 = si + st2[j0 + 3] + ef.w * ae; v3 = v3 >= 0.f ? v3 : 0.2f * v3; v3 = av.w > 0 ? v3 : -9e15f;
        float m = fmaxf(fmaxf(v0, v1), fmaxf(v2, v3));
#pragma unroll
        for (int o = 16; o; o >>= 1) m = fmaxf(m, __shfl_xor_sync(0xffffffffu, m, o));
        float e0 = __expf(v0 - m), e1 = __expf(v1 - m), e2 = __expf(v2 - m), e3 = __expf(v3 - m);
        float s = e0 + e1 + e2 + e3;
#pragma unroll
        for (int o = 16; o; o >>= 1) s += __shfl_xor_sync(0xffffffffu, s, o);
        float inv = 1.f / s;
        uint4 o4;
        o4.x = to_tf32(e0 * inv); o4.y = to_tf32(e1 * inv);
        o4.z = to_tf32(e2 * inv); o4.w = to_tf32(e3 * inv);
        *(uint4*)&sAtt[i * AT_STR + lane * 4] = o4;
    }
    __syncthreads();

    int wr = warp >> 2, wc = warp & 3;
    int lr4 = lane >> 2, lc4 = lane & 3;

    for (int ch = 0; ch < 8; ch++) {
        const float* wp = g_Wx + (size_t)b * Nn * HID + ch * 64;
        for (int i = tid; i < 128 * 16; i += 256) {
            int r = i >> 4, c = (i & 15) * 4;
            float4 v = *(const float4*)(wp + (size_t)r * HID + c);
            uint4 t;
            t.x = to_tf32(v.x); t.y = to_tf32(v.y);
            t.z = to_tf32(v.z); t.w = to_tf32(v.w);
            *(uint4*)&sWx[r * W64_STR + c] = t;
        }
        __syncthreads();

        float acc[2][2][4];
#pragma unroll
        for (int mt = 0; mt < 2; mt++)
#pragma unroll
            for (int nt = 0; nt < 2; nt++)
#pragma unroll
                for (int i = 0; i < 4; i++) acc[mt][nt][i] = 0.f;

#pragma unroll
        for (int kk = 0; kk < 128; kk += 8) {
            u32 afr[2][4], bfr[2][2];
#pragma unroll
            for (int mt = 0; mt < 2; mt++) {
                int r0 = wr * 32 + mt * 16 + lr4;
                int c0 = kk + lc4;
                afr[mt][0] = sAtt[r0 * AT_STR + c0];
                afr[mt][1] = sAtt[(r0 + 8) * AT_STR + c0];
                afr[mt][2] = sAtt[r0 * AT_STR + c0 + 4];
                afr[mt][3] = sAtt[(r0 + 8) * AT_STR + c0 + 4];
            }
#pragma unroll
            for (int nt = 0; nt < 2; nt++) {
                int col = wc * 16 + nt * 8 + lr4;
                bfr[nt][0] = sWx[(kk + lc4) * W64_STR + col];
                bfr[nt][1] = sWx[(kk + lc4 + 4) * W64_STR + col];
            }
#pragma unroll
            for (int mt = 0; mt < 2; mt++)
#pragma unroll
                for (int nt = 0; nt < 2; nt++)
                    mma_tf32(acc[mt][nt], afr[mt], bfr[nt]);
        }

        float cs[2][2];
#pragma unroll
        for (int nt = 0; nt < 2; nt++) {
            cs[nt][0] = 0.f; cs[nt][1] = 0.f;
#pragma unroll
            for (int mt = 0; mt < 2; mt++) {
                cs[nt][0] += elu1(acc[mt][nt][0]) + elu1(acc[mt][nt][2]);
                cs[nt][1] += elu1(acc[mt][nt][1]) + elu1(acc[mt][nt][3]);
            }
        }
#pragma unroll
        for (int o = 4; o <= 16; o <<= 1) {
#pragma unroll
            for (int nt = 0; nt < 2; nt++) {
                cs[nt][0] += __shfl_xor_sync(0xffffffffu, cs[nt][0], o);
                cs[nt][1] += __shfl_xor_sync(0xffffffffu, cs[nt][1], o);
            }
        }
        if (lr4 == 0) {
#pragma unroll
            for (int nt = 0; nt < 2; nt++) {
                int col = wc * 16 + nt * 8 + lc4 * 2;
                scratch[wr * 64 + col]     = cs[nt][0];
                scratch[wr * 64 + col + 1] = cs[nt][1];
            }
        }
        __syncthreads();
        if (tid < 64)
            g_gatp[((size_t)b * 2 + hb) * HID + ch * 64 + tid] =
                scratch[tid] + scratch[64 + tid];
        __syncthreads();
    }
}

// ---------------------------------------------------------------------------
__global__ void gat_reduce_kernel()
{
    int idx = blockIdx.x * blockDim.x + threadIdx.x;
    if (idx >= Bq * HID) return;
    int b = idx >> 9, c = idx & 511;
    g_gat[idx] = (g_gatp[((size_t)b * 2) * HID + c] +
                  g_gatp[((size_t)b * 2 + 1) * HID + c]) * (1.f / 128.f);
}

// ---------------------------------------------------------------------------
__global__ void final_kernel(const float* __restrict__ X,
                             const float* __restrict__ W,
                             const float* __restrict__ bias,
                             float* __restrict__ out)
{
    int idx = blockIdx.x * blockDim.x + threadIdx.x;
    if (idx >= Bq * TASKS) return;
    int b = idx / TASKS, t = idx - b * TASKS;
    const float* x = X + (size_t)b * HID;
    float s = bias[t];
    for (int d = 0; d < HID; d++) s += x[d] * W[d * TASKS + t];
    out[idx] = s;
}

// ---------------------------------------------------------------------------
extern "C" void kernel_launch(void* const* d_in, const int* in_sizes, int n_in,
                              void* d_out, int out_size)
{
    const float* h        = (const float*)d_in[0];
    const int*   adj      = (const int*)d_in[1];
    const float* edge     = (const float*)d_in[2];
    const float* fp       = (const float*)d_in[3];
    const float* W_heads  = (const float*)d_in[4];
    const float* a1_heads = (const float*)d_in[5];
    const float* a2_heads = (const float*)d_in[6];
    const float* ae_heads = (const float*)d_in[7];
    const float* W_out    = (const float*)d_in[8];
    const float* a1_out   = (const float*)d_in[9];
    const float* a2_out   = (const float*)d_in[10];
    const float* ae_out   = (const float*)d_in[11];
    const float* fc1_w    = (const float*)d_in[12];
    const float* fc1_b    = (const float*)d_in[13];
    const float* fc2_w    = (const float*)d_in[14];
    const float* fc2_b    = (const float*)d_in[15];
    const float* q_w      = (const float*)d_in[16];
    const float* q_b      = (const float*)d_in[17];
    // k_w (18), k_b (19) unused: softmax over size-1 axis == 1 -> fused = q+v
    const float* v_w      = (const float*)d_in[20];
    const float* v_b      = (const float*)d_in[21];
    const float* o_w      = (const float*)d_in[22];
    const float* o_b      = (const float*)d_in[23];
    const float* ffn1_w   = (const float*)d_in[24];
    const float* ffn1_b   = (const float*)d_in[25];
    const float* ffn2_w   = (const float*)d_in[26];
    const float* ffn2_b   = (const float*)d_in[27];
    float* out = (float*)d_out;

    float *Wh, *x, *gat, *fpnh, *fpn, *buf1, *buf2, *Wx, *Wcat;
    cudaGetSymbolAddress((void**)&Wh, g_Wh);
    cudaGetSymbolAddress((void**)&x, g_x);
    cudaGetSymbolAddress((void**)&Wx, g_Wx);
    cudaGetSymbolAddress((void**)&gat, g_gat);
    cudaGetSymbolAddress((void**)&fpnh, g_fpnh);
    cudaGetSymbolAddress((void**)&fpn, g_fpn);
    cudaGetSymbolAddress((void**)&buf1, g_buf1);
    cudaGetSymbolAddress((void**)&buf2, g_buf2);
    cudaGetSymbolAddress((void**)&Wcat, g_Wcat);

    const int ATT1_SMEM = (128 * WCH_STR + 64 * AT_STR + 192) * 4;   // 55040
    const int ATT2_SMEM = (64 * AT_STR + 128 * W64_STR + 320) * 4;   // 71936
    cudaFuncSetAttribute(attn1_kernel, cudaFuncAttributeMaxDynamicSharedMemorySize, ATT1_SMEM);
    cudaFuncSetAttribute(attn2_kernel, cudaFuncAttributeMaxDynamicSharedMemorySize, ATT2_SMEM);

    const int M1 = Bq * Nn;  // 65536

    // 1. Wcat transpose
    wcat_kernel<<<(NHEADS * F_IN * NHID + 255) / 256, 256>>>(W_heads);

    // 2. Wh = h @ Wcat  (fast tf32)
    {
        dim3 grid(HID / 128, M1 / 128);
        sgemm_tc_kernel<<<grid, 256>>>(h, Wcat, nullptr, Wh, M1, HID, F_IN, 0);
    }

    // 3. s1/s2
    s12_kernel<<<(Bq * NHEADS * Nn * 32) / 256, 256>>>(a1_heads, a2_heads);

    // 4. attn1 (tf32 mma, 32-col chunks, 4 CTAs/SM)
    attn1_kernel<<<Bq * NHEADS * 2, 256, ATT1_SMEM>>>(ae_heads, adj, edge);

    // 5. Wx = x @ W_out (fast tf32)
    {
        dim3 grid(HID / 128, M1 / 128);
        sgemm_tc_kernel<<<grid, 256>>>(x, W_out, nullptr, Wx, M1, HID, HID, 0);
    }

    // 6. t1/t2
    t12_kernel<<<(Bq * Nn * 32) / 256, 256>>>(a1_out, a2_out);

    // 7. attn2 (tf32 mma, 64-col chunks) + mean reduce
    attn2_kernel<<<Bq * 2, 256, ATT2_SMEM>>>(ae_out, adj, edge);
    gat_reduce_kernel<<<(Bq * HID + 255) / 256, 256>>>();

    // 8. FPN (exact fp32 tails)
    {
        dim3 grid(HID / 64, Bq / 64);
        tail_gemm_kernel<<<grid, 256>>>(fp, fc1_w, fc1_b, fpnh, Bq, HID, FP_DIM, 1 | 2);
        tail_gemm_kernel<<<grid, 256>>>(fpnh, fc2_w, fc2_b, fpn, Bq, HID, HID, 1);
    }

    // 9. fusion + FFN (exact fp32 tails)
    {
        dim3 grid(HID / 64, Bq / 64);
        tail_gemm_kernel<<<grid, 256>>>(gat, q_w, q_b, buf1, Bq, HID, HID, 1);
        tail_gemm_kernel<<<grid, 256>>>(fpn, v_w, v_b, buf1, Bq, HID, HID, 1 | 4);
        tail_gemm_kernel<<<grid, 256>>>(buf1, o_w, o_b, buf2, Bq, HID, HID, 1 | 2);
        tail_gemm_kernel<<<grid, 256>>>(buf2, ffn1_w, ffn1_b, buf1, Bq, HID, HID, 1 | 2);
    }

    // 10. final projection
    final_kernel<<<(Bq * TASKS + 255) / 256, 256>>>(buf1, ffn2_w, ffn2_b, out);
}

// round 13
// speedup vs baseline: 1.0475x; 1.0135x over previous
#include <cuda_runtime.h>
#include <cuda_bf16.h>
#include <math.h>

// ---------------------------------------------------------------------------
// FPGNN forward. R13:
//  - big GEMMs (Wh, Wx): 1x tf32 mma.sync
//  - attn1: tf32 mma, 32-col chunks (4 CTAs/SM)              [R11]
//  - attn2 SPLIT: softmax2 writes att (tf32) to gmem, then av2 = batched
//    tf32 GEMM att@Wx with fused ELU+column-mean epilogue -> gat directly
//  - tail GEMMs: exact fp32 FFMA2, 64x64 tiles
// ---------------------------------------------------------------------------

#define Bq 512
#define Nn 128
#define F_IN 133
#define NHEADS 8
#define NHID 64
#define HID 512
#define FP_DIM 1489
#define TASKS 12

typedef unsigned long long u64;
typedef unsigned int u32;

__device__ __forceinline__ u64 pack2(float lo, float hi) {
    u64 r; asm("mov.b64 %0, {%1,%2};" : "=l"(r) : "f"(lo), "f"(hi)); return r;
}
__device__ __forceinline__ u64 dup2(float v) { return pack2(v, v); }
__device__ __forceinline__ void fma2(u64& d, u64 a, u64 b) {
    asm("fma.rn.f32x2 %0, %1, %2, %0;" : "+l"(d) : "l"(a), "l"(b));
}
__device__ __forceinline__ float2 upk2(u64 v) {
    float2 r; asm("mov.b64 {%0,%1}, %2;" : "=f"(r.x), "=f"(r.y) : "l"(v)); return r;
}
__device__ __forceinline__ u32 to_tf32(float f) {
    u32 r; asm("cvt.rna.tf32.f32 %0, %1;" : "=r"(r) : "f"(f)); return r;
}
__device__ __forceinline__ void mma_tf32(float* d, const u32* a, const u32* b) {
    asm volatile(
        "mma.sync.aligned.m16n8k8.row.col.f32.tf32.tf32.f32 "
        "{%0,%1,%2,%3}, {%4,%5,%6,%7}, {%8,%9}, {%0,%1,%2,%3};\n"
        : "+f"(d[0]), "+f"(d[1]), "+f"(d[2]), "+f"(d[3])
        : "r"(a[0]), "r"(a[1]), "r"(a[2]), "r"(a[3]), "r"(b[0]), "r"(b[1]));
}
__device__ __forceinline__ float elu1(float v) {
    return v > 0.f ? v : (__expf(v) - 1.f);
}

// ---- scratch (device globals; no allocation allowed) ----
__device__ float g_Wcat[F_IN * HID];
__device__ float g_Wh[(size_t)Bq * Nn * HID];
__device__ float g_s1[Bq * NHEADS * Nn];
__device__ float g_s2[Bq * NHEADS * Nn];
__device__ float g_x[(size_t)Bq * Nn * HID];
__device__ float g_Wx[(size_t)Bq * Nn * HID];
__device__ float g_t1[Bq * Nn];
__device__ float g_t2[Bq * Nn];
__device__ u32   g_att2[(size_t)Bq * Nn * Nn];   // tf32 att, 134 MB
__device__ float g_gat[Bq * HID];
__device__ float g_fpnh[Bq * HID];
__device__ float g_fpn[Bq * HID];
__device__ float g_buf1[Bq * HID];
__device__ float g_buf2[Bq * HID];

// ---------------------------------------------------------------------------
// 1x tf32 GEMM (fast path, big GEMMs). Validated R8.
// flags: 1 = bias, 2 = relu, 4 = accumulate
// ---------------------------------------------------------------------------
#define SA_STRIDE 20
#define SB_STRIDE 136

__global__ __launch_bounds__(256) void sgemm_tc_kernel(
    const float* __restrict__ A, const float* __restrict__ B,
    const float* __restrict__ bias, float* __restrict__ C,
    int M, int N, int K, int flags)
{
    __shared__ u32 sA[2][128 * SA_STRIDE];
    __shared__ u32 sB[2][16 * SB_STRIDE];

    int tid = threadIdx.x;
    int warp = tid >> 5, lane = tid & 31;
    int wr = warp >> 2, wc = warp & 3;
    int bm = blockIdx.y * 128;
    int bn = blockIdx.x * 128;
    int lr4 = lane >> 2, lc4 = lane & 3;

    float acc[4][4][4];
#pragma unroll
    for (int mt = 0; mt < 4; mt++)
#pragma unroll
        for (int nt = 0; nt < 4; nt++)
#pragma unroll
            for (int i = 0; i < 4; i++) acc[mt][nt][i] = 0.f;

    const int Ktiles = (K + 15) / 16;
    int aRow0 = tid >> 2,         aK0 = (tid & 3) * 4;
    int aRow1 = (tid + 256) >> 2, aK1 = ((tid + 256) & 3) * 4;
    int bK0 = tid >> 5,           bN0 = (tid & 31) * 4;
    int bK1 = (tid + 256) >> 5,   bN1 = ((tid + 256) & 31) * 4;

    float ar[2][4], br[2][4];
    {
#pragma unroll
        for (int i = 0; i < 4; i++) {
            int k = aK0 + i;
            ar[0][i] = (k < K) ? A[(size_t)(bm + aRow0) * K + k] : 0.f;
            k = aK1 + i;
            ar[1][i] = (k < K) ? A[(size_t)(bm + aRow1) * K + k] : 0.f;
        }
        if (bK0 < K) *(float4*)br[0] = *(const float4*)(B + (size_t)bK0 * N + bn + bN0);
        else { br[0][0] = br[0][1] = br[0][2] = br[0][3] = 0.f; }
        if (bK1 < K) *(float4*)br[1] = *(const float4*)(B + (size_t)bK1 * N + bn + bN1);
        else { br[1][0] = br[1][1] = br[1][2] = br[1][3] = 0.f; }
    }
#pragma unroll
    for (int i = 0; i < 4; i++) {
        sA[0][aRow0 * SA_STRIDE + aK0 + i] = to_tf32(ar[0][i]);
        sA[0][aRow1 * SA_STRIDE + aK1 + i] = to_tf32(ar[1][i]);
        sB[0][bK0 * SB_STRIDE + bN0 + i] = to_tf32(br[0][i]);
        sB[0][bK1 * SB_STRIDE + bN1 + i] = to_tf32(br[1][i]);
    }
    __syncthreads();

    int buf = 0;
    for (int t = 0; t < Ktiles; t++) {
        bool has_next = (t + 1 < Ktiles);
        if (has_next) {
            int k0 = (t + 1) * 16;
#pragma unroll
            for (int i = 0; i < 4; i++) {
                int k = k0 + aK0 + i;
                ar[0][i] = (k < K) ? A[(size_t)(bm + aRow0) * K + k] : 0.f;
                k = k0 + aK1 + i;
                ar[1][i] = (k < K) ? A[(size_t)(bm + aRow1) * K + k] : 0.f;
            }
            int k = k0 + bK0;
            if (k < K) *(float4*)br[0] = *(const float4*)(B + (size_t)k * N + bn + bN0);
            else { br[0][0] = br[0][1] = br[0][2] = br[0][3] = 0.f; }
            k = k0 + bK1;
            if (k < K) *(float4*)br[1] = *(const float4*)(B + (size_t)k * N + bn + bN1);
            else { br[1][0] = br[1][1] = br[1][2] = br[1][3] = 0.f; }
        }

        const u32* cA = sA[buf];
        const u32* cB = sB[buf];
#pragma unroll
        for (int kk = 0; kk < 16; kk += 8) {
            u32 afr[4][4], bfr[4][2];
#pragma unroll
            for (int mt = 0; mt < 4; mt++) {
                int r0 = wr * 64 + mt * 16 + lr4;
                int c0 = kk + lc4;
                afr[mt][0] = cA[r0 * SA_STRIDE + c0];
                afr[mt][1] = cA[(r0 + 8) * SA_STRIDE + c0];
                afr[mt][2] = cA[r0 * SA_STRIDE + c0 + 4];
                afr[mt][3] = cA[(r0 + 8) * SA_STRIDE + c0 + 4];
            }
#pragma unroll
            for (int nt = 0; nt < 4; nt++) {
                int col = wc * 32 + nt * 8 + lr4;
                bfr[nt][0] = cB[(kk + lc4) * SB_STRIDE + col];
                bfr[nt][1] = cB[(kk + lc4 + 4) * SB_STRIDE + col];
            }
#pragma unroll
            for (int mt = 0; mt < 4; mt++)
#pragma unroll
                for (int nt = 0; nt < 4; nt++)
                    mma_tf32(acc[mt][nt], afr[mt], bfr[nt]);
        }

        if (has_next) {
#pragma unroll
            for (int i = 0; i < 4; i++) {
                sA[buf ^ 1][aRow0 * SA_STRIDE + aK0 + i] = to_tf32(ar[0][i]);
                sA[buf ^ 1][aRow1 * SA_STRIDE + aK1 + i] = to_tf32(ar[1][i]);
                sB[buf ^ 1][bK0 * SB_STRIDE + bN0 + i] = to_tf32(br[0][i]);
                sB[buf ^ 1][bK1 * SB_STRIDE + bN1 + i] = to_tf32(br[1][i]);
            }
        }
        __syncthreads();
        buf ^= 1;
    }

#pragma unroll
    for (int mt = 0; mt < 4; mt++) {
#pragma unroll
        for (int nt = 0; nt < 4; nt++) {
            int col = bn + wc * 32 + nt * 8 + lc4 * 2;
#pragma unroll
            for (int half = 0; half < 2; half++) {
                int row = bm + wr * 64 + mt * 16 + lr4 + half * 8;
                float2 v = make_float2(acc[mt][nt][half * 2],
                                       acc[mt][nt][half * 2 + 1]);
                if (flags & 4) {
                    float2 c = *(const float2*)&C[(size_t)row * N + col];
                    v.x += c.x; v.y += c.y;
                }
                if (flags & 1) { v.x += bias[col]; v.y += bias[col + 1]; }
                if (flags & 2) { v.x = fmaxf(v.x, 0.f); v.y = fmaxf(v.y, 0.f); }
                *(float2*)&C[(size_t)row * N + col] = v;
            }
        }
    }
}

// ---------------------------------------------------------------------------
// av2: batched tf32 GEMM  D[b] = att2[b](128x128, tf32) @ Wx[b][:, bn..bn+127]
// with fused ELU + column-mean epilogue -> g_gat[b, bn + col].
// grid (4, Bq); same pipeline as sgemm_tc (A already tf32; K = M = 128).
// ---------------------------------------------------------------------------
__global__ __launch_bounds__(256) void av2_kernel()
{
    __shared__ u32 sA[2][128 * SA_STRIDE];
    __shared__ u32 sB[2][16 * SB_STRIDE];

    int tid = threadIdx.x;
    int warp = tid >> 5, lane = tid & 31;
    int wr = warp >> 2, wc = warp & 3;
    int b = blockIdx.y;
    int bn = blockIdx.x * 128;
    int lr4 = lane >> 2, lc4 = lane & 3;

    const u32*   Ab = g_att2 + (size_t)b * Nn * Nn;          // 128x128 tf32
    const float* Bb = g_Wx + (size_t)b * Nn * HID;            // 128x512

    float acc[4][4][4];
#pragma unroll
    for (int mt = 0; mt < 4; mt++)
#pragma unroll
        for (int nt = 0; nt < 4; nt++)
#pragma unroll
            for (int i = 0; i < 4; i++) acc[mt][nt][i] = 0.f;

    int aRow0 = tid >> 2,         aK0 = (tid & 3) * 4;
    int aRow1 = (tid + 256) >> 2, aK1 = ((tid + 256) & 3) * 4;
    int bK0 = tid >> 5,           bN0 = (tid & 31) * 4;
    int bK1 = (tid + 256) >> 5,   bN1 = ((tid + 256) & 31) * 4;

    // preload tile 0
    {
        *(uint4*)&sA[0][aRow0 * SA_STRIDE + aK0] = *(const uint4*)(Ab + (size_t)aRow0 * Nn + aK0);
        *(uint4*)&sA[0][aRow1 * SA_STRIDE + aK1] = *(const uint4*)(Ab + (size_t)aRow1 * Nn + aK1);
        float4 v0 = *(const float4*)(Bb + (size_t)bK0 * HID + bn + bN0);
        float4 v1 = *(const float4*)(Bb + (size_t)bK1 * HID + bn + bN1);
        sB[0][bK0 * SB_STRIDE + bN0 + 0] = to_tf32(v0.x);
        sB[0][bK0 * SB_STRIDE + bN0 + 1] = to_tf32(v0.y);
        sB[0][bK0 * SB_STRIDE + bN0 + 2] = to_tf32(v0.z);
        sB[0][bK0 * SB_STRIDE + bN0 + 3] = to_tf32(v0.w);
        sB[0][bK1 * SB_STRIDE + bN1 + 0] = to_tf32(v1.x);
        sB[0][bK1 * SB_STRIDE + bN1 + 1] = to_tf32(v1.y);
        sB[0][bK1 * SB_STRIDE + bN1 + 2] = to_tf32(v1.z);
        sB[0][bK1 * SB_STRIDE + bN1 + 3] = to_tf32(v1.w);
    }
    __syncthreads();

    int buf = 0;
    for (int t = 0; t < 8; t++) {                 // K = 128, BK = 16
        bool has_next = (t + 1 < 8);
        uint4 an0, an1;
        float4 v0, v1;
        if (has_next) {
            int k0 = (t + 1) * 16;
            an0 = *(const uint4*)(Ab + (size_t)aRow0 * Nn + k0 + aK0);
            an1 = *(const uint4*)(Ab + (size_t)aRow1 * Nn + k0 + aK1);
            v0 = *(const float4*)(Bb + (size_t)(k0 + bK0) * HID + bn + bN0);
            v1 = *(const float4*)(Bb + (size_t)(k0 + bK1) * HID + bn + bN1);
        }

        const u32* cA = sA[buf];
        const u32* cB = sB[buf];
#pragma unroll
        for (int kk = 0; kk < 16; kk += 8) {
            u32 afr[4][4], bfr[4][2];
#pragma unroll
            for (int mt = 0; mt < 4; mt++) {
                int r0 = wr * 64 + mt * 16 + lr4;
                int c0 = kk + lc4;
                afr[mt][0] = cA[r0 * SA_STRIDE + c0];
                afr[mt][1] = cA[(r0 + 8) * SA_STRIDE + c0];
                afr[mt][2] = cA[r0 * SA_STRIDE + c0 + 4];
                afr[mt][3] = cA[(r0 + 8) * SA_STRIDE + c0 + 4];
            }
#pragma unroll
            for (int nt = 0; nt < 4; nt++) {
                int col = wc * 32 + nt * 8 + lr4;
                bfr[nt][0] = cB[(kk + lc4) * SB_STRIDE + col];
                bfr[nt][1] = cB[(kk + lc4 + 4) * SB_STRIDE + col];
            }
#pragma unroll
            for (int mt = 0; mt < 4; mt++)
#pragma unroll
                for (int nt = 0; nt < 4; nt++)
                    mma_tf32(acc[mt][nt], afr[mt], bfr[nt]);
        }

        if (has_next) {
            *(uint4*)&sA[buf ^ 1][aRow0 * SA_STRIDE + aK0] = an0;
            *(uint4*)&sA[buf ^ 1][aRow1 * SA_STRIDE + aK1] = an1;
            sB[buf ^ 1][bK0 * SB_STRIDE + bN0 + 0] = to_tf32(v0.x);
            sB[buf ^ 1][bK0 * SB_STRIDE + bN0 + 1] = to_tf32(v0.y);
            sB[buf ^ 1][bK0 * SB_STRIDE + bN0 + 2] = to_tf32(v0.z);
            sB[buf ^ 1][bK0 * SB_STRIDE + bN0 + 3] = to_tf32(v0.w);
            sB[buf ^ 1][bK1 * SB_STRIDE + bN1 + 0] = to_tf32(v1.x);
            sB[buf ^ 1][bK1 * SB_STRIDE + bN1 + 1] = to_tf32(v1.y);
            sB[buf ^ 1][bK1 * SB_STRIDE + bN1 + 2] = to_tf32(v1.z);
            sB[buf ^ 1][bK1 * SB_STRIDE + bN1 + 3] = to_tf32(v1.w);
        }
        __syncthreads();
        buf ^= 1;
    }

    // ---- epilogue: ELU + column sums over all 128 rows -> gat/128 ----
    // per-thread: 8 rows (4 mt x 2 half) x 8 cols (4 nt x 2)
    float cs[4][2];
#pragma unroll
    for (int nt = 0; nt < 4; nt++) {
        cs[nt][0] = 0.f; cs[nt][1] = 0.f;
#pragma unroll
        for (int mt = 0; mt < 4; mt++) {
            cs[nt][0] += elu1(acc[mt][nt][0]) + elu1(acc[mt][nt][2]);
            cs[nt][1] += elu1(acc[mt][nt][1]) + elu1(acc[mt][nt][3]);
        }
    }
    // reduce over lr4 (xor 4, 8, 16) -> sum over this wr's 64 rows
#pragma unroll
    for (int o = 4; o <= 16; o <<= 1) {
#pragma unroll
        for (int nt = 0; nt < 4; nt++) {
            cs[nt][0] += __shfl_xor_sync(0xffffffffu, cs[nt][0], o);
            cs[nt][1] += __shfl_xor_sync(0xffffffffu, cs[nt][1], o);
        }
    }
    float* scratch = (float*)sA;   // all smem reads done (post-sync)
    if (lr4 == 0) {
#pragma unroll
        for (int nt = 0; nt < 4; nt++) {
            int col = wc * 32 + nt * 8 + lc4 * 2;
            scratch[wr * 128 + col]     = cs[nt][0];
            scratch[wr * 128 + col + 1] = cs[nt][1];
        }
    }
    __syncthreads();
    if (tid < 128)
        g_gat[(size_t)b * HID + bn + tid] =
            (scratch[tid] + scratch[128 + tid]) * (1.f / 128.f);
}

// ---------------------------------------------------------------------------
// softmax2: per (b, half) block, computes att rows and writes tf32 to g_att2.
// ---------------------------------------------------------------------------
__global__ __launch_bounds__(256) void softmax2_kernel(
    const float* __restrict__ ae_out, const int* __restrict__ adj,
    const float* __restrict__ edge)
{
    __shared__ float st1[64];
    __shared__ float st2[128];

    int tid = threadIdx.x;
    int blk = blockIdx.x;
    int hb = blk & 1;
    int b = blk >> 1;
    int i0 = hb * 64;
    float ae = ae_out[0];

    if (tid < 64)  st1[tid] = g_t1[b * Nn + i0 + tid];
    else if (tid < 192) st2[tid - 64] = g_t2[b * Nn + tid - 64];
    __syncthreads();

    int warp = tid >> 5, lane = tid & 31;
    for (int i = warp; i < 64; i += 8) {
        int row = i0 + i;
        float4 ef = ((const float4*)(edge + ((size_t)b * Nn + row) * Nn))[lane];
        int4  av  = ((const int4*)(adj  + ((size_t)b * Nn + row) * Nn))[lane];
        float si = st1[i];
        int j0 = lane * 4;
        float v0 = si + st2[j0 + 0] + ef.x * ae; v0 = v0 >= 0.f ? v0 : 0.2f * v0; v0 = av.x > 0 ? v0 : -9e15f;
        float v1 = si + st2[j0 + 1] + ef.y * ae; v1 = v1 >= 0.f ? v1 : 0.2f * v1; v1 = av.y > 0 ? v1 : -9e15f;
        float v2 = si + st2[j0 + 2] + ef.z * ae; v2 = v2 >= 0.f ? v2 : 0.2f * v2; v2 = av.z > 0 ? v2 : -9e15f;
        float v3 = si + st2[j0 + 3] + ef.w * ae; v3 = v3 >= 0.f ? v3 : 0.2f * v3; v3 = av.w > 0 ? v3 : -9e15f;
        float m = fmaxf(fmaxf(v0, v1), fmaxf(v2, v3));
#pragma unroll
        for (int o = 16; o; o >>= 1) m = fmaxf(m, __shfl_xor_sync(0xffffffffu, m, o));
        float e0 = __expf(v0 - m), e1 = __expf(v1 - m), e2 = __expf(v2 - m), e3 = __expf(v3 - m);
        float s = e0 + e1 + e2 + e3;
#pragma unroll
        for (int o = 16; o; o >>= 1) s += __shfl_xor_sync(0xffffffffu, s, o);
        float inv = 1.f / s;
        uint4 o4;
        o4.x = to_tf32(e0 * inv); o4.y = to_tf32(e1 * inv);
        o4.z = to_tf32(e2 * inv); o4.w = to_tf32(e3 * inv);
        *(uint4*)(g_att2 + ((size_t)b * Nn + row) * Nn + j0) = o4;
    }
}

// ---------------------------------------------------------------------------
// Tail fp32 GEMM (exact): BM=BN=64, BK=16, 256 threads. Validated R10.
// ---------------------------------------------------------------------------
__global__ __launch_bounds__(256) void tail_gemm_kernel(
    const float* __restrict__ A, const float* __restrict__ B,
    const float* __restrict__ bias, float* __restrict__ C,
    int M, int N, int K, int flags)
{
    __shared__ float As[2][16][64];
    __shared__ float Bs[2][16][64];

    int tid = threadIdx.x;
    int bm = blockIdx.y * 64;
    int bn = blockIdx.x * 64;
    int tx = tid & 15;
    int ty = tid >> 4;

    int aRow = tid >> 2, aK = (tid & 3) * 4;
    int bK = tid >> 4, bN = (tid & 15) * 4;

    u64 acc[4][2];
#pragma unroll
    for (int i = 0; i < 4; i++) { acc[i][0] = 0ull; acc[i][1] = 0ull; }

    const int Ktiles = (K + 15) / 16;
    const float* Arow = A + (size_t)(bm + aRow) * K;

    {
#pragma unroll
        for (int i = 0; i < 4; i++) {
            int k = aK + i;
            As[0][aK + i][aRow] = (k < K) ? Arow[k] : 0.f;
        }
        float4 v = make_float4(0.f, 0.f, 0.f, 0.f);
        if (bK < K) v = *(const float4*)(B + (size_t)bK * N + bn + bN);
        *(float4*)&Bs[0][bK][bN] = v;
    }
    __syncthreads();

    int buf = 0;
    for (int t = 0; t < Ktiles; t++) {
        float ap[4];
        float4 bp = make_float4(0.f, 0.f, 0.f, 0.f);
        bool has_next = (t + 1 < Ktiles);
        if (has_next) {
            int k0 = (t + 1) * 16;
#pragma unroll
            for (int i = 0; i < 4; i++) {
                int k = k0 + aK + i;
                ap[i] = (k < K) ? Arow[k] : 0.f;
            }
            int k = k0 + bK;
            if (k < K) bp = *(const float4*)(B + (size_t)k * N + bn + bN);
        }

#pragma unroll
        for (int kk = 0; kk < 16; kk++) {
            u64 b0 = *(const u64*)&Bs[buf][kk][tx * 4];
            u64 b1 = *(const u64*)&Bs[buf][kk][tx * 4 + 2];
            float a0 = As[buf][kk][ty * 4];
            float a1 = As[buf][kk][ty * 4 + 1];
            float a2 = As[buf][kk][ty * 4 + 2];
            float a3 = As[buf][kk][ty * 4 + 3];
            u64 d0 = dup2(a0), d1 = dup2(a1), d2 = dup2(a2), d3 = dup2(a3);
            fma2(acc[0][0], d0, b0); fma2(acc[0][1], d0, b1);
            fma2(acc[1][0], d1, b0); fma2(acc[1][1], d1, b1);
            fma2(acc[2][0], d2, b0); fma2(acc[2][1], d2, b1);
            fma2(acc[3][0], d3, b0); fma2(acc[3][1], d3, b1);
        }

        if (has_next) {
#pragma unroll
            for (int i = 0; i < 4; i++) As[buf ^ 1][aK + i][aRow] = ap[i];
            *(float4*)&Bs[buf ^ 1][bK][bN] = bp;
        }
        __syncthreads();
        buf ^= 1;
    }

#pragma unroll
    for (int i = 0; i < 4; i++) {
        int row = bm + ty * 4 + i;
#pragma unroll
        for (int j = 0; j < 2; j++) {
            int col = bn + tx * 4 + j * 2;
            float2 v = upk2(acc[i][j]);
            if (flags & 4) {
                float2 c = *(const float2*)&C[(size_t)row * N + col];
                v.x += c.x; v.y += c.y;
            }
            if (flags & 1) { v.x += bias[col]; v.y += bias[col + 1]; }
            if (flags & 2) { v.x = fmaxf(v.x, 0.f); v.y = fmaxf(v.y, 0.f); }
            *(float2*)&C[(size_t)row * N + col] = v;
        }
    }
}

// ---------------------------------------------------------------------------
__global__ void wcat_kernel(const float* __restrict__ W_heads)
{
    int idx = blockIdx.x * blockDim.x + threadIdx.x;
    if (idx >= NHEADS * F_IN * NHID) return;
    int h = idx / (F_IN * NHID);
    int rem = idx - h * (F_IN * NHID);
    int f = rem / NHID;
    int d = rem - f * NHID;
    g_Wcat[f * HID + h * NHID + d] = W_heads[idx];
}

// ---------------------------------------------------------------------------
__global__ __launch_bounds__(256) void s12_kernel(
    const float* __restrict__ a1, const float* __restrict__ a2)
{
    int gw = (blockIdx.x * blockDim.x + threadIdx.x) >> 5;
    int lane = threadIdx.x & 31;
    if (gw >= Bq * NHEADS * Nn) return;
    int n  = gw & 127;
    int hh = (gw >> 7) & 7;
    int b  = gw >> 10;
    const float* row = g_Wh + ((size_t)b * Nn + n) * HID + hh * NHID;
    const float* av1 = a1 + hh * NHID;
    const float* av2 = a2 + hh * NHID;
    float x0 = row[lane], x1 = row[lane + 32];
    float r1 = x0 * av1[lane] + x1 * av1[lane + 32];
    float r2 = x0 * av2[lane] + x1 * av2[lane + 32];
#pragma unroll
    for (int o = 16; o; o >>= 1) {
        r1 += __shfl_xor_sync(0xffffffffu, r1, o);
        r2 += __shfl_xor_sync(0xffffffffu, r2, o);
    }
    if (lane == 0) {
        int o = (b * NHEADS + hh) * Nn + n;
        g_s1[o] = r1;
        g_s2[o] = r2;
    }
}

// ---------------------------------------------------------------------------
__global__ __launch_bounds__(256) void t12_kernel(
    const float* __restrict__ a1, const float* __restrict__ a2)
{
    int gw = (blockIdx.x * blockDim.x + threadIdx.x) >> 5;
    int lane = threadIdx.x & 31;
    if (gw >= Bq * Nn) return;
    const float* row = g_Wx + (size_t)gw * HID;
    float r1 = 0.f, r2 = 0.f;
#pragma unroll
    for (int c0 = 0; c0 < HID; c0 += 128) {
        float4 v = *(const float4*)(row + c0 + lane * 4);
        float4 w1 = *(const float4*)(a1 + c0 + lane * 4);
        float4 w2 = *(const float4*)(a2 + c0 + lane * 4);
        r1 += v.x * w1.x + v.y * w1.y + v.z * w1.z + v.w * w1.w;
        r2 += v.x * w2.x + v.y * w2.y + v.z * w2.z + v.w * w2.w;
    }
#pragma unroll
    for (int o = 16; o; o >>= 1) {
        r1 += __shfl_xor_sync(0xffffffffu, r1, o);
        r2 += __shfl_xor_sync(0xffffffffu, r2, o);
    }
    if (lane == 0) { g_t1[gw] = r1; g_t2[gw] = r2; }
}

// ---------------------------------------------------------------------------
// attn1 (tf32 mma, 32-col B-chunks): R11 form, 55 KB -> 4 CTAs/SM.
// ---------------------------------------------------------------------------
#define WCH_STR 40
#define AT_STR 132

__global__ __launch_bounds__(256) void attn1_kernel(
    const float* __restrict__ ae_heads, const int* __restrict__ adj,
    const float* __restrict__ edge)
{
    extern __shared__ u32 smu[];
    u32* sWh  = smu;                        // 128*40
    u32* sAtt = smu + 128 * WCH_STR;        // 64*132
    float* ss1 = (float*)(smu + 128 * WCH_STR + 64 * AT_STR);  // 64
    float* ss2 = ss1 + 64;                                      // 128

    int tid = threadIdx.x;
    int blk = blockIdx.x;
    int hb = blk & 1;
    int bh = blk >> 1;
    int hh = bh & 7, b = bh >> 3;
    int i0 = hb * 64;
    float ae = ae_heads[hh];

    if (tid < 64)  ss1[tid] = g_s1[bh * Nn + i0 + tid];
    if (tid < 128) ss2[tid] = g_s2[bh * Nn + tid];
    __syncthreads();

    int warp = tid >> 5, lane = tid & 31;
    for (int i = warp; i < 64; i += 8) {
        int row = i0 + i;
        float4 ef = ((const float4*)(edge + ((size_t)b * Nn + row) * Nn))[lane];
        int4  av  = ((const int4*)(adj  + ((size_t)b * Nn + row) * Nn))[lane];
        float si = ss1[i];
        int j0 = lane * 4;
        float v0 = si + ss2[j0 + 0] + ef.x * ae; v0 = v0 >= 0.f ? v0 : 0.2f * v0; v0 = av.x > 0 ? v0 : -9e15f;
        float v1 = si + ss2[j0 + 1] + ef.y * ae; v1 = v1 >= 0.f ? v1 : 0.2f * v1; v1 = av.y > 0 ? v1 : -9e15f;
        float v2 = si + ss2[j0 + 2] + ef.z * ae; v2 = v2 >= 0.f ? v2 : 0.2f * v2; v2 = av.z > 0 ? v2 : -9e15f;
        float v3 = si + ss2[j0 + 3] + ef.w * ae; v3 = v3 >= 0.f ? v3 : 0.2f * v3; v3 = av.w > 0 ? v3 : -9e15f;
        float m = fmaxf(fmaxf(v0, v1), fmaxf(v2, v3));
#pragma unroll
        for (int o = 16; o; o >>= 1) m = fmaxf(m, __shfl_xor_sync(0xffffffffu, m, o));
        float e0 = __expf(v0 - m), e1 = __expf(v1 - m), e2 = __expf(v2 - m), e3 = __expf(v3 - m);
        float s = e0 + e1 + e2 + e3;
#pragma unroll
        for (int o = 16; o; o >>= 1) s += __shfl_xor_sync(0xffffffffu, s, o);
        float inv = 1.f / s;
        uint4 o4;
        o4.x = to_tf32(e0 * inv); o4.y = to_tf32(e1 * inv);
        o4.z = to_tf32(e2 * inv); o4.w = to_tf32(e3 * inv);
        *(uint4*)&sAtt[i * AT_STR + lane * 4] = o4;
    }

    int wr = warp >> 2, wc = warp & 3;
    int lr4 = lane >> 2, lc4 = lane & 3;

    const float* whp = g_Wh + (size_t)b * Nn * HID + hh * NHID;

#pragma unroll
    for (int ch = 0; ch < 2; ch++) {
        __syncthreads();
        for (int i = tid; i < 128 * 8; i += 256) {
            int r = i >> 3, c = (i & 7) * 4;
            float4 v = *(const float4*)(whp + (size_t)r * HID + ch * 32 + c);
            uint4 t;
            t.x = to_tf32(v.x); t.y = to_tf32(v.y);
            t.z = to_tf32(v.z); t.w = to_tf32(v.w);
            *(uint4*)&sWh[r * WCH_STR + c] = t;
        }
        __syncthreads();

        float acc[2][4];
#pragma unroll
        for (int mt = 0; mt < 2; mt++)
#pragma unroll
            for (int i = 0; i < 4; i++) acc[mt][i] = 0.f;

#pragma unroll
        for (int kk = 0; kk < 128; kk += 8) {
            u32 afr[2][4], bfr[2];
#pragma unroll
            for (int mt = 0; mt < 2; mt++) {
                int r0 = wr * 32 + mt * 16 + lr4;
                int c0 = kk + lc4;
                afr[mt][0] = sAtt[r0 * AT_STR + c0];
                afr[mt][1] = sAtt[(r0 + 8) * AT_STR + c0];
                afr[mt][2] = sAtt[r0 * AT_STR + c0 + 4];
                afr[mt][3] = sAtt[(r0 + 8) * AT_STR + c0 + 4];
            }
            {
                int col = wc * 8 + lr4;
                bfr[0] = sWh[(kk + lc4) * WCH_STR + col];
                bfr[1] = sWh[(kk + lc4 + 4) * WCH_STR + col];
            }
#pragma unroll
            for (int mt = 0; mt < 2; mt++)
                mma_tf32(acc[mt], afr[mt], bfr);
        }

#pragma unroll
        for (int mt = 0; mt < 2; mt++) {
            int col = ch * 32 + wc * 8 + lc4 * 2;
#pragma unroll
            for (int half = 0; half < 2; half++) {
                int i = i0 + wr * 32 + mt * 16 + lr4 + half * 8;
                float2 v;
                v.x = elu1(acc[mt][half * 2]);
                v.y = elu1(acc[mt][half * 2 + 1]);
                *(float2*)(g_x + ((size_t)b * Nn + i) * HID + hh * NHID + col) = v;
            }
        }
    }
}

// ---------------------------------------------------------------------------
__global__ void final_kernel(const float* __restrict__ X,
                             const float* __restrict__ W,
                             const float* __restrict__ bias,
                             float* __restrict__ out)
{
    int idx = blockIdx.x * blockDim.x + threadIdx.x;
    if (idx >= Bq * TASKS) return;
    int b = idx / TASKS, t = idx - b * TASKS;
    const float* x = X + (size_t)b * HID;
    float s = bias[t];
    for (int d = 0; d < HID; d++) s += x[d] * W[d * TASKS + t];
    out[idx] = s;
}

// ---------------------------------------------------------------------------
extern "C" void kernel_launch(void* const* d_in, const int* in_sizes, int n_in,
                              void* d_out, int out_size)
{
    const float* h        = (const float*)d_in[0];
    const int*   adj      = (const int*)d_in[1];
    const float* edge     = (const float*)d_in[2];
    const float* fp       = (const float*)d_in[3];
    const float* W_heads  = (const float*)d_in[4];
    const float* a1_heads = (const float*)d_in[5];
    const float* a2_heads = (const float*)d_in[6];
    const float* ae_heads = (const float*)d_in[7];
    const float* W_out    = (const float*)d_in[8];
    const float* a1_out   = (const float*)d_in[9];
    const float* a2_out   = (const float*)d_in[10];
    const float* ae_out   = (const float*)d_in[11];
    const float* fc1_w    = (const float*)d_in[12];
    const float* fc1_b    = (const float*)d_in[13];
    const float* fc2_w    = (const float*)d_in[14];
    const float* fc2_b    = (const float*)d_in[15];
    const float* q_w      = (const float*)d_in[16];
    const float* q_b      = (const float*)d_in[17];
    // k_w (18), k_b (19) unused: softmax over size-1 axis == 1 -> fused = q+v
    const float* v_w      = (const float*)d_in[20];
    const float* v_b      = (const float*)d_in[21];
    const float* o_w      = (const float*)d_in[22];
    const float* o_b      = (const float*)d_in[23];
    const float* ffn1_w   = (const float*)d_in[24];
    const float* ffn1_b   = (const float*)d_in[25];
    const float* ffn2_w   = (const float*)d_in[26];
    const float* ffn2_b   = (const float*)d_in[27];
    float* out = (float*)d_out;

    float *Wh, *x, *gat, *fpnh, *fpn, *buf1, *buf2, *Wx, *Wcat;
    cudaGetSymbolAddress((void**)&Wh, g_Wh);
    cudaGetSymbolAddress((void**)&x, g_x);
    cudaGetSymbolAddress((void**)&Wx, g_Wx);
    cudaGetSymbolAddress((void**)&gat, g_gat);
    cudaGetSymbolAddress((void**)&fpnh, g_fpnh);
    cudaGetSymbolAddress((void**)&fpn, g_fpn);
    cudaGetSymbolAddress((void**)&buf1, g_buf1);
    cudaGetSymbolAddress((void**)&buf2, g_buf2);
    cudaGetSymbolAddress((void**)&Wcat, g_Wcat);

    const int ATT1_SMEM = (128 * WCH_STR + 64 * AT_STR + 192) * 4;   // 55040
    cudaFuncSetAttribute(attn1_kernel, cudaFuncAttributeMaxDynamicSharedMemorySize, ATT1_SMEM);

    const int M1 = Bq * Nn;  // 65536

    // 1. Wcat transpose
    wcat_kernel<<<(NHEADS * F_IN * NHID + 255) / 256, 256>>>(W_heads);

    // 2. Wh = h @ Wcat  (fast tf32)
    {
        dim3 grid(HID / 128, M1 / 128);
        sgemm_tc_kernel<<<grid, 256>>>(h, Wcat, nullptr, Wh, M1, HID, F_IN, 0);
    }

    // 3. s1/s2
    s12_kernel<<<(Bq * NHEADS * Nn * 32) / 256, 256>>>(a1_heads, a2_heads);

    // 4. attn1 (tf32 mma, 32-col chunks, 4 CTAs/SM)
    attn1_kernel<<<Bq * NHEADS * 2, 256, ATT1_SMEM>>>(ae_heads, adj, edge);

    // 5. Wx = x @ W_out (fast tf32)
    {
        dim3 grid(HID / 128, M1 / 128);
        sgemm_tc_kernel<<<grid, 256>>>(x, W_out, nullptr, Wx, M1, HID, HID, 0);
    }

    // 6. t1/t2
    t12_kernel<<<(Bq * Nn * 32) / 256, 256>>>(a1_out, a2_out);

    // 7. attn2 split: softmax -> gmem att (tf32), then batched AV GEMM
    //    with fused ELU + column-mean -> gat
    softmax2_kernel<<<Bq * 2, 256>>>(ae_out, adj, edge);
    {
        dim3 grid(HID / 128, Bq);
        av2_kernel<<<grid, 256>>>();
    }

    // 8. FPN (exact fp32 tails)
    {
        dim3 grid(HID / 64, Bq / 64);
        tail_gemm_kernel<<<grid, 256>>>(fp, fc1_w, fc1_b, fpnh, Bq, HID, FP_DIM, 1 | 2);
        tail_gemm_kernel<<<grid, 256>>>(fpnh, fc2_w, fc2_b, fpn, Bq, HID, HID, 1);
    }

    // 9. fusion + FFN (exact fp32 tails)
    {
        dim3 grid(HID / 64, Bq / 64);
        tail_gemm_kernel<<<grid, 256>>>(gat, q_w, q_b, buf1, Bq, HID, HID, 1);
        tail_gemm_kernel<<<grid, 256>>>(fpn, v_w, v_b, buf1, Bq, HID, HID, 1 | 4);
        tail_gemm_kernel<<<grid, 256>>>(buf1, o_w, o_b, buf2, Bq, HID, HID, 1 | 2);
        tail_gemm_kernel<<<grid, 256>>>(buf2, ffn1_w, ffn1_b, buf1, Bq, HID, HID, 1 | 2);
    }

    // 10. final projection
    final_kernel<<<(Bq * TASKS + 255) / 256, 256>>>(buf1, ffn2_w, ffn2_b, out);
}

// round 14
// speedup vs baseline: 1.1043x; 1.0542x over previous
#include <cuda_runtime.h>
#include <cuda_bf16.h>
#include <math.h>

// ---------------------------------------------------------------------------
// FPGNN forward. R14:
//  - Wh GEMM: tf32 mma + fused s1/s2 epilogue (per-head dots, no s12 kernel)
//  - Wx GEMM: tf32 mma + fused t1/t2 partial epilogue (+tiny combine kernel)
//  - attn1: tf32 mma, 32-col chunks, chunk-0 prefetch, no-max softmax
//  - attn2: softmax2 (no-max) -> gmem tf32 att, av2 batched tf32 GEMM
//  - tail GEMMs: exact fp32 FFMA2, 64x64 tiles
// ---------------------------------------------------------------------------

#define Bq 512
#define Nn 128
#define F_IN 133
#define NHEADS 8
#define NHID 64
#define HID 512
#define FP_DIM 1489
#define TASKS 12

typedef unsigned long long u64;
typedef unsigned int u32;

__device__ __forceinline__ u64 pack2(float lo, float hi) {
    u64 r; asm("mov.b64 %0, {%1,%2};" : "=l"(r) : "f"(lo), "f"(hi)); return r;
}
__device__ __forceinline__ u64 dup2(float v) { return pack2(v, v); }
__device__ __forceinline__ void fma2(u64& d, u64 a, u64 b) {
    asm("fma.rn.f32x2 %0, %1, %2, %0;" : "+l"(d) : "l"(a), "l"(b));
}
__device__ __forceinline__ float2 upk2(u64 v) {
    float2 r; asm("mov.b64 {%0,%1}, %2;" : "=f"(r.x), "=f"(r.y) : "l"(v)); return r;
}
__device__ __forceinline__ u32 to_tf32(float f) {
    u32 r; asm("cvt.rna.tf32.f32 %0, %1;" : "=r"(r) : "f"(f)); return r;
}
__device__ __forceinline__ void mma_tf32(float* d, const u32* a, const u32* b) {
    asm volatile(
        "mma.sync.aligned.m16n8k8.row.col.f32.tf32.tf32.f32 "
        "{%0,%1,%2,%3}, {%4,%5,%6,%7}, {%8,%9}, {%0,%1,%2,%3};\n"
        : "+f"(d[0]), "+f"(d[1]), "+f"(d[2]), "+f"(d[3])
        : "r"(a[0]), "r"(a[1]), "r"(a[2]), "r"(a[3]), "r"(b[0]), "r"(b[1]));
}
__device__ __forceinline__ float elu1(float v) {
    return v > 0.f ? v : (__expf(v) - 1.f);
}

// ---- scratch (device globals; no allocation allowed) ----
__device__ float g_Wcat[F_IN * HID];
__device__ float g_Wh[(size_t)Bq * Nn * HID];
__device__ float g_s1[Bq * NHEADS * Nn];
__device__ float g_s2[Bq * NHEADS * Nn];
__device__ float g_x[(size_t)Bq * Nn * HID];
__device__ float g_Wx[(size_t)Bq * Nn * HID];
__device__ float g_t1[Bq * Nn];
__device__ float g_t2[Bq * Nn];
__device__ float g_t1p[4 * Bq * Nn];
__device__ float g_t2p[4 * Bq * Nn];
__device__ u32   g_att2[(size_t)Bq * Nn * Nn];   // tf32 att, 134 MB
__device__ float g_gat[Bq * HID];
__device__ float g_fpnh[Bq * HID];
__device__ float g_fpn[Bq * HID];
__device__ float g_buf1[Bq * HID];
__device__ float g_buf2[Bq * HID];

// ---------------------------------------------------------------------------
// 1x tf32 GEMM (validated R8) + optional fused score epilogue.
// flags: 1 = bias, 2 = relu, 4 = accumulate
// smode: 0 none; 1 = per-64col-head final dots -> so1/so2 = g_s1/g_s2 layout
//        [b*8+h]*128+n; 2 = per-CTA 128-col partials -> so1[bx*M + row].
// ---------------------------------------------------------------------------
#define SA_STRIDE 20
#define SB_STRIDE 136

__global__ __launch_bounds__(256) void sgemm_tc_kernel(
    const float* __restrict__ A, const float* __restrict__ B,
    const float* __restrict__ bias, float* __restrict__ C,
    int M, int N, int K, int flags,
    int smode, const float* __restrict__ av1, const float* __restrict__ av2,
    float* __restrict__ so1, float* __restrict__ so2)
{
    __shared__ u32 sA[2][128 * SA_STRIDE];
    __shared__ u32 sB[2][16 * SB_STRIDE];

    int tid = threadIdx.x;
    int warp = tid >> 5, lane = tid & 31;
    int wr = warp >> 2, wc = warp & 3;
    int bm = blockIdx.y * 128;
    int bn = blockIdx.x * 128;
    int lr4 = lane >> 2, lc4 = lane & 3;

    float acc[4][4][4];
#pragma unroll
    for (int mt = 0; mt < 4; mt++)
#pragma unroll
        for (int nt = 0; nt < 4; nt++)
#pragma unroll
            for (int i = 0; i < 4; i++) acc[mt][nt][i] = 0.f;

    const int Ktiles = (K + 15) / 16;
    int aRow0 = tid >> 2,         aK0 = (tid & 3) * 4;
    int aRow1 = (tid + 256) >> 2, aK1 = ((tid + 256) & 3) * 4;
    int bK0 = tid >> 5,           bN0 = (tid & 31) * 4;
    int bK1 = (tid + 256) >> 5,   bN1 = ((tid + 256) & 31) * 4;

    float ar[2][4], br[2][4];
    {
#pragma unroll
        for (int i = 0; i < 4; i++) {
            int k = aK0 + i;
            ar[0][i] = (k < K) ? A[(size_t)(bm + aRow0) * K + k] : 0.f;
            k = aK1 + i;
            ar[1][i] = (k < K) ? A[(size_t)(bm + aRow1) * K + k] : 0.f;
        }
        if (bK0 < K) *(float4*)br[0] = *(const float4*)(B + (size_t)bK0 * N + bn + bN0);
        else { br[0][0] = br[0][1] = br[0][2] = br[0][3] = 0.f; }
        if (bK1 < K) *(float4*)br[1] = *(const float4*)(B + (size_t)bK1 * N + bn + bN1);
        else { br[1][0] = br[1][1] = br[1][2] = br[1][3] = 0.f; }
    }
#pragma unroll
    for (int i = 0; i < 4; i++) {
        sA[0][aRow0 * SA_STRIDE + aK0 + i] = to_tf32(ar[0][i]);
        sA[0][aRow1 * SA_STRIDE + aK1 + i] = to_tf32(ar[1][i]);
        sB[0][bK0 * SB_STRIDE + bN0 + i] = to_tf32(br[0][i]);
        sB[0][bK1 * SB_STRIDE + bN1 + i] = to_tf32(br[1][i]);
    }
    __syncthreads();

    int buf = 0;
    for (int t = 0; t < Ktiles; t++) {
        bool has_next = (t + 1 < Ktiles);
        if (has_next) {
            int k0 = (t + 1) * 16;
#pragma unroll
            for (int i = 0; i < 4; i++) {
                int k = k0 + aK0 + i;
                ar[0][i] = (k < K) ? A[(size_t)(bm + aRow0) * K + k] : 0.f;
                k = k0 + aK1 + i;
                ar[1][i] = (k < K) ? A[(size_t)(bm + aRow1) * K + k] : 0.f;
            }
            int k = k0 + bK0;
            if (k < K) *(float4*)br[0] = *(const float4*)(B + (size_t)k * N + bn + bN0);
            else { br[0][0] = br[0][1] = br[0][2] = br[0][3] = 0.f; }
            k = k0 + bK1;
            if (k < K) *(float4*)br[1] = *(const float4*)(B + (size_t)k * N + bn + bN1);
            else { br[1][0] = br[1][1] = br[1][2] = br[1][3] = 0.f; }
        }

        const u32* cA = sA[buf];
        const u32* cB = sB[buf];
#pragma unroll
        for (int kk = 0; kk < 16; kk += 8) {
            u32 afr[4][4], bfr[4][2];
#pragma unroll
            for (int mt = 0; mt < 4; mt++) {
                int r0 = wr * 64 + mt * 16 + lr4;
                int c0 = kk + lc4;
                afr[mt][0] = cA[r0 * SA_STRIDE + c0];
                afr[mt][1] = cA[(r0 + 8) * SA_STRIDE + c0];
                afr[mt][2] = cA[r0 * SA_STRIDE + c0 + 4];
                afr[mt][3] = cA[(r0 + 8) * SA_STRIDE + c0 + 4];
            }
#pragma unroll
            for (int nt = 0; nt < 4; nt++) {
                int col = wc * 32 + nt * 8 + lr4;
                bfr[nt][0] = cB[(kk + lc4) * SB_STRIDE + col];
                bfr[nt][1] = cB[(kk + lc4 + 4) * SB_STRIDE + col];
            }
#pragma unroll
            for (int mt = 0; mt < 4; mt++)
#pragma unroll
                for (int nt = 0; nt < 4; nt++)
                    mma_tf32(acc[mt][nt], afr[mt], bfr[nt]);
        }

        if (has_next) {
#pragma unroll
            for (int i = 0; i < 4; i++) {
                sA[buf ^ 1][aRow0 * SA_STRIDE + aK0 + i] = to_tf32(ar[0][i]);
                sA[buf ^ 1][aRow1 * SA_STRIDE + aK1 + i] = to_tf32(ar[1][i]);
                sB[buf ^ 1][bK0 * SB_STRIDE + bN0 + i] = to_tf32(br[0][i]);
                sB[buf ^ 1][bK1 * SB_STRIDE + bN1 + i] = to_tf32(br[1][i]);
            }
        }
        __syncthreads();
        buf ^= 1;
    }

    // ---- C write ----
#pragma unroll
    for (int mt = 0; mt < 4; mt++) {
#pragma unroll
        for (int nt = 0; nt < 4; nt++) {
            int col = bn + wc * 32 + nt * 8 + lc4 * 2;
#pragma unroll
            for (int half = 0; half < 2; half++) {
                int row = bm + wr * 64 + mt * 16 + lr4 + half * 8;
                float2 v = make_float2(acc[mt][nt][half * 2],
                                       acc[mt][nt][half * 2 + 1]);
                if (flags & 4) {
                    float2 c = *(const float2*)&C[(size_t)row * N + col];
                    v.x += c.x; v.y += c.y;
                }
                if (flags & 1) { v.x += bias[col]; v.y += bias[col + 1]; }
                if (flags & 2) { v.x = fmaxf(v.x, 0.f); v.y = fmaxf(v.y, 0.f); }
                *(float2*)&C[(size_t)row * N + col] = v;
            }
        }
    }

    // ---- fused score epilogue ----
    if (smode) {
        float a1c[4][2], a2c[4][2];
#pragma unroll
        for (int nt = 0; nt < 4; nt++) {
            int col = bn + wc * 32 + nt * 8 + lc4 * 2;
            a1c[nt][0] = av1[col]; a1c[nt][1] = av1[col + 1];
            a2c[nt][0] = av2[col]; a2c[nt][1] = av2[col + 1];
        }
        // all mainloop smem reads done (post final sync); reuse sA as scratch
        float* sc1 = (float*)sA;            // 512 floats
        float* sc2 = sc1 + 512;             // 512 floats
#pragma unroll
        for (int mt = 0; mt < 4; mt++) {
#pragma unroll
            for (int half = 0; half < 2; half++) {
                float p1 = 0.f, p2 = 0.f;
#pragma unroll
                for (int nt = 0; nt < 4; nt++) {
                    p1 += acc[mt][nt][half*2] * a1c[nt][0] + acc[mt][nt][half*2+1] * a1c[nt][1];
                    p2 += acc[mt][nt][half*2] * a2c[nt][0] + acc[mt][nt][half*2+1] * a2c[nt][1];
                }
                p1 += __shfl_xor_sync(0xffffffffu, p1, 1);
                p1 += __shfl_xor_sync(0xffffffffu, p1, 2);
                p2 += __shfl_xor_sync(0xffffffffu, p2, 1);
                p2 += __shfl_xor_sync(0xffffffffu, p2, 2);
                if (lc4 == 0) {
                    int lrl = mt * 16 + lr4 + half * 8;     // 0..63
                    sc1[(wr * 4 + wc) * 64 + lrl] = p1;
                    sc2[(wr * 4 + wc) * 64 + lrl] = p2;
                }
            }
        }
        __syncthreads();
        if (smode == 1) {
            // N-tile = 2 complete heads -> final dots
            int hl = tid >> 7, lr = tid & 127;
            int wr2 = lr >> 6, ri = lr & 63;
            float v1 = sc1[(wr2*4 + 2*hl)*64 + ri] + sc1[(wr2*4 + 2*hl + 1)*64 + ri];
            float v2 = sc2[(wr2*4 + 2*hl)*64 + ri] + sc2[(wr2*4 + 2*hl + 1)*64 + ri];
            int rg = bm + lr;
            int bb = rg >> 7, nn2 = rg & 127;
            int hg = blockIdx.x * 2 + hl;
            so1[((size_t)bb * NHEADS + hg) * Nn + nn2] = v1;
            so2[((size_t)bb * NHEADS + hg) * Nn + nn2] = v2;
        } else {
            // per-CTA partial over this tile's 128 cols
            if (tid < 128) {
                int wr2 = tid >> 6, ri = tid & 63;
                float v1 = 0.f, v2 = 0.f;
#pragma unroll
                for (int w = 0; w < 4; w++) {
                    v1 += sc1[(wr2*4 + w)*64 + ri];
                    v2 += sc2[(wr2*4 + w)*64 + ri];
                }
                so1[(size_t)blockIdx.x * M + bm + tid] = v1;
                so2[(size_t)blockIdx.x * M + bm + tid] = v2;
            }
        }
    }
}

// ---------------------------------------------------------------------------
// t_combine: g_t1/g_t2 = sum of 4 N-tile partials
// ---------------------------------------------------------------------------
__global__ void t_combine_kernel()
{
    int r = blockIdx.x * blockDim.x + threadIdx.x;
    if (r >= Bq * Nn) return;
    const int M = Bq * Nn;
    g_t1[r] = g_t1p[r] + g_t1p[M + r] + g_t1p[2*M + r] + g_t1p[3*M + r];
    g_t2[r] = g_t2p[r] + g_t2p[M + r] + g_t2p[2*M + r] + g_t2p[3*M + r];
}

// ---------------------------------------------------------------------------
// av2: batched tf32 GEMM D[b] = att2[b] @ Wx[b][:, bn..+127], fused
// ELU + column-mean -> g_gat. Validated R13.
// ---------------------------------------------------------------------------
__global__ __launch_bounds__(256) void av2_kernel()
{
    __shared__ u32 sA[2][128 * SA_STRIDE];
    __shared__ u32 sB[2][16 * SB_STRIDE];

    int tid = threadIdx.x;
    int warp = tid >> 5, lane = tid & 31;
    int wr = warp >> 2, wc = warp & 3;
    int b = blockIdx.y;
    int bn = blockIdx.x * 128;
    int lr4 = lane >> 2, lc4 = lane & 3;

    const u32*   Ab = g_att2 + (size_t)b * Nn * Nn;
    const float* Bb = g_Wx + (size_t)b * Nn * HID;

    float acc[4][4][4];
#pragma unroll
    for (int mt = 0; mt < 4; mt++)
#pragma unroll
        for (int nt = 0; nt < 4; nt++)
#pragma unroll
            for (int i = 0; i < 4; i++) acc[mt][nt][i] = 0.f;

    int aRow0 = tid >> 2,         aK0 = (tid & 3) * 4;
    int aRow1 = (tid + 256) >> 2, aK1 = ((tid + 256) & 3) * 4;
    int bK0 = tid >> 5,           bN0 = (tid & 31) * 4;
    int bK1 = (tid + 256) >> 5,   bN1 = ((tid + 256) & 31) * 4;

    {
        *(uint4*)&sA[0][aRow0 * SA_STRIDE + aK0] = *(const uint4*)(Ab + (size_t)aRow0 * Nn + aK0);
        *(uint4*)&sA[0][aRow1 * SA_STRIDE + aK1] = *(const uint4*)(Ab + (size_t)aRow1 * Nn + aK1);
        float4 v0 = *(const float4*)(Bb + (size_t)bK0 * HID + bn + bN0);
        float4 v1 = *(const float4*)(Bb + (size_t)bK1 * HID + bn + bN1);
        sB[0][bK0 * SB_STRIDE + bN0 + 0] = to_tf32(v0.x);
        sB[0][bK0 * SB_STRIDE + bN0 + 1] = to_tf32(v0.y);
        sB[0][bK0 * SB_STRIDE + bN0 + 2] = to_tf32(v0.z);
        sB[0][bK0 * SB_STRIDE + bN0 + 3] = to_tf32(v0.w);
        sB[0][bK1 * SB_STRIDE + bN1 + 0] = to_tf32(v1.x);
        sB[0][bK1 * SB_STRIDE + bN1 + 1] = to_tf32(v1.y);
        sB[0][bK1 * SB_STRIDE + bN1 + 2] = to_tf32(v1.z);
        sB[0][bK1 * SB_STRIDE + bN1 + 3] = to_tf32(v1.w);
    }
    __syncthreads();

    int buf = 0;
    for (int t = 0; t < 8; t++) {
        bool has_next = (t + 1 < 8);
        uint4 an0, an1;
        float4 v0, v1;
        if (has_next) {
            int k0 = (t + 1) * 16;
            an0 = *(const uint4*)(Ab + (size_t)aRow0 * Nn + k0 + aK0);
            an1 = *(const uint4*)(Ab + (size_t)aRow1 * Nn + k0 + aK1);
            v0 = *(const float4*)(Bb + (size_t)(k0 + bK0) * HID + bn + bN0);
            v1 = *(const float4*)(Bb + (size_t)(k0 + bK1) * HID + bn + bN1);
        }

        const u32* cA = sA[buf];
        const u32* cB = sB[buf];
#pragma unroll
        for (int kk = 0; kk < 16; kk += 8) {
            u32 afr[4][4], bfr[4][2];
#pragma unroll
            for (int mt = 0; mt < 4; mt++) {
                int r0 = wr * 64 + mt * 16 + lr4;
                int c0 = kk + lc4;
                afr[mt][0] = cA[r0 * SA_STRIDE + c0];
                afr[mt][1] = cA[(r0 + 8) * SA_STRIDE + c0];
                afr[mt][2] = cA[r0 * SA_STRIDE + c0 + 4];
                afr[mt][3] = cA[(r0 + 8) * SA_STRIDE + c0 + 4];
            }
#pragma unroll
            for (int nt = 0; nt < 4; nt++) {
                int col = wc * 32 + nt * 8 + lr4;
                bfr[nt][0] = cB[(kk + lc4) * SB_STRIDE + col];
                bfr[nt][1] = cB[(kk + lc4 + 4) * SB_STRIDE + col];
            }
#pragma unroll
            for (int mt = 0; mt < 4; mt++)
#pragma unroll
                for (int nt = 0; nt < 4; nt++)
                    mma_tf32(acc[mt][nt], afr[mt], bfr[nt]);
        }

        if (has_next) {
            *(uint4*)&sA[buf ^ 1][aRow0 * SA_STRIDE + aK0] = an0;
            *(uint4*)&sA[buf ^ 1][aRow1 * SA_STRIDE + aK1] = an1;
            sB[buf ^ 1][bK0 * SB_STRIDE + bN0 + 0] = to_tf32(v0.x);
            sB[buf ^ 1][bK0 * SB_STRIDE + bN0 + 1] = to_tf32(v0.y);
            sB[buf ^ 1][bK0 * SB_STRIDE + bN0 + 2] = to_tf32(v0.z);
            sB[buf ^ 1][bK0 * SB_STRIDE + bN0 + 3] = to_tf32(v0.w);
            sB[buf ^ 1][bK1 * SB_STRIDE + bN1 + 0] = to_tf32(v1.x);
            sB[buf ^ 1][bK1 * SB_STRIDE + bN1 + 1] = to_tf32(v1.y);
            sB[buf ^ 1][bK1 * SB_STRIDE + bN1 + 2] = to_tf32(v1.z);
            sB[buf ^ 1][bK1 * SB_STRIDE + bN1 + 3] = to_tf32(v1.w);
        }
        __syncthreads();
        buf ^= 1;
    }

    float cs[4][2];
#pragma unroll
    for (int nt = 0; nt < 4; nt++) {
        cs[nt][0] = 0.f; cs[nt][1] = 0.f;
#pragma unroll
        for (int mt = 0; mt < 4; mt++) {
            cs[nt][0] += elu1(acc[mt][nt][0]) + elu1(acc[mt][nt][2]);
            cs[nt][1] += elu1(acc[mt][nt][1]) + elu1(acc[mt][nt][3]);
        }
    }
#pragma unroll
    for (int o = 4; o <= 16; o <<= 1) {
#pragma unroll
        for (int nt = 0; nt < 4; nt++) {
            cs[nt][0] += __shfl_xor_sync(0xffffffffu, cs[nt][0], o);
            cs[nt][1] += __shfl_xor_sync(0xffffffffu, cs[nt][1], o);
        }
    }
    float* scratch = (float*)sA;
    if (lr4 == 0) {
#pragma unroll
        for (int nt = 0; nt < 4; nt++) {
            int col = wc * 32 + nt * 8 + lc4 * 2;
            scratch[wr * 128 + col]     = cs[nt][0];
            scratch[wr * 128 + col + 1] = cs[nt][1];
        }
    }
    __syncthreads();
    if (tid < 128)
        g_gat[(size_t)b * HID + bn + tid] =
            (scratch[tid] + scratch[128 + tid]) * (1.f / 128.f);
}

// ---------------------------------------------------------------------------
// softmax2 (no-max): writes att rows tf32 to g_att2.
// ---------------------------------------------------------------------------
__global__ __launch_bounds__(256) void softmax2_kernel(
    const float* __restrict__ ae_out, const int* __restrict__ adj,
    const float* __restrict__ edge)
{
    __shared__ float st1[64];
    __shared__ float st2[128];

    int tid = threadIdx.x;
    int blk = blockIdx.x;
    int hb = blk & 1;
    int b = blk >> 1;
    int i0 = hb * 64;
    float ae = ae_out[0];

    if (tid < 64)  st1[tid] = g_t1[b * Nn + i0 + tid];
    else if (tid < 192) st2[tid - 64] = g_t2[b * Nn + tid - 64];
    __syncthreads();

    int warp = tid >> 5, lane = tid & 31;
    for (int i = warp; i < 64; i += 8) {
        int row = i0 + i;
        float4 ef = ((const float4*)(edge + ((size_t)b * Nn + row) * Nn))[lane];
        int4  av  = ((const int4*)(adj  + ((size_t)b * Nn + row) * Nn))[lane];
        float si = st1[i];
        int j0 = lane * 4;
        float v0 = si + st2[j0 + 0] + ef.x * ae; v0 = v0 >= 0.f ? v0 : 0.2f * v0; v0 = av.x > 0 ? v0 : -9e15f;
        float v1 = si + st2[j0 + 1] + ef.y * ae; v1 = v1 >= 0.f ? v1 : 0.2f * v1; v1 = av.y > 0 ? v1 : -9e15f;
        float v2 = si + st2[j0 + 2] + ef.z * ae; v2 = v2 >= 0.f ? v2 : 0.2f * v2; v2 = av.z > 0 ? v2 : -9e15f;
        float v3 = si + st2[j0 + 3] + ef.w * ae; v3 = v3 >= 0.f ? v3 : 0.2f * v3; v3 = av.w > 0 ? v3 : -9e15f;
        // no-max softmax: scores O(+-15); masked exp underflows to 0
        float e0 = __expf(v0), e1 = __expf(v1), e2 = __expf(v2), e3 = __expf(v3);
        float s = e0 + e1 + e2 + e3;
#pragma unroll
        for (int o = 16; o; o >>= 1) s += __shfl_xor_sync(0xffffffffu, s, o);
        float inv = 1.f / s;
        uint4 o4;
        o4.x = to_tf32(e0 * inv); o4.y = to_tf32(e1 * inv);
        o4.z = to_tf32(e2 * inv); o4.w = to_tf32(e3 * inv);
        *(uint4*)(g_att2 + ((size_t)b * Nn + row) * Nn + j0) = o4;
    }
}

// ---------------------------------------------------------------------------
// Tail fp32 GEMM (exact). Validated R10.
// ---------------------------------------------------------------------------
__global__ __launch_bounds__(256) void tail_gemm_kernel(
    const float* __restrict__ A, const float* __restrict__ B,
    const float* __restrict__ bias, float* __restrict__ C,
    int M, int N, int K, int flags)
{
    __shared__ float As[2][16][64];
    __shared__ float Bs[2][16][64];

    int tid = threadIdx.x;
    int bm = blockIdx.y * 64;
    int bn = blockIdx.x * 64;
    int tx = tid & 15;
    int ty = tid >> 4;

    int aRow = tid >> 2, aK = (tid & 3) * 4;
    int bK = tid >> 4, bN = (tid & 15) * 4;

    u64 acc[4][2];
#pragma unroll
    for (int i = 0; i < 4; i++) { acc[i][0] = 0ull; acc[i][1] = 0ull; }

    const int Ktiles = (K + 15) / 16;
    const float* Arow = A + (size_t)(bm + aRow) * K;

    {
#pragma unroll
        for (int i = 0; i < 4; i++) {
            int k = aK + i;
            As[0][aK + i][aRow] = (k < K) ? Arow[k] : 0.f;
        }
        float4 v = make_float4(0.f, 0.f, 0.f, 0.f);
        if (bK < K) v = *(const float4*)(B + (size_t)bK * N + bn + bN);
        *(float4*)&Bs[0][bK][bN] = v;
    }
    __syncthreads();

    int buf = 0;
    for (int t = 0; t < Ktiles; t++) {
        float ap[4];
        float4 bp = make_float4(0.f, 0.f, 0.f, 0.f);
        bool has_next = (t + 1 < Ktiles);
        if (has_next) {
            int k0 = (t + 1) * 16;
#pragma unroll
            for (int i = 0; i < 4; i++) {
                int k = k0 + aK + i;
                ap[i] = (k < K) ? Arow[k] : 0.f;
            }
            int k = k0 + bK;
            if (k < K) bp = *(const float4*)(B + (size_t)k * N + bn + bN);
        }

#pragma unroll
        for (int kk = 0; kk < 16; kk++) {
            u64 b0 = *(const u64*)&Bs[buf][kk][tx * 4];
            u64 b1 = *(const u64*)&Bs[buf][kk][tx * 4 + 2];
            float a0 = As[buf][kk][ty * 4];
            float a1 = As[buf][kk][ty * 4 + 1];
            float a2 = As[buf][kk][ty * 4 + 2];
            float a3 = As[buf][kk][ty * 4 + 3];
            u64 d0 = dup2(a0), d1 = dup2(a1), d2 = dup2(a2), d3 = dup2(a3);
            fma2(acc[0][0], d0, b0); fma2(acc[0][1], d0, b1);
            fma2(acc[1][0], d1, b0); fma2(acc[1][1], d1, b1);
            fma2(acc[2][0], d2, b0); fma2(acc[2][1], d2, b1);
            fma2(acc[3][0], d3, b0); fma2(acc[3][1], d3, b1);
        }

        if (has_next) {
#pragma unroll
            for (int i = 0; i < 4; i++) As[buf ^ 1][aK + i][aRow] = ap[i];
            *(float4*)&Bs[buf ^ 1][bK][bN] = bp;
        }
        __syncthreads();
        buf ^= 1;
    }

#pragma unroll
    for (int i = 0; i < 4; i++) {
        int row = bm + ty * 4 + i;
#pragma unroll
        for (int j = 0; j < 2; j++) {
            int col = bn + tx * 4 + j * 2;
            float2 v = upk2(acc[i][j]);
            if (flags & 4) {
                float2 c = *(const float2*)&C[(size_t)row * N + col];
                v.x += c.x; v.y += c.y;
            }
            if (flags & 1) { v.x += bias[col]; v.y += bias[col + 1]; }
            if (flags & 2) { v.x = fmaxf(v.x, 0.f); v.y = fmaxf(v.y, 0.f); }
            *(float2*)&C[(size_t)row * N + col] = v;
        }
    }
}

// ---------------------------------------------------------------------------
__global__ void wcat_kernel(const float* __restrict__ W_heads)
{
    int idx = blockIdx.x * blockDim.x + threadIdx.x;
    if (idx >= NHEADS * F_IN * NHID) return;
    int h = idx / (F_IN * NHID);
    int rem = idx - h * (F_IN * NHID);
    int f = rem / NHID;
    int d = rem - f * NHID;
    g_Wcat[f * HID + h * NHID + d] = W_heads[idx];
}

// ---------------------------------------------------------------------------
// attn1 (tf32 mma, 32-col B-chunks, no-max softmax, chunk-0 prefetch).
// ---------------------------------------------------------------------------
#define WCH_STR 40
#define AT_STR 132

__global__ __launch_bounds__(256) void attn1_kernel(
    const float* __restrict__ ae_heads, const int* __restrict__ adj,
    const float* __restrict__ edge)
{
    extern __shared__ u32 smu[];
    u32* sWh  = smu;                        // 128*40
    u32* sAtt = smu + 128 * WCH_STR;        // 64*132
    float* ss1 = (float*)(smu + 128 * WCH_STR + 64 * AT_STR);  // 64
    float* ss2 = ss1 + 64;                                      // 128

    int tid = threadIdx.x;
    int blk = blockIdx.x;
    int hb = blk & 1;
    int bh = blk >> 1;
    int hh = bh & 7, b = bh >> 3;
    int i0 = hb * 64;
    float ae = ae_heads[hh];

    const float* whp = g_Wh + (size_t)b * Nn * HID + hh * NHID;

    // prefetch Wh chunk 0 (independent of softmax) + score vectors
    for (int i = tid; i < 128 * 8; i += 256) {
        int r = i >> 3, c = (i & 7) * 4;
        float4 v = *(const float4*)(whp + (size_t)r * HID + c);
        uint4 t;
        t.x = to_tf32(v.x); t.y = to_tf32(v.y);
        t.z = to_tf32(v.z); t.w = to_tf32(v.w);
        *(uint4*)&sWh[r * WCH_STR + c] = t;
    }
    if (tid < 64)  ss1[tid] = g_s1[bh * Nn + i0 + tid];
    if (tid < 128) ss2[tid] = g_s2[bh * Nn + tid];
    __syncthreads();

    int warp = tid >> 5, lane = tid & 31;
    for (int i = warp; i < 64; i += 8) {
        int row = i0 + i;
        float4 ef = ((const float4*)(edge + ((size_t)b * Nn + row) * Nn))[lane];
        int4  av  = ((const int4*)(adj  + ((size_t)b * Nn + row) * Nn))[lane];
        float si = ss1[i];
        int j0 = lane * 4;
        float v0 = si + ss2[j0 + 0] + ef.x * ae; v0 = v0 >= 0.f ? v0 : 0.2f * v0; v0 = av.x > 0 ? v0 : -9e15f;
        float v1 = si + ss2[j0 + 1] + ef.y * ae; v1 = v1 >= 0.f ? v1 : 0.2f * v1; v1 = av.y > 0 ? v1 : -9e15f;
        float v2 = si + ss2[j0 + 2] + ef.z * ae; v2 = v2 >= 0.f ? v2 : 0.2f * v2; v2 = av.z > 0 ? v2 : -9e15f;
        float v3 = si + ss2[j0 + 3] + ef.w * ae; v3 = v3 >= 0.f ? v3 : 0.2f * v3; v3 = av.w > 0 ? v3 : -9e15f;
        // no-max softmax
        float e0 = __expf(v0), e1 = __expf(v1), e2 = __expf(v2), e3 = __expf(v3);
        float s = e0 + e1 + e2 + e3;
#pragma unroll
        for (int o = 16; o; o >>= 1) s += __shfl_xor_sync(0xffffffffu, s, o);
        float inv = 1.f / s;
        uint4 o4;
        o4.x = to_tf32(e0 * inv); o4.y = to_tf32(e1 * inv);
        o4.z = to_tf32(e2 * inv); o4.w = to_tf32(e3 * inv);
        *(uint4*)&sAtt[i * AT_STR + lane * 4] = o4;
    }
    __syncthreads();   // sAtt ready (sWh chunk 0 already covered above)

    int wr = warp >> 2, wc = warp & 3;
    int lr4 = lane >> 2, lc4 = lane & 3;

#pragma unroll
    for (int ch = 0; ch < 2; ch++) {
        if (ch == 1) {
            __syncthreads();   // done reading chunk-0 sWh
            for (int i = tid; i < 128 * 8; i += 256) {
                int r = i >> 3, c = (i & 7) * 4;
                float4 v = *(const float4*)(whp + (size_t)r * HID + 32 + c);
                uint4 t;
                t.x = to_tf32(v.x); t.y = to_tf32(v.y);
                t.z = to_tf32(v.z); t.w = to_tf32(v.w);
                *(uint4*)&sWh[r * WCH_STR + c] = t;
            }
            __syncthreads();
        }

        float acc[2][4];
#pragma unroll
        for (int mt = 0; mt < 2; mt++)
#pragma unroll
            for (int i = 0; i < 4; i++) acc[mt][i] = 0.f;

#pragma unroll
        for (int kk = 0; kk < 128; kk += 8) {
            u32 afr[2][4], bfr[2];
#pragma unroll
            for (int mt = 0; mt < 2; mt++) {
                int r0 = wr * 32 + mt * 16 + lr4;
                int c0 = kk + lc4;
                afr[mt][0] = sAtt[r0 * AT_STR + c0];
                afr[mt][1] = sAtt[(r0 + 8) * AT_STR + c0];
                afr[mt][2] = sAtt[r0 * AT_STR + c0 + 4];
                afr[mt][3] = sAtt[(r0 + 8) * AT_STR + c0 + 4];
            }
            {
                int col = wc * 8 + lr4;
                bfr[0] = sWh[(kk + lc4) * WCH_STR + col];
                bfr[1] = sWh[(kk + lc4 + 4) * WCH_STR + col];
            }
#pragma unroll
            for (int mt = 0; mt < 2; mt++)
                mma_tf32(acc[mt], afr[mt], bfr);
        }

#pragma unroll
        for (int mt = 0; mt < 2; mt++) {
            int col = ch * 32 + wc * 8 + lc4 * 2;
#pragma unroll
            for (int half = 0; half < 2; half++) {
                int i = i0 + wr * 32 + mt * 16 + lr4 + half * 8;
                float2 v;
                v.x = elu1(acc[mt][half * 2]);
                v.y = elu1(acc[mt][half * 2 + 1]);
                *(float2*)(g_x + ((size_t)b * Nn + i) * HID + hh * NHID + col) = v;
            }
        }
    }
}

// ---------------------------------------------------------------------------
__global__ void final_kernel(const float* __restrict__ X,
                             const float* __restrict__ W,
                             const float* __restrict__ bias,
                             float* __restrict__ out)
{
    int idx = blockIdx.x * blockDim.x + threadIdx.x;
    if (idx >= Bq * TASKS) return;
    int b = idx / TASKS, t = idx - b * TASKS;
    const float* x = X + (size_t)b * HID;
    float s = bias[t];
    for (int d = 0; d < HID; d++) s += x[d] * W[d * TASKS + t];
    out[idx] = s;
}

// ---------------------------------------------------------------------------
extern "C" void kernel_launch(void* const* d_in, const int* in_sizes, int n_in,
                              void* d_out, int out_size)
{
    const float* h        = (const float*)d_in[0];
    const int*   adj      = (const int*)d_in[1];
    const float* edge     = (const float*)d_in[2];
    const float* fp       = (const float*)d_in[3];
    const float* W_heads  = (const float*)d_in[4];
    const float* a1_heads = (const float*)d_in[5];
    const float* a2_heads = (const float*)d_in[6];
    const float* ae_heads = (const float*)d_in[7];
    const float* W_out    = (const float*)d_in[8];
    const float* a1_out   = (const float*)d_in[9];
    const float* a2_out   = (const float*)d_in[10];
    const float* ae_out   = (const float*)d_in[11];
    const float* fc1_w    = (const float*)d_in[12];
    const float* fc1_b    = (const float*)d_in[13];
    const float* fc2_w    = (const float*)d_in[14];
    const float* fc2_b    = (const float*)d_in[15];
    const float* q_w      = (const float*)d_in[16];
    const float* q_b      = (const float*)d_in[17];
    // k_w (18), k_b (19) unused: softmax over size-1 axis == 1 -> fused = q+v
    const float* v_w      = (const float*)d_in[20];
    const float* v_b      = (const float*)d_in[21];
    const float* o_w      = (const float*)d_in[22];
    const float* o_b      = (const float*)d_in[23];
    const float* ffn1_w   = (const float*)d_in[24];
    const float* ffn1_b   = (const float*)d_in[25];
    const float* ffn2_w   = (const float*)d_in[26];
    const float* ffn2_b   = (const float*)d_in[27];
    float* out = (float*)d_out;

    float *Wh, *x, *gat, *fpnh, *fpn, *buf1, *buf2, *Wx, *Wcat;
    float *s1p, *s2p, *t1p, *t2p;
    cudaGetSymbolAddress((void**)&Wh, g_Wh);
    cudaGetSymbolAddress((void**)&x, g_x);
    cudaGetSymbolAddress((void**)&Wx, g_Wx);
    cudaGetSymbolAddress((void**)&gat, g_gat);
    cudaGetSymbolAddress((void**)&fpnh, g_fpnh);
    cudaGetSymbolAddress((void**)&fpn, g_fpn);
    cudaGetSymbolAddress((void**)&buf1, g_buf1);
    cudaGetSymbolAddress((void**)&buf2, g_buf2);
    cudaGetSymbolAddress((void**)&Wcat, g_Wcat);
    cudaGetSymbolAddress((void**)&s1p, g_s1);
    cudaGetSymbolAddress((void**)&s2p, g_s2);
    cudaGetSymbolAddress((void**)&t1p, g_t1p);
    cudaGetSymbolAddress((void**)&t2p, g_t2p);

    const int ATT1_SMEM = (128 * WCH_STR + 64 * AT_STR + 192) * 4;   // 55040
    cudaFuncSetAttribute(attn1_kernel, cudaFuncAttributeMaxDynamicSharedMemorySize, ATT1_SMEM);

    const int M1 = Bq * Nn;  // 65536

    // 1. Wcat transpose
    wcat_kernel<<<(NHEADS * F_IN * NHID + 255) / 256, 256>>>(W_heads);

    // 2. Wh = h @ Wcat  (tf32) + fused s1/s2 epilogue
    {
        dim3 grid(HID / 128, M1 / 128);
        sgemm_tc_kernel<<<grid, 256>>>(h, Wcat, nullptr, Wh, M1, HID, F_IN, 0,
                                       1, a1_heads, a2_heads, s1p, s2p);
    }

    // 3. attn1 (tf32 mma, 32-col chunks, prefetch, no-max softmax)
    attn1_kernel<<<Bq * NHEADS * 2, 256, ATT1_SMEM>>>(ae_heads, adj, edge);

    // 4. Wx = x @ W_out (tf32) + fused t1/t2 partial epilogue, then combine
    {
        dim3 grid(HID / 128, M1 / 128);
        sgemm_tc_kernel<<<grid, 256>>>(x, W_out, nullptr, Wx, M1, HID, HID, 0,
                                       2, a1_out, a2_out, t1p, t2p);
    }
    t_combine_kernel<<<(Bq * Nn + 255) / 256, 256>>>();

    // 5. attn2 split: softmax -> gmem att (tf32), batched AV GEMM -> gat
    softmax2_kernel<<<Bq * 2, 256>>>(ae_out, adj, edge);
    {
        dim3 grid(HID / 128, Bq);
        av2_kernel<<<grid, 256>>>();
    }

    // 6. FPN (exact fp32 tails)
    {
        dim3 grid(HID / 64, Bq / 64);
        tail_gemm_kernel<<<grid, 256>>>(fp, fc1_w, fc1_b, fpnh, Bq, HID, FP_DIM, 1 | 2);
        tail_gemm_kernel<<<grid, 256>>>(fpnh, fc2_w, fc2_b, fpn, Bq, HID, HID, 1);
    }

    // 7. fusion + FFN (exact fp32 tails)
    {
        dim3 grid(HID / 64, Bq / 64);
        tail_gemm_kernel<<<grid, 256>>>(gat, q_w, q_b, buf1, Bq, HID, HID, 1);
        tail_gemm_kernel<<<grid, 256>>>(fpn, v_w, v_b, buf1, Bq, HID, HID, 1 | 4);
        tail_gemm_kernel<<<grid, 256>>>(buf1, o_w, o_b, buf2, Bq, HID, HID, 1 | 2);
        tail_gemm_kernel<<<grid, 256>>>(buf2, ffn1_w, ffn1_b, buf1, Bq, HID, HID, 1 | 2);
    }

    // 8. final projection
    final_kernel<<<(Bq * TASKS + 255) / 256, 256>>>(buf1, ffn2_w, ffn2_b, out);
}

// round 15
// speedup vs baseline: 1.2199x; 1.1047x over previous
#include <cuda_runtime.h>
#include <cuda_bf16.h>
#include <math.h>

// ---------------------------------------------------------------------------
// FPGNN forward. R15:
//  - Wh GEMM: tf32 mma + fused s1/s2 epilogue
//  - Wx GEMM: tf32 mma + fused t1/t2 partial epilogue (combined in softmax2)
//  - attn1: tf32 mma, 32-col chunks, chunk-0 prefetch, no-max softmax
//  - attn2: softmax2 (reads t-partials) -> gmem tf32 att, av2 batched GEMM
//  - tails: exact fp32 FFMA2 64x64; q+v fused into one concat-GEMM
// ---------------------------------------------------------------------------

#define Bq 512
#define Nn 128
#define F_IN 133
#define NHEADS 8
#define NHID 64
#define HID 512
#define FP_DIM 1489
#define TASKS 12

typedef unsigned long long u64;
typedef unsigned int u32;

__device__ __forceinline__ u64 pack2(float lo, float hi) {
    u64 r; asm("mov.b64 %0, {%1,%2};" : "=l"(r) : "f"(lo), "f"(hi)); return r;
}
__device__ __forceinline__ u64 dup2(float v) { return pack2(v, v); }
__device__ __forceinline__ void fma2(u64& d, u64 a, u64 b) {
    asm("fma.rn.f32x2 %0, %1, %2, %0;" : "+l"(d) : "l"(a), "l"(b));
}
__device__ __forceinline__ float2 upk2(u64 v) {
    float2 r; asm("mov.b64 {%0,%1}, %2;" : "=f"(r.x), "=f"(r.y) : "l"(v)); return r;
}
__device__ __forceinline__ u32 to_tf32(float f) {
    u32 r; asm("cvt.rna.tf32.f32 %0, %1;" : "=r"(r) : "f"(f)); return r;
}
__device__ __forceinline__ void mma_tf32(float* d, const u32* a, const u32* b) {
    asm volatile(
        "mma.sync.aligned.m16n8k8.row.col.f32.tf32.tf32.f32 "
        "{%0,%1,%2,%3}, {%4,%5,%6,%7}, {%8,%9}, {%0,%1,%2,%3};\n"
        : "+f"(d[0]), "+f"(d[1]), "+f"(d[2]), "+f"(d[3])
        : "r"(a[0]), "r"(a[1]), "r"(a[2]), "r"(a[3]), "r"(b[0]), "r"(b[1]));
}
__device__ __forceinline__ float elu1(float v) {
    return v > 0.f ? v : (__expf(v) - 1.f);
}

// ---- scratch (device globals; no allocation allowed) ----
__device__ float g_Wcat[F_IN * HID];
__device__ float g_Wh[(size_t)Bq * Nn * HID];
__device__ float g_s1[Bq * NHEADS * Nn];
__device__ float g_s2[Bq * NHEADS * Nn];
__device__ float g_x[(size_t)Bq * Nn * HID];
__device__ float g_Wx[(size_t)Bq * Nn * HID];
__device__ float g_t1p[4 * Bq * Nn];
__device__ float g_t2p[4 * Bq * Nn];
__device__ u32   g_att2[(size_t)Bq * Nn * Nn];   // tf32 att
__device__ float g_gat[Bq * HID];
__device__ float g_fpnh[Bq * HID];
__device__ float g_fpn[Bq * HID];
__device__ float g_buf1[Bq * HID];
__device__ float g_buf2[Bq * HID];

// ---------------------------------------------------------------------------
// 1x tf32 GEMM (validated R8) + optional fused score epilogue.
// flags: 1 = bias, 2 = relu, 4 = accumulate
// smode: 1 = per-64col-head dots -> g_s1/g_s2; 2 = per-CTA partials.
// ---------------------------------------------------------------------------
#define SA_STRIDE 20
#define SB_STRIDE 136

__global__ __launch_bounds__(256) void sgemm_tc_kernel(
    const float* __restrict__ A, const float* __restrict__ B,
    const float* __restrict__ bias, float* __restrict__ C,
    int M, int N, int K, int flags,
    int smode, const float* __restrict__ av1, const float* __restrict__ av2,
    float* __restrict__ so1, float* __restrict__ so2)
{
    __shared__ u32 sA[2][128 * SA_STRIDE];
    __shared__ u32 sB[2][16 * SB_STRIDE];

    int tid = threadIdx.x;
    int warp = tid >> 5, lane = tid & 31;
    int wr = warp >> 2, wc = warp & 3;
    int bm = blockIdx.y * 128;
    int bn = blockIdx.x * 128;
    int lr4 = lane >> 2, lc4 = lane & 3;

    float acc[4][4][4];
#pragma unroll
    for (int mt = 0; mt < 4; mt++)
#pragma unroll
        for (int nt = 0; nt < 4; nt++)
#pragma unroll
            for (int i = 0; i < 4; i++) acc[mt][nt][i] = 0.f;

    const int Ktiles = (K + 15) / 16;
    int aRow0 = tid >> 2,         aK0 = (tid & 3) * 4;
    int aRow1 = (tid + 256) >> 2, aK1 = ((tid + 256) & 3) * 4;
    int bK0 = tid >> 5,           bN0 = (tid & 31) * 4;
    int bK1 = (tid + 256) >> 5,   bN1 = ((tid + 256) & 31) * 4;

    float ar[2][4], br[2][4];
    {
#pragma unroll
        for (int i = 0; i < 4; i++) {
            int k = aK0 + i;
            ar[0][i] = (k < K) ? A[(size_t)(bm + aRow0) * K + k] : 0.f;
            k = aK1 + i;
            ar[1][i] = (k < K) ? A[(size_t)(bm + aRow1) * K + k] : 0.f;
        }
        if (bK0 < K) *(float4*)br[0] = *(const float4*)(B + (size_t)bK0 * N + bn + bN0);
        else { br[0][0] = br[0][1] = br[0][2] = br[0][3] = 0.f; }
        if (bK1 < K) *(float4*)br[1] = *(const float4*)(B + (size_t)bK1 * N + bn + bN1);
        else { br[1][0] = br[1][1] = br[1][2] = br[1][3] = 0.f; }
    }
#pragma unroll
    for (int i = 0; i < 4; i++) {
        sA[0][aRow0 * SA_STRIDE + aK0 + i] = to_tf32(ar[0][i]);
        sA[0][aRow1 * SA_STRIDE + aK1 + i] = to_tf32(ar[1][i]);
        sB[0][bK0 * SB_STRIDE + bN0 + i] = to_tf32(br[0][i]);
        sB[0][bK1 * SB_STRIDE + bN1 + i] = to_tf32(br[1][i]);
    }
    __syncthreads();

    int buf = 0;
    for (int t = 0; t < Ktiles; t++) {
        bool has_next = (t + 1 < Ktiles);
        if (has_next) {
            int k0 = (t + 1) * 16;
#pragma unroll
            for (int i = 0; i < 4; i++) {
                int k = k0 + aK0 + i;
                ar[0][i] = (k < K) ? A[(size_t)(bm + aRow0) * K + k] : 0.f;
                k = k0 + aK1 + i;
                ar[1][i] = (k < K) ? A[(size_t)(bm + aRow1) * K + k] : 0.f;
            }
            int k = k0 + bK0;
            if (k < K) *(float4*)br[0] = *(const float4*)(B + (size_t)k * N + bn + bN0);
            else { br[0][0] = br[0][1] = br[0][2] = br[0][3] = 0.f; }
            k = k0 + bK1;
            if (k < K) *(float4*)br[1] = *(const float4*)(B + (size_t)k * N + bn + bN1);
            else { br[1][0] = br[1][1] = br[1][2] = br[1][3] = 0.f; }
        }

        const u32* cA = sA[buf];
        const u32* cB = sB[buf];
#pragma unroll
        for (int kk = 0; kk < 16; kk += 8) {
            u32 afr[4][4], bfr[4][2];
#pragma unroll
            for (int mt = 0; mt < 4; mt++) {
                int r0 = wr * 64 + mt * 16 + lr4;
                int c0 = kk + lc4;
                afr[mt][0] = cA[r0 * SA_STRIDE + c0];
                afr[mt][1] = cA[(r0 + 8) * SA_STRIDE + c0];
                afr[mt][2] = cA[r0 * SA_STRIDE + c0 + 4];
                afr[mt][3] = cA[(r0 + 8) * SA_STRIDE + c0 + 4];
            }
#pragma unroll
            for (int nt = 0; nt < 4; nt++) {
                int col = wc * 32 + nt * 8 + lr4;
                bfr[nt][0] = cB[(kk + lc4) * SB_STRIDE + col];
                bfr[nt][1] = cB[(kk + lc4 + 4) * SB_STRIDE + col];
            }
#pragma unroll
            for (int mt = 0; mt < 4; mt++)
#pragma unroll
                for (int nt = 0; nt < 4; nt++)
                    mma_tf32(acc[mt][nt], afr[mt], bfr[nt]);
        }

        if (has_next) {
#pragma unroll
            for (int i = 0; i < 4; i++) {
                sA[buf ^ 1][aRow0 * SA_STRIDE + aK0 + i] = to_tf32(ar[0][i]);
                sA[buf ^ 1][aRow1 * SA_STRIDE + aK1 + i] = to_tf32(ar[1][i]);
                sB[buf ^ 1][bK0 * SB_STRIDE + bN0 + i] = to_tf32(br[0][i]);
                sB[buf ^ 1][bK1 * SB_STRIDE + bN1 + i] = to_tf32(br[1][i]);
            }
        }
        __syncthreads();
        buf ^= 1;
    }

    // ---- C write ----
#pragma unroll
    for (int mt = 0; mt < 4; mt++) {
#pragma unroll
        for (int nt = 0; nt < 4; nt++) {
            int col = bn + wc * 32 + nt * 8 + lc4 * 2;
#pragma unroll
            for (int half = 0; half < 2; half++) {
                int row = bm + wr * 64 + mt * 16 + lr4 + half * 8;
                float2 v = make_float2(acc[mt][nt][half * 2],
                                       acc[mt][nt][half * 2 + 1]);
                if (flags & 4) {
                    float2 c = *(const float2*)&C[(size_t)row * N + col];
                    v.x += c.x; v.y += c.y;
                }
                if (flags & 1) { v.x += bias[col]; v.y += bias[col + 1]; }
                if (flags & 2) { v.x = fmaxf(v.x, 0.f); v.y = fmaxf(v.y, 0.f); }
                *(float2*)&C[(size_t)row * N + col] = v;
            }
        }
    }

    // ---- fused score epilogue ----
    if (smode) {
        float a1c[4][2], a2c[4][2];
#pragma unroll
        for (int nt = 0; nt < 4; nt++) {
            int col = bn + wc * 32 + nt * 8 + lc4 * 2;
            a1c[nt][0] = av1[col]; a1c[nt][1] = av1[col + 1];
            a2c[nt][0] = av2[col]; a2c[nt][1] = av2[col + 1];
        }
        float* sc1 = (float*)sA;            // 512 floats
        float* sc2 = sc1 + 512;             // 512 floats
#pragma unroll
        for (int mt = 0; mt < 4; mt++) {
#pragma unroll
            for (int half = 0; half < 2; half++) {
                float p1 = 0.f, p2 = 0.f;
#pragma unroll
                for (int nt = 0; nt < 4; nt++) {
                    p1 += acc[mt][nt][half*2] * a1c[nt][0] + acc[mt][nt][half*2+1] * a1c[nt][1];
                    p2 += acc[mt][nt][half*2] * a2c[nt][0] + acc[mt][nt][half*2+1] * a2c[nt][1];
                }
                p1 += __shfl_xor_sync(0xffffffffu, p1, 1);
                p1 += __shfl_xor_sync(0xffffffffu, p1, 2);
                p2 += __shfl_xor_sync(0xffffffffu, p2, 1);
                p2 += __shfl_xor_sync(0xffffffffu, p2, 2);
                if (lc4 == 0) {
                    int lrl = mt * 16 + lr4 + half * 8;
                    sc1[(wr * 4 + wc) * 64 + lrl] = p1;
                    sc2[(wr * 4 + wc) * 64 + lrl] = p2;
                }
            }
        }
        __syncthreads();
        if (smode == 1) {
            int hl = tid >> 7, lr = tid & 127;
            int wr2 = lr >> 6, ri = lr & 63;
            float v1 = sc1[(wr2*4 + 2*hl)*64 + ri] + sc1[(wr2*4 + 2*hl + 1)*64 + ri];
            float v2 = sc2[(wr2*4 + 2*hl)*64 + ri] + sc2[(wr2*4 + 2*hl + 1)*64 + ri];
            int rg = bm + lr;
            int bb = rg >> 7, nn2 = rg & 127;
            int hg = blockIdx.x * 2 + hl;
            so1[((size_t)bb * NHEADS + hg) * Nn + nn2] = v1;
            so2[((size_t)bb * NHEADS + hg) * Nn + nn2] = v2;
        } else {
            if (tid < 128) {
                int wr2 = tid >> 6, ri = tid & 63;
                float v1 = 0.f, v2 = 0.f;
#pragma unroll
                for (int w = 0; w < 4; w++) {
                    v1 += sc1[(wr2*4 + w)*64 + ri];
                    v2 += sc2[(wr2*4 + w)*64 + ri];
                }
                so1[(size_t)blockIdx.x * M + bm + tid] = v1;
                so2[(size_t)blockIdx.x * M + bm + tid] = v2;
            }
        }
    }
}

// ---------------------------------------------------------------------------
// av2: batched tf32 GEMM D[b] = att2[b] @ Wx[b][:, bn..+127], fused
// ELU + column-mean -> g_gat. Validated R13.
// ---------------------------------------------------------------------------
__global__ __launch_bounds__(256) void av2_kernel()
{
    __shared__ u32 sA[2][128 * SA_STRIDE];
    __shared__ u32 sB[2][16 * SB_STRIDE];

    int tid = threadIdx.x;
    int warp = tid >> 5, lane = tid & 31;
    int wr = warp >> 2, wc = warp & 3;
    int b = blockIdx.y;
    int bn = blockIdx.x * 128;
    int lr4 = lane >> 2, lc4 = lane & 3;

    const u32*   Ab = g_att2 + (size_t)b * Nn * Nn;
    const float* Bb = g_Wx + (size_t)b * Nn * HID;

    float acc[4][4][4];
#pragma unroll
    for (int mt = 0; mt < 4; mt++)
#pragma unroll
        for (int nt = 0; nt < 4; nt++)
#pragma unroll
            for (int i = 0; i < 4; i++) acc[mt][nt][i] = 0.f;

    int aRow0 = tid >> 2,         aK0 = (tid & 3) * 4;
    int aRow1 = (tid + 256) >> 2, aK1 = ((tid + 256) & 3) * 4;
    int bK0 = tid >> 5,           bN0 = (tid & 31) * 4;
    int bK1 = (tid + 256) >> 5,   bN1 = ((tid + 256) & 31) * 4;

    {
        *(uint4*)&sA[0][aRow0 * SA_STRIDE + aK0] = *(const uint4*)(Ab + (size_t)aRow0 * Nn + aK0);
        *(uint4*)&sA[0][aRow1 * SA_STRIDE + aK1] = *(const uint4*)(Ab + (size_t)aRow1 * Nn + aK1);
        float4 v0 = *(const float4*)(Bb + (size_t)bK0 * HID + bn + bN0);
        float4 v1 = *(const float4*)(Bb + (size_t)bK1 * HID + bn + bN1);
        sB[0][bK0 * SB_STRIDE + bN0 + 0] = to_tf32(v0.x);
        sB[0][bK0 * SB_STRIDE + bN0 + 1] = to_tf32(v0.y);
        sB[0][bK0 * SB_STRIDE + bN0 + 2] = to_tf32(v0.z);
        sB[0][bK0 * SB_STRIDE + bN0 + 3] = to_tf32(v0.w);
        sB[0][bK1 * SB_STRIDE + bN1 + 0] = to_tf32(v1.x);
        sB[0][bK1 * SB_STRIDE + bN1 + 1] = to_tf32(v1.y);
        sB[0][bK1 * SB_STRIDE + bN1 + 2] = to_tf32(v1.z);
        sB[0][bK1 * SB_STRIDE + bN1 + 3] = to_tf32(v1.w);
    }
    __syncthreads();

    int buf = 0;
    for (int t = 0; t < 8; t++) {
        bool has_next = (t + 1 < 8);
        uint4 an0, an1;
        float4 v0, v1;
        if (has_next) {
            int k0 = (t + 1) * 16;
            an0 = *(const uint4*)(Ab + (size_t)aRow0 * Nn + k0 + aK0);
            an1 = *(const uint4*)(Ab + (size_t)aRow1 * Nn + k0 + aK1);
            v0 = *(const float4*)(Bb + (size_t)(k0 + bK0) * HID + bn + bN0);
            v1 = *(const float4*)(Bb + (size_t)(k0 + bK1) * HID + bn + bN1);
        }

        const u32* cA = sA[buf];
        const u32* cB = sB[buf];
#pragma unroll
        for (int kk = 0; kk < 16; kk += 8) {
            u32 afr[4][4], bfr[4][2];
#pragma unroll
            for (int mt = 0; mt < 4; mt++) {
                int r0 = wr * 64 + mt * 16 + lr4;
                int c0 = kk + lc4;
                afr[mt][0] = cA[r0 * SA_STRIDE + c0];
                afr[mt][1] = cA[(r0 + 8) * SA_STRIDE + c0];
                afr[mt][2] = cA[r0 * SA_STRIDE + c0 + 4];
                afr[mt][3] = cA[(r0 + 8) * SA_STRIDE + c0 + 4];
            }
#pragma unroll
            for (int nt = 0; nt < 4; nt++) {
                int col = wc * 32 + nt * 8 + lr4;
                bfr[nt][0] = cB[(kk + lc4) * SB_STRIDE + col];
                bfr[nt][1] = cB[(kk + lc4 + 4) * SB_STRIDE + col];
            }
#pragma unroll
            for (int mt = 0; mt < 4; mt++)
#pragma unroll
                for (int nt = 0; nt < 4; nt++)
                    mma_tf32(acc[mt][nt], afr[mt], bfr[nt]);
        }

        if (has_next) {
            *(uint4*)&sA[buf ^ 1][aRow0 * SA_STRIDE + aK0] = an0;
            *(uint4*)&sA[buf ^ 1][aRow1 * SA_STRIDE + aK1] = an1;
            sB[buf ^ 1][bK0 * SB_STRIDE + bN0 + 0] = to_tf32(v0.x);
            sB[buf ^ 1][bK0 * SB_STRIDE + bN0 + 1] = to_tf32(v0.y);
            sB[buf ^ 1][bK0 * SB_STRIDE + bN0 + 2] = to_tf32(v0.z);
            sB[buf ^ 1][bK0 * SB_STRIDE + bN0 + 3] = to_tf32(v0.w);
            sB[buf ^ 1][bK1 * SB_STRIDE + bN1 + 0] = to_tf32(v1.x);
            sB[buf ^ 1][bK1 * SB_STRIDE + bN1 + 1] = to_tf32(v1.y);
            sB[buf ^ 1][bK1 * SB_STRIDE + bN1 + 2] = to_tf32(v1.z);
            sB[buf ^ 1][bK1 * SB_STRIDE + bN1 + 3] = to_tf32(v1.w);
        }
        __syncthreads();
        buf ^= 1;
    }

    float cs[4][2];
#pragma unroll
    for (int nt = 0; nt < 4; nt++) {
        cs[nt][0] = 0.f; cs[nt][1] = 0.f;
#pragma unroll
        for (int mt = 0; mt < 4; mt++) {
            cs[nt][0] += elu1(acc[mt][nt][0]) + elu1(acc[mt][nt][2]);
            cs[nt][1] += elu1(acc[mt][nt][1]) + elu1(acc[mt][nt][3]);
        }
    }
#pragma unroll
    for (int o = 4; o <= 16; o <<= 1) {
#pragma unroll
        for (int nt = 0; nt < 4; nt++) {
            cs[nt][0] += __shfl_xor_sync(0xffffffffu, cs[nt][0], o);
            cs[nt][1] += __shfl_xor_sync(0xffffffffu, cs[nt][1], o);
        }
    }
    float* scratch = (float*)sA;
    if (lr4 == 0) {
#pragma unroll
        for (int nt = 0; nt < 4; nt++) {
            int col = wc * 32 + nt * 8 + lc4 * 2;
            scratch[wr * 128 + col]     = cs[nt][0];
            scratch[wr * 128 + col + 1] = cs[nt][1];
        }
    }
    __syncthreads();
    if (tid < 128)
        g_gat[(size_t)b * HID + bn + tid] =
            (scratch[tid] + scratch[128 + tid]) * (1.f / 128.f);
}

// ---------------------------------------------------------------------------
// softmax2 (no-max): sums the 4 t-partials inline (replaces t_combine),
// writes att rows tf32 to g_att2.
// ---------------------------------------------------------------------------
__global__ __launch_bounds__(256) void softmax2_kernel(
    const float* __restrict__ ae_out, const int* __restrict__ adj,
    const float* __restrict__ edge)
{
    __shared__ float st1[64];
    __shared__ float st2[128];

    int tid = threadIdx.x;
    int blk = blockIdx.x;
    int hb = blk & 1;
    int b = blk >> 1;
    int i0 = hb * 64;
    float ae = ae_out[0];
    const int M = Bq * Nn;

    if (tid < 64) {
        int r = b * Nn + i0 + tid;
        st1[tid] = g_t1p[r] + g_t1p[M + r] + g_t1p[2*M + r] + g_t1p[3*M + r];
    } else if (tid < 192) {
        int r = b * Nn + (tid - 64);
        st2[tid - 64] = g_t2p[r] + g_t2p[M + r] + g_t2p[2*M + r] + g_t2p[3*M + r];
    }
    __syncthreads();

    int warp = tid >> 5, lane = tid & 31;
    for (int i = warp; i < 64; i += 8) {
        int row = i0 + i;
        float4 ef = ((const float4*)(edge + ((size_t)b * Nn + row) * Nn))[lane];
        int4  av  = ((const int4*)(adj  + ((size_t)b * Nn + row) * Nn))[lane];
        float si = st1[i];
        int j0 = lane * 4;
        float v0 = si + st2[j0 + 0] + ef.x * ae; v0 = v0 >= 0.f ? v0 : 0.2f * v0; v0 = av.x > 0 ? v0 : -9e15f;
        float v1 = si + st2[j0 + 1] + ef.y * ae; v1 = v1 >= 0.f ? v1 : 0.2f * v1; v1 = av.y > 0 ? v1 : -9e15f;
        float v2 = si + st2[j0 + 2] + ef.z * ae; v2 = v2 >= 0.f ? v2 : 0.2f * v2; v2 = av.z > 0 ? v2 : -9e15f;
        float v3 = si + st2[j0 + 3] + ef.w * ae; v3 = v3 >= 0.f ? v3 : 0.2f * v3; v3 = av.w > 0 ? v3 : -9e15f;
        float e0 = __expf(v0), e1 = __expf(v1), e2 = __expf(v2), e3 = __expf(v3);
        float s = e0 + e1 + e2 + e3;
#pragma unroll
        for (int o = 16; o; o >>= 1) s += __shfl_xor_sync(0xffffffffu, s, o);
        float inv = 1.f / s;
        uint4 o4;
        o4.x = to_tf32(e0 * inv); o4.y = to_tf32(e1 * inv);
        o4.z = to_tf32(e2 * inv); o4.w = to_tf32(e3 * inv);
        *(uint4*)(g_att2 + ((size_t)b * Nn + row) * Nn + j0) = o4;
    }
}

// ---------------------------------------------------------------------------
// Tail fp32 GEMM (exact), with optional concat mode:
// A index = row*Ksplit + k for k < Ksplit, else A2[row*Ksplit + k-Ksplit];
// B index = B[k*N+col] for k < Ksplit, else B2[(k-Ksplit)*N+col].
// Normal calls: Ksplit == K, A2/B2/bias2 null.
// flags: 1 = bias, 2 = relu, 4 = accumulate
// ---------------------------------------------------------------------------
__global__ __launch_bounds__(256) void tail_gemm_kernel(
    const float* __restrict__ A, const float* __restrict__ A2,
    const float* __restrict__ B, const float* __restrict__ B2,
    const float* __restrict__ bias, const float* __restrict__ bias2,
    float* __restrict__ C, int M, int N, int K, int Ksplit, int flags)
{
    __shared__ float As[2][16][64];
    __shared__ float Bs[2][16][64];

    int tid = threadIdx.x;
    int bm = blockIdx.y * 64;
    int bn = blockIdx.x * 64;
    int tx = tid & 15;
    int ty = tid >> 4;

    int aRow = tid >> 2, aK = (tid & 3) * 4;
    int bK = tid >> 4, bN = (tid & 15) * 4;

    u64 acc[4][2];
#pragma unroll
    for (int i = 0; i < 4; i++) { acc[i][0] = 0ull; acc[i][1] = 0ull; }

    const int Ktiles = (K + 15) / 16;
    const float* Arow1 = A + (size_t)(bm + aRow) * Ksplit;
    const float* Arow2 = A2 ? A2 + (size_t)(bm + aRow) * Ksplit : A;

    {
#pragma unroll
        for (int i = 0; i < 4; i++) {
            int k = aK + i;
            float v = 0.f;
            if (k < K) v = (k < Ksplit) ? Arow1[k] : Arow2[k - Ksplit];
            As[0][aK + i][aRow] = v;
        }
        float4 v = make_float4(0.f, 0.f, 0.f, 0.f);
        if (bK < K) {
            v = (bK < Ksplit) ? *(const float4*)(B + (size_t)bK * N + bn + bN)
                              : *(const float4*)(B2 + (size_t)(bK - Ksplit) * N + bn + bN);
        }
        *(float4*)&Bs[0][bK][bN] = v;
    }
    __syncthreads();

    int buf = 0;
    for (int t = 0; t < Ktiles; t++) {
        float ap[4];
        float4 bp = make_float4(0.f, 0.f, 0.f, 0.f);
        bool has_next = (t + 1 < Ktiles);
        if (has_next) {
            int k0 = (t + 1) * 16;
#pragma unroll
            for (int i = 0; i < 4; i++) {
                int k = k0 + aK + i;
                float v = 0.f;
                if (k < K) v = (k < Ksplit) ? Arow1[k] : Arow2[k - Ksplit];
                ap[i] = v;
            }
            int k = k0 + bK;
            if (k < K) {
                bp = (k < Ksplit) ? *(const float4*)(B + (size_t)k * N + bn + bN)
                                  : *(const float4*)(B2 + (size_t)(k - Ksplit) * N + bn + bN);
            }
        }

#pragma unroll
        for (int kk = 0; kk < 16; kk++) {
            u64 b0 = *(const u64*)&Bs[buf][kk][tx * 4];
            u64 b1 = *(const u64*)&Bs[buf][kk][tx * 4 + 2];
            float a0 = As[buf][kk][ty * 4];
            float a1 = As[buf][kk][ty * 4 + 1];
            float a2 = As[buf][kk][ty * 4 + 2];
            float a3 = As[buf][kk][ty * 4 + 3];
            u64 d0 = dup2(a0), d1 = dup2(a1), d2 = dup2(a2), d3 = dup2(a3);
            fma2(acc[0][0], d0, b0); fma2(acc[0][1], d0, b1);
            fma2(acc[1][0], d1, b0); fma2(acc[1][1], d1, b1);
            fma2(acc[2][0], d2, b0); fma2(acc[2][1], d2, b1);
            fma2(acc[3][0], d3, b0); fma2(acc[3][1], d3, b1);
        }

        if (has_next) {
#pragma unroll
            for (int i = 0; i < 4; i++) As[buf ^ 1][aK + i][aRow] = ap[i];
            *(float4*)&Bs[buf ^ 1][bK][bN] = bp;
        }
        __syncthreads();
        buf ^= 1;
    }

#pragma unroll
    for (int i = 0; i < 4; i++) {
        int row = bm + ty * 4 + i;
#pragma unroll
        for (int j = 0; j < 2; j++) {
            int col = bn + tx * 4 + j * 2;
            float2 v = upk2(acc[i][j]);
            if (flags & 4) {
                float2 c = *(const float2*)&C[(size_t)row * N + col];
                v.x += c.x; v.y += c.y;
            }
            if (flags & 1) { v.x += bias[col]; v.y += bias[col + 1]; }
            if (bias2)     { v.x += bias2[col]; v.y += bias2[col + 1]; }
            if (flags & 2) { v.x = fmaxf(v.x, 0.f); v.y = fmaxf(v.y, 0.f); }
            *(float2*)&C[(size_t)row * N + col] = v;
        }
    }
}

// ---------------------------------------------------------------------------
__global__ void wcat_kernel(const float* __restrict__ W_heads)
{
    int idx = blockIdx.x * blockDim.x + threadIdx.x;
    if (idx >= NHEADS * F_IN * NHID) return;
    int h = idx / (F_IN * NHID);
    int rem = idx - h * (F_IN * NHID);
    int f = rem / NHID;
    int d = rem - f * NHID;
    g_Wcat[f * HID + h * NHID + d] = W_heads[idx];
}

// ---------------------------------------------------------------------------
// attn1 (tf32 mma, 32-col B-chunks, no-max softmax, chunk-0 prefetch).
// ---------------------------------------------------------------------------
#define WCH_STR 40
#define AT_STR 132

__global__ __launch_bounds__(256) void attn1_kernel(
    const float* __restrict__ ae_heads, const int* __restrict__ adj,
    const float* __restrict__ edge)
{
    extern __shared__ u32 smu[];
    u32* sWh  = smu;                        // 128*40
    u32* sAtt = smu + 128 * WCH_STR;        // 64*132
    float* ss1 = (float*)(smu + 128 * WCH_STR + 64 * AT_STR);  // 64
    float* ss2 = ss1 + 64;                                      // 128

    int tid = threadIdx.x;
    int blk = blockIdx.x;
    int hb = blk & 1;
    int bh = blk >> 1;
    int hh = bh & 7, b = bh >> 3;
    int i0 = hb * 64;
    float ae = ae_heads[hh];

    const float* whp = g_Wh + (size_t)b * Nn * HID + hh * NHID;

    for (int i = tid; i < 128 * 8; i += 256) {
        int r = i >> 3, c = (i & 7) * 4;
        float4 v = *(const float4*)(whp + (size_t)r * HID + c);
        uint4 t;
        t.x = to_tf32(v.x); t.y = to_tf32(v.y);
        t.z = to_tf32(v.z); t.w = to_tf32(v.w);
        *(uint4*)&sWh[r * WCH_STR + c] = t;
    }
    if (tid < 64)  ss1[tid] = g_s1[bh * Nn + i0 + tid];
    if (tid < 128) ss2[tid] = g_s2[bh * Nn + tid];
    __syncthreads();

    int warp = tid >> 5, lane = tid & 31;
    for (int i = warp; i < 64; i += 8) {
        int row = i0 + i;
        float4 ef = ((const float4*)(edge + ((size_t)b * Nn + row) * Nn))[lane];
        int4  av  = ((const int4*)(adj  + ((size_t)b * Nn + row) * Nn))[lane];
        float si = ss1[i];
        int j0 = lane * 4;
        float v0 = si + ss2[j0 + 0] + ef.x * ae; v0 = v0 >= 0.f ? v0 : 0.2f * v0; v0 = av.x > 0 ? v0 : -9e15f;
        float v1 = si + ss2[j0 + 1] + ef.y * ae; v1 = v1 >= 0.f ? v1 : 0.2f * v1; v1 = av.y > 0 ? v1 : -9e15f;
        float v2 = si + ss2[j0 + 2] + ef.z * ae; v2 = v2 >= 0.f ? v2 : 0.2f * v2; v2 = av.z > 0 ? v2 : -9e15f;
        float v3 = si + ss2[j0 + 3] + ef.w * ae; v3 = v3 >= 0.f ? v3 : 0.2f * v3; v3 = av.w > 0 ? v3 : -9e15f;
        float e0 = __expf(v0), e1 = __expf(v1), e2 = __expf(v2), e3 = __expf(v3);
        float s = e0 + e1 + e2 + e3;
#pragma unroll
        for (int o = 16; o; o >>= 1) s += __shfl_xor_sync(0xffffffffu, s, o);
        float inv = 1.f / s;
        uint4 o4;
        o4.x = to_tf32(e0 * inv); o4.y = to_tf32(e1 * inv);
        o4.z = to_tf32(e2 * inv); o4.w = to_tf32(e3 * inv);
        *(uint4*)&sAtt[i * AT_STR + lane * 4] = o4;
    }
    __syncthreads();

    int wr = warp >> 2, wc = warp & 3;
    int lr4 = lane >> 2, lc4 = lane & 3;

#pragma unroll
    for (int ch = 0; ch < 2; ch++) {
        if (ch == 1) {
            __syncthreads();
            for (int i = tid; i < 128 * 8; i += 256) {
                int r = i >> 3, c = (i & 7) * 4;
                float4 v = *(const float4*)(whp + (size_t)r * HID + 32 + c);
                uint4 t;
                t.x = to_tf32(v.x); t.y = to_tf32(v.y);
                t.z = to_tf32(v.z); t.w = to_tf32(v.w);
                *(uint4*)&sWh[r * WCH_STR + c] = t;
            }
            __syncthreads();
        }

        float acc[2][4];
#pragma unroll
        for (int mt = 0; mt < 2; mt++)
#pragma unroll
            for (int i = 0; i < 4; i++) acc[mt][i] = 0.f;

#pragma unroll
        for (int kk = 0; kk < 128; kk += 8) {
            u32 afr[2][4], bfr[2];
#pragma unroll
            for (int mt = 0; mt < 2; mt++) {
                int r0 = wr * 32 + mt * 16 + lr4;
                int c0 = kk + lc4;
                afr[mt][0] = sAtt[r0 * AT_STR + c0];
                afr[mt][1] = sAtt[(r0 + 8) * AT_STR + c0];
                afr[mt][2] = sAtt[r0 * AT_STR + c0 + 4];
                afr[mt][3] = sAtt[(r0 + 8) * AT_STR + c0 + 4];
            }
            {
                int col = wc * 8 + lr4;
                bfr[0] = sWh[(kk + lc4) * WCH_STR + col];
                bfr[1] = sWh[(kk + lc4 + 4) * WCH_STR + col];
            }
#pragma unroll
            for (int mt = 0; mt < 2; mt++)
                mma_tf32(acc[mt], afr[mt], bfr);
        }

#pragma unroll
        for (int mt = 0; mt < 2; mt++) {
            int col = ch * 32 + wc * 8 + lc4 * 2;
#pragma unroll
            for (int half = 0; half < 2; half++) {
                int i = i0 + wr * 32 + mt * 16 + lr4 + half * 8;
                float2 v;
                v.x = elu1(acc[mt][half * 2]);
                v.y = elu1(acc[mt][half * 2 + 1]);
                *(float2*)(g_x + ((size_t)b * Nn + i) * HID + hh * NHID + col) = v;
            }
        }
    }
}

// ---------------------------------------------------------------------------
// final: warp per (b,t): coalesced lane-strided dot-512 + reduce.
// ---------------------------------------------------------------------------
__global__ __launch_bounds__(256) void final_kernel(
    const float* __restrict__ X, const float* __restrict__ W,
    const float* __restrict__ bias, float* __restrict__ out)
{
    int gw = (blockIdx.x * blockDim.x + threadIdx.x) >> 5;
    int lane = threadIdx.x & 31;
    if (gw >= Bq * TASKS) return;
    int b = gw / TASKS, t = gw - b * TASKS;
    const float* x = X + (size_t)b * HID;
    float s = 0.f;
#pragma unroll
    for (int i = 0; i < 16; i++) {
        int d = lane + i * 32;
        s += x[d] * W[d * TASKS + t];
    }
#pragma unroll
    for (int o = 16; o; o >>= 1) s += __shfl_xor_sync(0xffffffffu, s, o);
    if (lane == 0) out[gw] = s + bias[t];
}

// ---------------------------------------------------------------------------
extern "C" void kernel_launch(void* const* d_in, const int* in_sizes, int n_in,
                              void* d_out, int out_size)
{
    const float* h        = (const float*)d_in[0];
    const int*   adj      = (const int*)d_in[1];
    const float* edge     = (const float*)d_in[2];
    const float* fp       = (const float*)d_in[3];
    const float* W_heads  = (const float*)d_in[4];
    const float* a1_heads = (const float*)d_in[5];
    const float* a2_heads = (const float*)d_in[6];
    const float* ae_heads = (const float*)d_in[7];
    const float* W_out    = (const float*)d_in[8];
    const float* a1_out   = (const float*)d_in[9];
    const float* a2_out   = (const float*)d_in[10];
    const float* ae_out   = (const float*)d_in[11];
    const float* fc1_w    = (const float*)d_in[12];
    const float* fc1_b    = (const float*)d_in[13];
    const float* fc2_w    = (const float*)d_in[14];
    const float* fc2_b    = (const float*)d_in[15];
    const float* q_w      = (const float*)d_in[16];
    const float* q_b      = (const float*)d_in[17];
    // k_w (18), k_b (19) unused: softmax over size-1 axis == 1 -> fused = q+v
    const float* v_w      = (const float*)d_in[20];
    const float* v_b      = (const float*)d_in[21];
    const float* o_w      = (const float*)d_in[22];
    const float* o_b      = (const float*)d_in[23];
    const float* ffn1_w   = (const float*)d_in[24];
    const float* ffn1_b   = (const float*)d_in[25];
    const float* ffn2_w   = (const float*)d_in[26];
    const float* ffn2_b   = (const float*)d_in[27];
    float* out = (float*)d_out;

    float *Wh, *x, *gat, *fpnh, *fpn, *buf1, *buf2, *Wx, *Wcat;
    float *s1p, *s2p, *t1p, *t2p;
    cudaGetSymbolAddress((void**)&Wh, g_Wh);
    cudaGetSymbolAddress((void**)&x, g_x);
    cudaGetSymbolAddress((void**)&Wx, g_Wx);
    cudaGetSymbolAddress((void**)&gat, g_gat);
    cudaGetSymbolAddress((void**)&fpnh, g_fpnh);
    cudaGetSymbolAddress((void**)&fpn, g_fpn);
    cudaGetSymbolAddress((void**)&buf1, g_buf1);
    cudaGetSymbolAddress((void**)&buf2, g_buf2);
    cudaGetSymbolAddress((void**)&Wcat, g_Wcat);
    cudaGetSymbolAddress((void**)&s1p, g_s1);
    cudaGetSymbolAddress((void**)&s2p, g_s2);
    cudaGetSymbolAddress((void**)&t1p, g_t1p);
    cudaGetSymbolAddress((void**)&t2p, g_t2p);

    const int ATT1_SMEM = (128 * WCH_STR + 64 * AT_STR + 192) * 4;   // 55040
    cudaFuncSetAttribute(attn1_kernel, cudaFuncAttributeMaxDynamicSharedMemorySize, ATT1_SMEM);

    const int M1 = Bq * Nn;  // 65536

    // 1. Wcat transpose
    wcat_kernel<<<(NHEADS * F_IN * NHID + 255) / 256, 256>>>(W_heads);

    // 2. Wh = h @ Wcat (tf32) + fused s1/s2 epilogue
    {
        dim3 grid(HID / 128, M1 / 128);
        sgemm_tc_kernel<<<grid, 256>>>(h, Wcat, nullptr, Wh, M1, HID, F_IN, 0,
                                       1, a1_heads, a2_heads, s1p, s2p);
    }

    // 3. attn1
    attn1_kernel<<<Bq * NHEADS * 2, 256, ATT1_SMEM>>>(ae_heads, adj, edge);

    // 4. Wx = x @ W_out (tf32) + fused t1/t2 partial epilogue
    {
        dim3 grid(HID / 128, M1 / 128);
        sgemm_tc_kernel<<<grid, 256>>>(x, W_out, nullptr, Wx, M1, HID, HID, 0,
                                       2, a1_out, a2_out, t1p, t2p);
    }

    // 5. attn2 split (softmax2 sums t-partials inline), then batched AV GEMM
    softmax2_kernel<<<Bq * 2, 256>>>(ae_out, adj, edge);
    {
        dim3 grid(HID / 128, Bq);
        av2_kernel<<<grid, 256>>>();
    }

    // 6. FPN (exact fp32 tails)
    {
        dim3 grid(HID / 64, Bq / 64);
        tail_gemm_kernel<<<grid, 256>>>(fp, nullptr, fc1_w, nullptr, fc1_b, nullptr,
                                        fpnh, Bq, HID, FP_DIM, FP_DIM, 1 | 2);
        tail_gemm_kernel<<<grid, 256>>>(fpnh, nullptr, fc2_w, nullptr, fc2_b, nullptr,
                                        fpn, Bq, HID, HID, HID, 1);
    }

    // 7. fusion + FFN:
    //    buf1 = [gat|fpn] @ [[q_w],[v_w]] + q_b + v_b  (one concat GEMM)
    //    buf2 = relu(buf1@o_w + o_b); buf1 = relu(buf2@ffn1 + b)
    {
        dim3 grid(HID / 64, Bq / 64);
        tail_gemm_kernel<<<grid, 256>>>(gat, fpn, q_w, v_w, q_b, v_b,
                                        buf1, Bq, HID, 2 * HID, HID, 1);
        tail_gemm_kernel<<<grid, 256>>>(buf1, nullptr, o_w, nullptr, o_b, nullptr,
                                        buf2, Bq, HID, HID, HID, 1 | 2);
        tail_gemm_kernel<<<grid, 256>>>(buf2, nullptr, ffn1_w, nullptr, ffn1_b, nullptr,
                                        buf1, Bq, HID, HID, HID, 1 | 2);
    }

    // 8. final projection (warp per output)
    final_kernel<<<(Bq * TASKS * 32 + 255) / 256, 256>>>(buf1, ffn2_w, ffn2_b, out);
}

// round 16
// speedup vs baseline: 1.2911x; 1.0583x over previous
#include <cuda_runtime.h>
#include <cuda_bf16.h>
#include <math.h>

// ---------------------------------------------------------------------------
// FPGNN forward. R16:
//  - big GEMMs: tf32 mma, 128x256 CTA tile / 64x64 warp tile (1.5x less
//    smem-crossbar traffic per flop), fused s/t epilogues
//  - attn1: tf32 mma, 32-col chunks, no-max softmax           [R11/R14]
//  - attn2: softmax2 (2 t-partials) -> gmem tf32 att, av2 batched GEMM
//  - tails: exact fp32 FFMA2 64x64; q+v concat-GEMM
// ---------------------------------------------------------------------------

#define Bq 512
#define Nn 128
#define F_IN 133
#define NHEADS 8
#define NHID 64
#define HID 512
#define FP_DIM 1489
#define TASKS 12

typedef unsigned long long u64;
typedef unsigned int u32;

__device__ __forceinline__ u64 pack2(float lo, float hi) {
    u64 r; asm("mov.b64 %0, {%1,%2};" : "=l"(r) : "f"(lo), "f"(hi)); return r;
}
__device__ __forceinline__ u64 dup2(float v) { return pack2(v, v); }
__device__ __forceinline__ void fma2(u64& d, u64 a, u64 b) {
    asm("fma.rn.f32x2 %0, %1, %2, %0;" : "+l"(d) : "l"(a), "l"(b));
}
__device__ __forceinline__ float2 upk2(u64 v) {
    float2 r; asm("mov.b64 {%0,%1}, %2;" : "=f"(r.x), "=f"(r.y) : "l"(v)); return r;
}
__device__ __forceinline__ u32 to_tf32(float f) {
    u32 r; asm("cvt.rna.tf32.f32 %0, %1;" : "=r"(r) : "f"(f)); return r;
}
__device__ __forceinline__ void mma_tf32(float* d, const u32* a, const u32* b) {
    asm volatile(
        "mma.sync.aligned.m16n8k8.row.col.f32.tf32.tf32.f32 "
        "{%0,%1,%2,%3}, {%4,%5,%6,%7}, {%8,%9}, {%0,%1,%2,%3};\n"
        : "+f"(d[0]), "+f"(d[1]), "+f"(d[2]), "+f"(d[3])
        : "r"(a[0]), "r"(a[1]), "r"(a[2]), "r"(a[3]), "r"(b[0]), "r"(b[1]));
}
__device__ __forceinline__ float elu1(float v) {
    return v > 0.f ? v : (__expf(v) - 1.f);
}

// ---- scratch (device globals; no allocation allowed) ----
__device__ float g_Wcat[F_IN * HID];
__device__ float g_Wh[(size_t)Bq * Nn * HID];
__device__ float g_s1[Bq * NHEADS * Nn];
__device__ float g_s2[Bq * NHEADS * Nn];
__device__ float g_x[(size_t)Bq * Nn * HID];
__device__ float g_Wx[(size_t)Bq * Nn * HID];
__device__ float g_t1p[2 * Bq * Nn];
__device__ float g_t2p[2 * Bq * Nn];
__device__ u32   g_att2[(size_t)Bq * Nn * Nn];   // tf32 att
__device__ float g_gat[Bq * HID];
__device__ float g_fpnh[Bq * HID];
__device__ float g_fpn[Bq * HID];
__device__ float g_buf1[Bq * HID];
__device__ float g_buf2[Bq * HID];

// ---------------------------------------------------------------------------
// Big tf32 GEMM: BM=128, BN=256, BK=16. 256 threads = 8 warps (2x4),
// warp tile 64x64 (mt 0..3, nt 0..7). Dynamic smem (54.3 KB), 1 CTA/SM.
// flags: 1 = bias, 2 = relu, 4 = accumulate
// smode: 1 = per-head (64-col) dots -> so1/so2 (g_s1/g_s2 layout);
//        2 = per-CTA 256-col partials -> so1[bx*M + row] (2 N-tiles).
// Bank proofs: A (20*lr4+lc4)%32 distinct; B (264*lc4+col)%32 = (8*lc4+lr4)
// distinct.
// ---------------------------------------------------------------------------
#define SA_STRIDE 20
#define SB_STRIDE 264
#define SGEMM_SMEM ((2 * 128 * SA_STRIDE + 2 * 16 * SB_STRIDE) * 4)

__global__ __launch_bounds__(256) void sgemm_tc_kernel(
    const float* __restrict__ A, const float* __restrict__ B,
    const float* __restrict__ bias, float* __restrict__ C,
    int M, int N, int K, int flags,
    int smode, const float* __restrict__ av1, const float* __restrict__ av2,
    float* __restrict__ so1, float* __restrict__ so2)
{
    extern __shared__ u32 dsm[];
    u32* sAb = dsm;                              // 2 x 128*20
    u32* sBb = dsm + 2 * 128 * SA_STRIDE;        // 2 x 16*264

    int tid = threadIdx.x;
    int warp = tid >> 5, lane = tid & 31;
    int wr = warp >> 2, wc = warp & 3;           // 2 x 4; warp tile 64 x 64
    int bm = blockIdx.y * 128;
    int bn = blockIdx.x * 256;
    int lr4 = lane >> 2, lc4 = lane & 3;

    float acc[4][8][4];
#pragma unroll
    for (int mt = 0; mt < 4; mt++)
#pragma unroll
        for (int nt = 0; nt < 8; nt++)
#pragma unroll
            for (int i = 0; i < 4; i++) acc[mt][nt][i] = 0.f;

    const int Ktiles = (K + 15) / 16;
    // A loader: 2 chunks per thread (rows 0..127, 4-k segments)
    int aRow0 = tid >> 2,         aK0 = (tid & 3) * 4;
    int aRow1 = (tid + 256) >> 2, aK1 = ((tid + 256) & 3) * 4;
    // B loader: row bK (0..15), 4 quarter-columns of 4 floats
    int bK = tid >> 4;                // 0..15
    int bC = (tid & 15) * 4;          // 0..60

    float ar[2][4], br[4][4];

    // ---- prefetch tile 0 ----
    {
#pragma unroll
        for (int i = 0; i < 4; i++) {
            int k = aK0 + i;
            ar[0][i] = (k < K) ? A[(size_t)(bm + aRow0) * K + k] : 0.f;
            k = aK1 + i;
            ar[1][i] = (k < K) ? A[(size_t)(bm + aRow1) * K + k] : 0.f;
        }
#pragma unroll
        for (int q = 0; q < 4; q++) {
            if (bK < K) *(float4*)br[q] = *(const float4*)(B + (size_t)bK * N + bn + q * 64 + bC);
            else { br[q][0] = br[q][1] = br[q][2] = br[q][3] = 0.f; }
        }
    }
#pragma unroll
    for (int i = 0; i < 4; i++) {
        sAb[aRow0 * SA_STRIDE + aK0 + i] = to_tf32(ar[0][i]);
        sAb[aRow1 * SA_STRIDE + aK1 + i] = to_tf32(ar[1][i]);
    }
#pragma unroll
    for (int q = 0; q < 4; q++)
#pragma unroll
        for (int i = 0; i < 4; i++)
            sBb[bK * SB_STRIDE + q * 64 + bC + i] = to_tf32(br[q][i]);
    __syncthreads();

    int buf = 0;
    for (int t = 0; t < Ktiles; t++) {
        bool has_next = (t + 1 < Ktiles);
        if (has_next) {
            int k0 = (t + 1) * 16;
#pragma unroll
            for (int i = 0; i < 4; i++) {
                int k = k0 + aK0 + i;
                ar[0][i] = (k < K) ? A[(size_t)(bm + aRow0) * K + k] : 0.f;
                k = k0 + aK1 + i;
                ar[1][i] = (k < K) ? A[(size_t)(bm + aRow1) * K + k] : 0.f;
            }
            int k = k0 + bK;
#pragma unroll
            for (int q = 0; q < 4; q++) {
                if (k < K) *(float4*)br[q] = *(const float4*)(B + (size_t)k * N + bn + q * 64 + bC);
                else { br[q][0] = br[q][1] = br[q][2] = br[q][3] = 0.f; }
            }
        }

        const u32* cA = sAb + buf * 128 * SA_STRIDE;
        const u32* cB = sBb + buf * 16 * SB_STRIDE;
#pragma unroll
        for (int kk = 0; kk < 16; kk += 8) {
            u32 afr[4][4], bfr[8][2];
#pragma unroll
            for (int mt = 0; mt < 4; mt++) {
                int r0 = wr * 64 + mt * 16 + lr4;
                int c0 = kk + lc4;
                afr[mt][0] = cA[r0 * SA_STRIDE + c0];
                afr[mt][1] = cA[(r0 + 8) * SA_STRIDE + c0];
                afr[mt][2] = cA[r0 * SA_STRIDE + c0 + 4];
                afr[mt][3] = cA[(r0 + 8) * SA_STRIDE + c0 + 4];
            }
#pragma unroll
            for (int nt = 0; nt < 8; nt++) {
                int col = wc * 64 + nt * 8 + lr4;
                bfr[nt][0] = cB[(kk + lc4) * SB_STRIDE + col];
                bfr[nt][1] = cB[(kk + lc4 + 4) * SB_STRIDE + col];
            }
#pragma unroll
            for (int mt = 0; mt < 4; mt++)
#pragma unroll
                for (int nt = 0; nt < 8; nt++)
                    mma_tf32(acc[mt][nt], afr[mt], bfr[nt]);
        }

        if (has_next) {
            u32* nA = sAb + (buf ^ 1) * 128 * SA_STRIDE;
            u32* nB = sBb + (buf ^ 1) * 16 * SB_STRIDE;
#pragma unroll
            for (int i = 0; i < 4; i++) {
                nA[aRow0 * SA_STRIDE + aK0 + i] = to_tf32(ar[0][i]);
                nA[aRow1 * SA_STRIDE + aK1 + i] = to_tf32(ar[1][i]);
            }
#pragma unroll
            for (int q = 0; q < 4; q++)
#pragma unroll
                for (int i = 0; i < 4; i++)
                    nB[bK * SB_STRIDE + q * 64 + bC + i] = to_tf32(br[q][i]);
        }
        __syncthreads();
        buf ^= 1;
    }

    // ---- C write ----
#pragma unroll
    for (int mt = 0; mt < 4; mt++) {
#pragma unroll
        for (int nt = 0; nt < 8; nt++) {
            int col = bn + wc * 64 + nt * 8 + lc4 * 2;
#pragma unroll
            for (int half = 0; half < 2; half++) {
                int row = bm + wr * 64 + mt * 16 + lr4 + half * 8;
                float2 v = make_float2(acc[mt][nt][half * 2],
                                       acc[mt][nt][half * 2 + 1]);
                if (flags & 4) {
                    float2 c = *(const float2*)&C[(size_t)row * N + col];
                    v.x += c.x; v.y += c.y;
                }
                if (flags & 1) { v.x += bias[col]; v.y += bias[col + 1]; }
                if (flags & 2) { v.x = fmaxf(v.x, 0.f); v.y = fmaxf(v.y, 0.f); }
                *(float2*)&C[(size_t)row * N + col] = v;
            }
        }
    }

    // ---- fused score epilogue ----
    if (smode == 1) {
        // each warp's 64 cols = exactly one head (64-aligned); direct dots.
        int head = (bn >> 6) + wc;
        float a1c[8][2], a2c[8][2];
#pragma unroll
        for (int nt = 0; nt < 8; nt++) {
            int col = bn + wc * 64 + nt * 8 + lc4 * 2;
            a1c[nt][0] = av1[col]; a1c[nt][1] = av1[col + 1];
            a2c[nt][0] = av2[col]; a2c[nt][1] = av2[col + 1];
        }
#pragma unroll
        for (int mt = 0; mt < 4; mt++) {
#pragma unroll
            for (int half = 0; half < 2; half++) {
                float p1 = 0.f, p2 = 0.f;
#pragma unroll
                for (int nt = 0; nt < 8; nt++) {
                    p1 += acc[mt][nt][half*2] * a1c[nt][0] + acc[mt][nt][half*2+1] * a1c[nt][1];
                    p2 += acc[mt][nt][half*2] * a2c[nt][0] + acc[mt][nt][half*2+1] * a2c[nt][1];
                }
                p1 += __shfl_xor_sync(0xffffffffu, p1, 1);
                p1 += __shfl_xor_sync(0xffffffffu, p1, 2);
                p2 += __shfl_xor_sync(0xffffffffu, p2, 1);
                p2 += __shfl_xor_sync(0xffffffffu, p2, 2);
                if (lc4 == 0) {
                    int rg = bm + wr * 64 + mt * 16 + lr4 + half * 8;
                    int bb = rg >> 7, nn2 = rg & 127;
                    size_t o = ((size_t)bb * NHEADS + head) * Nn + nn2;
                    so1[o] = p1;
                    so2[o] = p2;
                }
            }
        }
    } else if (smode == 2) {
        float a1c[8][2], a2c[8][2];
#pragma unroll
        for (int nt = 0; nt < 8; nt++) {
            int col = bn + wc * 64 + nt * 8 + lc4 * 2;
            a1c[nt][0] = av1[col]; a1c[nt][1] = av1[col + 1];
            a2c[nt][0] = av2[col]; a2c[nt][1] = av2[col + 1];
        }
        float* sc1 = (float*)dsm;          // 4 wc x 128 rows
        float* sc2 = sc1 + 512;
#pragma unroll
        for (int mt = 0; mt < 4; mt++) {
#pragma unroll
            for (int half = 0; half < 2; half++) {
                float p1 = 0.f, p2 = 0.f;
#pragma unroll
                for (int nt = 0; nt < 8; nt++) {
                    p1 += acc[mt][nt][half*2] * a1c[nt][0] + acc[mt][nt][half*2+1] * a1c[nt][1];
                    p2 += acc[mt][nt][half*2] * a2c[nt][0] + acc[mt][nt][half*2+1] * a2c[nt][1];
                }
                p1 += __shfl_xor_sync(0xffffffffu, p1, 1);
                p1 += __shfl_xor_sync(0xffffffffu, p1, 2);
                p2 += __shfl_xor_sync(0xffffffffu, p2, 1);
                p2 += __shfl_xor_sync(0xffffffffu, p2, 2);
                if (lc4 == 0) {
                    int rl = wr * 64 + mt * 16 + lr4 + half * 8;   // 0..127
                    sc1[wc * 128 + rl] = p1;
                    sc2[wc * 128 + rl] = p2;
                }
            }
        }
        __syncthreads();
        if (tid < 128) {
            float v1 = sc1[tid] + sc1[128 + tid] + sc1[256 + tid] + sc1[384 + tid];
            float v2 = sc2[tid] + sc2[128 + tid] + sc2[256 + tid] + sc2[384 + tid];
            so1[(size_t)blockIdx.x * M + bm + tid] = v1;
            so2[(size_t)blockIdx.x * M + bm + tid] = v2;
        }
    }
}

// ---------------------------------------------------------------------------
// av2: batched tf32 GEMM D[b] = att2[b] @ Wx[b][:, bn..+127], fused
// ELU + column-mean -> g_gat. Validated R13 (128x128 tiles, static smem).
// ---------------------------------------------------------------------------
#define AV_SA 20
#define AV_SB 136

__global__ __launch_bounds__(256) void av2_kernel()
{
    __shared__ u32 sA[2][128 * AV_SA];
    __shared__ u32 sB[2][16 * AV_SB];

    int tid = threadIdx.x;
    int warp = tid >> 5, lane = tid & 31;
    int wr = warp >> 2, wc = warp & 3;
    int b = blockIdx.y;
    int bn = blockIdx.x * 128;
    int lr4 = lane >> 2, lc4 = lane & 3;

    const u32*   Ab = g_att2 + (size_t)b * Nn * Nn;
    const float* Bb = g_Wx + (size_t)b * Nn * HID;

    float acc[4][4][4];
#pragma unroll
    for (int mt = 0; mt < 4; mt++)
#pragma unroll
        for (int nt = 0; nt < 4; nt++)
#pragma unroll
            for (int i = 0; i < 4; i++) acc[mt][nt][i] = 0.f;

    int aRow0 = tid >> 2,         aK0 = (tid & 3) * 4;
    int aRow1 = (tid + 256) >> 2, aK1 = ((tid + 256) & 3) * 4;
    int bK0 = tid >> 5,           bN0 = (tid & 31) * 4;
    int bK1 = (tid + 256) >> 5,   bN1 = ((tid + 256) & 31) * 4;

    {
        *(uint4*)&sA[0][aRow0 * AV_SA + aK0] = *(const uint4*)(Ab + (size_t)aRow0 * Nn + aK0);
        *(uint4*)&sA[0][aRow1 * AV_SA + aK1] = *(const uint4*)(Ab + (size_t)aRow1 * Nn + aK1);
        float4 v0 = *(const float4*)(Bb + (size_t)bK0 * HID + bn + bN0);
        float4 v1 = *(const float4*)(Bb + (size_t)bK1 * HID + bn + bN1);
        sB[0][bK0 * AV_SB + bN0 + 0] = to_tf32(v0.x);
        sB[0][bK0 * AV_SB + bN0 + 1] = to_tf32(v0.y);
        sB[0][bK0 * AV_SB + bN0 + 2] = to_tf32(v0.z);
        sB[0][bK0 * AV_SB + bN0 + 3] = to_tf32(v0.w);
        sB[0][bK1 * AV_SB + bN1 + 0] = to_tf32(v1.x);
        sB[0][bK1 * AV_SB + bN1 + 1] = to_tf32(v1.y);
        sB[0][bK1 * AV_SB + bN1 + 2] = to_tf32(v1.z);
        sB[0][bK1 * AV_SB + bN1 + 3] = to_tf32(v1.w);
    }
    __syncthreads();

    int buf = 0;
    for (int t = 0; t < 8; t++) {
        bool has_next = (t + 1 < 8);
        uint4 an0, an1;
        float4 v0, v1;
        if (has_next) {
            int k0 = (t + 1) * 16;
            an0 = *(const uint4*)(Ab + (size_t)aRow0 * Nn + k0 + aK0);
            an1 = *(const uint4*)(Ab + (size_t)aRow1 * Nn + k0 + aK1);
            v0 = *(const float4*)(Bb + (size_t)(k0 + bK0) * HID + bn + bN0);
            v1 = *(const float4*)(Bb + (size_t)(k0 + bK1) * HID + bn + bN1);
        }

        const u32* cA = sA[buf];
        const u32* cB = sB[buf];
#pragma unroll
        for (int kk = 0; kk < 16; kk += 8) {
            u32 afr[4][4], bfr[4][2];
#pragma unroll
            for (int mt = 0; mt < 4; mt++) {
                int r0 = wr * 64 + mt * 16 + lr4;
                int c0 = kk + lc4;
                afr[mt][0] = cA[r0 * AV_SA + c0];
                afr[mt][1] = cA[(r0 + 8) * AV_SA + c0];
                afr[mt][2] = cA[r0 * AV_SA + c0 + 4];
                afr[mt][3] = cA[(r0 + 8) * AV_SA + c0 + 4];
            }
#pragma unroll
            for (int nt = 0; nt < 4; nt++) {
                int col = wc * 32 + nt * 8 + lr4;
                bfr[nt][0] = cB[(kk + lc4) * AV_SB + col];
                bfr[nt][1] = cB[(kk + lc4 + 4) * AV_SB + col];
            }
#pragma unroll
            for (int mt = 0; mt < 4; mt++)
#pragma unroll
                for (int nt = 0; nt < 4; nt++)
                    mma_tf32(acc[mt][nt], afr[mt], bfr[nt]);
        }

        if (has_next) {
            *(uint4*)&sA[buf ^ 1][aRow0 * AV_SA + aK0] = an0;
            *(uint4*)&sA[buf ^ 1][aRow1 * AV_SA + aK1] = an1;
            sB[buf ^ 1][bK0 * AV_SB + bN0 + 0] = to_tf32(v0.x);
            sB[buf ^ 1][bK0 * AV_SB + bN0 + 1] = to_tf32(v0.y);
            sB[buf ^ 1][bK0 * AV_SB + bN0 + 2] = to_tf32(v0.z);
            sB[buf ^ 1][bK0 * AV_SB + bN0 + 3] = to_tf32(v0.w);
            sB[buf ^ 1][bK1 * AV_SB + bN1 + 0] = to_tf32(v1.x);
            sB[buf ^ 1][bK1 * AV_SB + bN1 + 1] = to_tf32(v1.y);
            sB[buf ^ 1][bK1 * AV_SB + bN1 + 2] = to_tf32(v1.z);
            sB[buf ^ 1][bK1 * AV_SB + bN1 + 3] = to_tf32(v1.w);
        }
        __syncthreads();
        buf ^= 1;
    }

    float cs[4][2];
#pragma unroll
    for (int nt = 0; nt < 4; nt++) {
        cs[nt][0] = 0.f; cs[nt][1] = 0.f;
#pragma unroll
        for (int mt = 0; mt < 4; mt++) {
            cs[nt][0] += elu1(acc[mt][nt][0]) + elu1(acc[mt][nt][2]);
            cs[nt][1] += elu1(acc[mt][nt][1]) + elu1(acc[mt][nt][3]);
        }
    }
#pragma unroll
    for (int o = 4; o <= 16; o <<= 1) {
#pragma unroll
        for (int nt = 0; nt < 4; nt++) {
            cs[nt][0] += __shfl_xor_sync(0xffffffffu, cs[nt][0], o);
            cs[nt][1] += __shfl_xor_sync(0xffffffffu, cs[nt][1], o);
        }
    }
    float* scratch = (float*)sA;
    if (lr4 == 0) {
#pragma unroll
        for (int nt = 0; nt < 4; nt++) {
            int col = wc * 32 + nt * 8 + lc4 * 2;
            scratch[wr * 128 + col]     = cs[nt][0];
            scratch[wr * 128 + col + 1] = cs[nt][1];
        }
    }
    __syncthreads();
    if (tid < 128)
        g_gat[(size_t)b * HID + bn + tid] =
            (scratch[tid] + scratch[128 + tid]) * (1.f / 128.f);
}

// ---------------------------------------------------------------------------
// softmax2 (no-max): sums the 2 t-partials inline, writes tf32 att rows.
// ---------------------------------------------------------------------------
__global__ __launch_bounds__(256) void softmax2_kernel(
    const float* __restrict__ ae_out, const int* __restrict__ adj,
    const float* __restrict__ edge)
{
    __shared__ float st1[64];
    __shared__ float st2[128];

    int tid = threadIdx.x;
    int blk = blockIdx.x;
    int hb = blk & 1;
    int b = blk >> 1;
    int i0 = hb * 64;
    float ae = ae_out[0];
    const int M = Bq * Nn;

    if (tid < 64) {
        int r = b * Nn + i0 + tid;
        st1[tid] = g_t1p[r] + g_t1p[M + r];
    } else if (tid < 192) {
        int r = b * Nn + (tid - 64);
        st2[tid - 64] = g_t2p[r] + g_t2p[M + r];
    }
    __syncthreads();

    int warp = tid >> 5, lane = tid & 31;
    for (int i = warp; i < 64; i += 8) {
        int row = i0 + i;
        float4 ef = ((const float4*)(edge + ((size_t)b * Nn + row) * Nn))[lane];
        int4  av  = ((const int4*)(adj  + ((size_t)b * Nn + row) * Nn))[lane];
        float si = st1[i];
        int j0 = lane * 4;
        float v0 = si + st2[j0 + 0] + ef.x * ae; v0 = v0 >= 0.f ? v0 : 0.2f * v0; v0 = av.x > 0 ? v0 : -9e15f;
        float v1 = si + st2[j0 + 1] + ef.y * ae; v1 = v1 >= 0.f ? v1 : 0.2f * v1; v1 = av.y > 0 ? v1 : -9e15f;
        float v2 = si + st2[j0 + 2] + ef.z * ae; v2 = v2 >= 0.f ? v2 : 0.2f * v2; v2 = av.z > 0 ? v2 : -9e15f;
        float v3 = si + st2[j0 + 3] + ef.w * ae; v3 = v3 >= 0.f ? v3 : 0.2f * v3; v3 = av.w > 0 ? v3 : -9e15f;
        float e0 = __expf(v0), e1 = __expf(v1), e2 = __expf(v2), e3 = __expf(v3);
        float s = e0 + e1 + e2 + e3;
#pragma unroll
        for (int o = 16; o; o >>= 1) s += __shfl_xor_sync(0xffffffffu, s, o);
        float inv = 1.f / s;
        uint4 o4;
        o4.x = to_tf32(e0 * inv); o4.y = to_tf32(e1 * inv);
        o4.z = to_tf32(e2 * inv); o4.w = to_tf32(e3 * inv);
        *(uint4*)(g_att2 + ((size_t)b * Nn + row) * Nn + j0) = o4;
    }
}

// ---------------------------------------------------------------------------
// Tail fp32 GEMM (exact), with optional concat mode. Validated R15.
// flags: 1 = bias, 2 = relu, 4 = accumulate
// ---------------------------------------------------------------------------
__global__ __launch_bounds__(256) void tail_gemm_kernel(
    const float* __restrict__ A, const float* __restrict__ A2,
    const float* __restrict__ B, const float* __restrict__ B2,
    const float* __restrict__ bias, const float* __restrict__ bias2,
    float* __restrict__ C, int M, int N, int K, int Ksplit, int flags)
{
    __shared__ float As[2][16][64];
    __shared__ float Bs[2][16][64];

    int tid = threadIdx.x;
    int bm = blockIdx.y * 64;
    int bn = blockIdx.x * 64;
    int tx = tid & 15;
    int ty = tid >> 4;

    int aRow = tid >> 2, aK = (tid & 3) * 4;
    int bK = tid >> 4, bN = (tid & 15) * 4;

    u64 acc[4][2];
#pragma unroll
    for (int i = 0; i < 4; i++) { acc[i][0] = 0ull; acc[i][1] = 0ull; }

    const int Ktiles = (K + 15) / 16;
    const float* Arow1 = A + (size_t)(bm + aRow) * Ksplit;
    const float* Arow2 = A2 ? A2 + (size_t)(bm + aRow) * Ksplit : A;

    {
#pragma unroll
        for (int i = 0; i < 4; i++) {
            int k = aK + i;
            float v = 0.f;
            if (k < K) v = (k < Ksplit) ? Arow1[k] : Arow2[k - Ksplit];
            As[0][aK + i][aRow] = v;
        }
        float4 v = make_float4(0.f, 0.f, 0.f, 0.f);
        if (bK < K) {
            v = (bK < Ksplit) ? *(const float4*)(B + (size_t)bK * N + bn + bN)
                              : *(const float4*)(B2 + (size_t)(bK - Ksplit) * N + bn + bN);
        }
        *(float4*)&Bs[0][bK][bN] = v;
    }
    __syncthreads();

    int buf = 0;
    for (int t = 0; t < Ktiles; t++) {
        float ap[4];
        float4 bp = make_float4(0.f, 0.f, 0.f, 0.f);
        bool has_next = (t + 1 < Ktiles);
        if (has_next) {
            int k0 = (t + 1) * 16;
#pragma unroll
            for (int i = 0; i < 4; i++) {
                int k = k0 + aK + i;
                float v = 0.f;
                if (k < K) v = (k < Ksplit) ? Arow1[k] : Arow2[k - Ksplit];
                ap[i] = v;
            }
            int k = k0 + bK;
            if (k < K) {
                bp = (k < Ksplit) ? *(const float4*)(B + (size_t)k * N + bn + bN)
                                  : *(const float4*)(B2 + (size_t)(k - Ksplit) * N + bn + bN);
            }
        }

#pragma unroll
        for (int kk = 0; kk < 16; kk++) {
            u64 b0 = *(const u64*)&Bs[buf][kk][tx * 4];
            u64 b1 = *(const u64*)&Bs[buf][kk][tx * 4 + 2];
            float a0 = As[buf][kk][ty * 4];
            float a1 = As[buf][kk][ty * 4 + 1];
            float a2 = As[buf][kk][ty * 4 + 2];
            float a3 = As[buf][kk][ty * 4 + 3];
            u64 d0 = dup2(a0), d1 = dup2(a1), d2 = dup2(a2), d3 = dup2(a3);
            fma2(acc[0][0], d0, b0); fma2(acc[0][1], d0, b1);
            fma2(acc[1][0], d1, b0); fma2(acc[1][1], d1, b1);
            fma2(acc[2][0], d2, b0); fma2(acc[2][1], d2, b1);
            fma2(acc[3][0], d3, b0); fma2(acc[3][1], d3, b1);
        }

        if (has_next) {
#pragma unroll
            for (int i = 0; i < 4; i++) As[buf ^ 1][aK + i][aRow] = ap[i];
            *(float4*)&Bs[buf ^ 1][bK][bN] = bp;
        }
        __syncthreads();
        buf ^= 1;
    }

#pragma unroll
    for (int i = 0; i < 4; i++) {
        int row = bm + ty * 4 + i;
#pragma unroll
        for (int j = 0; j < 2; j++) {
            int col = bn + tx * 4 + j * 2;
            float2 v = upk2(acc[i][j]);
            if (flags & 4) {
                float2 c = *(const float2*)&C[(size_t)row * N + col];
                v.x += c.x; v.y += c.y;
            }
            if (flags & 1) { v.x += bias[col]; v.y += bias[col + 1]; }
            if (bias2)     { v.x += bias2[col]; v.y += bias2[col + 1]; }
            if (flags & 2) { v.x = fmaxf(v.x, 0.f); v.y = fmaxf(v.y, 0.f); }
            *(float2*)&C[(size_t)row * N + col] = v;
        }
    }
}

// ---------------------------------------------------------------------------
__global__ void wcat_kernel(const float* __restrict__ W_heads)
{
    int idx = blockIdx.x * blockDim.x + threadIdx.x;
    if (idx >= NHEADS * F_IN * NHID) return;
    int h = idx / (F_IN * NHID);
    int rem = idx - h * (F_IN * NHID);
    int f = rem / NHID;
    int d = rem - f * NHID;
    g_Wcat[f * HID + h * NHID + d] = W_heads[idx];
}

// ---------------------------------------------------------------------------
// attn1 (tf32 mma, 32-col B-chunks, no-max softmax, chunk-0 prefetch).
// ---------------------------------------------------------------------------
#define WCH_STR 40
#define AT_STR 132

__global__ __launch_bounds__(256) void attn1_kernel(
    const float* __restrict__ ae_heads, const int* __restrict__ adj,
    const float* __restrict__ edge)
{
    extern __shared__ u32 smu[];
    u32* sWh  = smu;                        // 128*40
    u32* sAtt = smu + 128 * WCH_STR;        // 64*132
    float* ss1 = (float*)(smu + 128 * WCH_STR + 64 * AT_STR);  // 64
    float* ss2 = ss1 + 64;                                      // 128

    int tid = threadIdx.x;
    int blk = blockIdx.x;
    int hb = blk & 1;
    int bh = blk >> 1;
    int hh = bh & 7, b = bh >> 3;
    int i0 = hb * 64;
    float ae = ae_heads[hh];

    const float* whp = g_Wh + (size_t)b * Nn * HID + hh * NHID;

    for (int i = tid; i < 128 * 8; i += 256) {
        int r = i >> 3, c = (i & 7) * 4;
        float4 v = *(const float4*)(whp + (size_t)r * HID + c);
        uint4 t;
        t.x = to_tf32(v.x); t.y = to_tf32(v.y);
        t.z = to_tf32(v.z); t.w = to_tf32(v.w);
        *(uint4*)&sWh[r * WCH_STR + c] = t;
    }
    if (tid < 64)  ss1[tid] = g_s1[bh * Nn + i0 + tid];
    if (tid < 128) ss2[tid] = g_s2[bh * Nn + tid];
    __syncthreads();

    int warp = tid >> 5, lane = tid & 31;
    for (int i = warp; i < 64; i += 8) {
        int row = i0 + i;
        float4 ef = ((const float4*)(edge + ((size_t)b * Nn + row) * Nn))[lane];
        int4  av  = ((const int4*)(adj  + ((size_t)b * Nn + row) * Nn))[lane];
        float si = ss1[i];
        int j0 = lane * 4;
        float v0 = si + ss2[j0 + 0] + ef.x * ae; v0 = v0 >= 0.f ? v0 : 0.2f * v0; v0 = av.x > 0 ? v0 : -9e15f;
        float v1 = si + ss2[j0 + 1] + ef.y * ae; v1 = v1 >= 0.f ? v1 : 0.2f * v1; v1 = av.y > 0 ? v1 : -9e15f;
        float v2 = si + ss2[j0 + 2] + ef.z * ae; v2 = v2 >= 0.f ? v2 : 0.2f * v2; v2 = av.z > 0 ? v2 : -9e15f;
        float v3 = si + ss2[j0 + 3] + ef.w * ae; v3 = v3 >= 0.f ? v3 : 0.2f * v3; v3 = av.w > 0 ? v3 : -9e15f;
        float e0 = __expf(v0), e1 = __expf(v1), e2 = __expf(v2), e3 = __expf(v3);
        float s = e0 + e1 + e2 + e3;
#pragma unroll
        for (int o = 16; o; o >>= 1) s += __shfl_xor_sync(0xffffffffu, s, o);
        float inv = 1.f / s;
        uint4 o4;
        o4.x = to_tf32(e0 * inv); o4.y = to_tf32(e1 * inv);
        o4.z = to_tf32(e2 * inv); o4.w = to_tf32(e3 * inv);
        *(uint4*)&sAtt[i * AT_STR + lane * 4] = o4;
    }
    __syncthreads();

    int wr = warp >> 2, wc = warp & 3;
    int lr4 = lane >> 2, lc4 = lane & 3;

#pragma unroll
    for (int ch = 0; ch < 2; ch++) {
        if (ch == 1) {
            __syncthreads();
            for (int i = tid; i < 128 * 8; i += 256) {
                int r = i >> 3, c = (i & 7) * 4;
                float4 v = *(const float4*)(whp + (size_t)r * HID + 32 + c);
                uint4 t;
                t.x = to_tf32(v.x); t.y = to_tf32(v.y);
                t.z = to_tf32(v.z); t.w = to_tf32(v.w);
                *(uint4*)&sWh[r * WCH_STR + c] = t;
            }
            __syncthreads();
        }

        float acc[2][4];
#pragma unroll
        for (int mt = 0; mt < 2; mt++)
#pragma unroll
            for (int i = 0; i < 4; i++) acc[mt][i] = 0.f;

#pragma unroll
        for (int kk = 0; kk < 128; kk += 8) {
            u32 afr[2][4], bfr[2];
#pragma unroll
            for (int mt = 0; mt < 2; mt++) {
                int r0 = wr * 32 + mt * 16 + lr4;
                int c0 = kk + lc4;
                afr[mt][0] = sAtt[r0 * AT_STR + c0];
                afr[mt][1] = sAtt[(r0 + 8) * AT_STR + c0];
                afr[mt][2] = sAtt[r0 * AT_STR + c0 + 4];
                afr[mt][3] = sAtt[(r0 + 8) * AT_STR + c0 + 4];
            }
            {
                int col = wc * 8 + lr4;
                bfr[0] = sWh[(kk + lc4) * WCH_STR + col];
                bfr[1] = sWh[(kk + lc4 + 4) * WCH_STR + col];
            }
#pragma unroll
            for (int mt = 0; mt < 2; mt++)
                mma_tf32(acc[mt], afr[mt], bfr);
        }

#pragma unroll
        for (int mt = 0; mt < 2; mt++) {
            int col = ch * 32 + wc * 8 + lc4 * 2;
#pragma unroll
            for (int half = 0; half < 2; half++) {
                int i = i0 + wr * 32 + mt * 16 + lr4 + half * 8;
                float2 v;
                v.x = elu1(acc[mt][half * 2]);
                v.y = elu1(acc[mt][half * 2 + 1]);
                *(float2*)(g_x + ((size_t)b * Nn + i) * HID + hh * NHID + col) = v;
            }
        }
    }
}

// ---------------------------------------------------------------------------
// final: warp per (b,t): coalesced lane-strided dot-512 + reduce.
// ---------------------------------------------------------------------------
__global__ __launch_bounds__(256) void final_kernel(
    const float* __restrict__ X, const float* __restrict__ W,
    const float* __restrict__ bias, float* __restrict__ out)
{
    int gw = (blockIdx.x * blockDim.x + threadIdx.x) >> 5;
    int lane = threadIdx.x & 31;
    if (gw >= Bq * TASKS) return;
    int b = gw / TASKS, t = gw - b * TASKS;
    const float* x = X + (size_t)b * HID;
    float s = 0.f;
#pragma unroll
    for (int i = 0; i < 16; i++) {
        int d = lane + i * 32;
        s += x[d] * W[d * TASKS + t];
    }
#pragma unroll
    for (int o = 16; o; o >>= 1) s += __shfl_xor_sync(0xffffffffu, s, o);
    if (lane == 0) out[gw] = s + bias[t];
}

// ---------------------------------------------------------------------------
extern "C" void kernel_launch(void* const* d_in, const int* in_sizes, int n_in,
                              void* d_out, int out_size)
{
    const float* h        = (const float*)d_in[0];
    const int*   adj      = (const int*)d_in[1];
    const float* edge     = (const float*)d_in[2];
    const float* fp       = (const float*)d_in[3];
    const float* W_heads  = (const float*)d_in[4];
    const float* a1_heads = (const float*)d_in[5];
    const float* a2_heads = (const float*)d_in[6];
    const float* ae_heads = (const float*)d_in[7];
    const float* W_out    = (const float*)d_in[8];
    const float* a1_out   = (const float*)d_in[9];
    const float* a2_out   = (const float*)d_in[10];
    const float* ae_out   = (const float*)d_in[11];
    const float* fc1_w    = (const float*)d_in[12];
    const float* fc1_b    = (const float*)d_in[13];
    const float* fc2_w    = (const float*)d_in[14];
    const float* fc2_b    = (const float*)d_in[15];
    const float* q_w      = (const float*)d_in[16];
    const float* q_b      = (const float*)d_in[17];
    // k_w (18), k_b (19) unused: softmax over size-1 axis == 1 -> fused = q+v
    const float* v_w      = (const float*)d_in[20];
    const float* v_b      = (const float*)d_in[21];
    const float* o_w      = (const float*)d_in[22];
    const float* o_b      = (const float*)d_in[23];
    const float* ffn1_w   = (const float*)d_in[24];
    const float* ffn1_b   = (const float*)d_in[25];
    const float* ffn2_w   = (const float*)d_in[26];
    const float* ffn2_b   = (const float*)d_in[27];
    float* out = (float*)d_out;

    float *Wh, *x, *gat, *fpnh, *fpn, *buf1, *buf2, *Wx, *Wcat;
    float *s1p, *s2p, *t1p, *t2p;
    cudaGetSymbolAddress((void**)&Wh, g_Wh);
    cudaGetSymbolAddress((void**)&x, g_x);
    cudaGetSymbolAddress((void**)&Wx, g_Wx);
    cudaGetSymbolAddress((void**)&gat, g_gat);
    cudaGetSymbolAddress((void**)&fpnh, g_fpnh);
    cudaGetSymbolAddress((void**)&fpn, g_fpn);
    cudaGetSymbolAddress((void**)&buf1, g_buf1);
    cudaGetSymbolAddress((void**)&buf2, g_buf2);
    cudaGetSymbolAddress((void**)&Wcat, g_Wcat);
    cudaGetSymbolAddress((void**)&s1p, g_s1);
    cudaGetSymbolAddress((void**)&s2p, g_s2);
    cudaGetSymbolAddress((void**)&t1p, g_t1p);
    cudaGetSymbolAddress((void**)&t2p, g_t2p);

    const int ATT1_SMEM = (128 * WCH_STR + 64 * AT_STR + 192) * 4;   // 55040
    cudaFuncSetAttribute(attn1_kernel, cudaFuncAttributeMaxDynamicSharedMemorySize, ATT1_SMEM);
    cudaFuncSetAttribute(sgemm_tc_kernel, cudaFuncAttributeMaxDynamicSharedMemorySize, SGEMM_SMEM);

    const int M1 = Bq * Nn;  // 65536

    // 1. Wcat transpose
    wcat_kernel<<<(NHEADS * F_IN * NHID + 255) / 256, 256>>>(W_heads);

    // 2. Wh = h @ Wcat (tf32, 128x256 tiles) + fused s1/s2 epilogue
    {
        dim3 grid(HID / 256, M1 / 128);
        sgemm_tc_kernel<<<grid, 256, SGEMM_SMEM>>>(h, Wcat, nullptr, Wh, M1, HID, F_IN, 0,
                                                   1, a1_heads, a2_heads, s1p, s2p);
    }

    // 3. attn1
    attn1_kernel<<<Bq * NHEADS * 2, 256, ATT1_SMEM>>>(ae_heads, adj, edge);

    // 4. Wx = x @ W_out (tf32, 128x256 tiles) + fused t1/t2 partials (2 tiles)
    {
        dim3 grid(HID / 256, M1 / 128);
        sgemm_tc_kernel<<<grid, 256, SGEMM_SMEM>>>(x, W_out, nullptr, Wx, M1, HID, HID, 0,
                                                   2, a1_out, a2_out, t1p, t2p);
    }

    // 5. attn2 split (softmax2 sums 2 t-partials), then batched AV GEMM
    softmax2_kernel<<<Bq * 2, 256>>>(ae_out, adj, edge);
    {
        dim3 grid(HID / 128, Bq);
        av2_kernel<<<grid, 256>>>();
    }

    // 6. FPN (exact fp32 tails)
    {
        dim3 grid(HID / 64, Bq / 64);
        tail_gemm_kernel<<<grid, 256>>>(fp, nullptr, fc1_w, nullptr, fc1_b, nullptr,
                                        fpnh, Bq, HID, FP_DIM, FP_DIM, 1 | 2);
        tail_gemm_kernel<<<grid, 256>>>(fpnh, nullptr, fc2_w, nullptr, fc2_b, nullptr,
                                        fpn, Bq, HID, HID, HID, 1);
    }

    // 7. fusion + FFN (concat q+v GEMM, then o, ffn1)
    {
        dim3 grid(HID / 64, Bq / 64);
        tail_gemm_kernel<<<grid, 256>>>(gat, fpn, q_w, v_w, q_b, v_b,
                                        buf1, Bq, HID, 2 * HID, HID, 1);
        tail_gemm_kernel<<<grid, 256>>>(buf1, nullptr, o_w, nullptr, o_b, nullptr,
                                        buf2, Bq, HID, HID, HID, 1 | 2);
        tail_gemm_kernel<<<grid, 256>>>(buf2, nullptr, ffn1_w, nullptr, ffn1_b, nullptr,
                                        buf1, Bq, HID, HID, HID, 1 | 2);
    }

    // 8. final projection (warp per output)
    final_kernel<<<(Bq * TASKS * 32 + 255) / 256, 256>>>(buf1, ffn2_w, ffn2_b, out);
}

// round 17
// speedup vs baseline: 1.3068x; 1.0122x over previous
#include <cuda_runtime.h>
#include <cuda_bf16.h>
#include <math.h>

// ---------------------------------------------------------------------------
// FPGNN forward. R17: tf32-typed intermediates (g_Wh, g_x, g_Wx as tf32 u32)
// + preconverted h / Wcat / W_out -> zero CVT in GEMM mainloops.
//  - big GEMMs: tf32 mma, 128x256 tile, fused s/t epilogues, u32 I/O
//  - attn1: tf32 mma, 32-col chunks; reads Wh u32, writes x u32 tf32
//  - attn2: softmax2 -> tf32 att, av2 batched GEMM (u32 B loads)
//  - tails: exact fp32 FFMA2 64x64; q+v concat-GEMM
// ---------------------------------------------------------------------------

#define Bq 512
#define Nn 128
#define F_IN 133
#define NHEADS 8
#define NHID 64
#define HID 512
#define FP_DIM 1489
#define TASKS 12

typedef unsigned long long u64;
typedef unsigned int u32;

__device__ __forceinline__ u64 pack2(float lo, float hi) {
    u64 r; asm("mov.b64 %0, {%1,%2};" : "=l"(r) : "f"(lo), "f"(hi)); return r;
}
__device__ __forceinline__ u64 dup2(float v) { return pack2(v, v); }
__device__ __forceinline__ void fma2(u64& d, u64 a, u64 b) {
    asm("fma.rn.f32x2 %0, %1, %2, %0;" : "+l"(d) : "l"(a), "l"(b));
}
__device__ __forceinline__ float2 upk2(u64 v) {
    float2 r; asm("mov.b64 {%0,%1}, %2;" : "=f"(r.x), "=f"(r.y) : "l"(v)); return r;
}
__device__ __forceinline__ u32 to_tf32(float f) {
    u32 r; asm("cvt.rna.tf32.f32 %0, %1;" : "=r"(r) : "f"(f)); return r;
}
__device__ __forceinline__ void mma_tf32(float* d, const u32* a, const u32* b) {
    asm volatile(
        "mma.sync.aligned.m16n8k8.row.col.f32.tf32.tf32.f32 "
        "{%0,%1,%2,%3}, {%4,%5,%6,%7}, {%8,%9}, {%0,%1,%2,%3};\n"
        : "+f"(d[0]), "+f"(d[1]), "+f"(d[2]), "+f"(d[3])
        : "r"(a[0]), "r"(a[1]), "r"(a[2]), "r"(a[3]), "r"(b[0]), "r"(b[1]));
}
__device__ __forceinline__ float elu1(float v) {
    return v > 0.f ? v : (__expf(v) - 1.f);
}

// ---- scratch (device globals; no allocation allowed) ----
__device__ u32   g_hc[(size_t)Bq * Nn * F_IN];     // h as tf32
__device__ u32   g_Wcat[F_IN * HID];               // tf32
__device__ u32   g_Wo[HID * HID];                  // W_out as tf32
__device__ u32   g_Wh[(size_t)Bq * Nn * HID];      // tf32
__device__ float g_s1[Bq * NHEADS * Nn];
__device__ float g_s2[Bq * NHEADS * Nn];
__device__ u32   g_x[(size_t)Bq * Nn * HID];       // tf32
__device__ u32   g_Wx[(size_t)Bq * Nn * HID];      // tf32
__device__ float g_t1p[2 * Bq * Nn];
__device__ float g_t2p[2 * Bq * Nn];
__device__ u32   g_att2[(size_t)Bq * Nn * Nn];     // tf32 att
__device__ float g_gat[Bq * HID];
__device__ float g_fpnh[Bq * HID];
__device__ float g_fpn[Bq * HID];
__device__ float g_buf1[Bq * HID];
__device__ float g_buf2[Bq * HID];

// ---------------------------------------------------------------------------
// conv_tf32: vectorized fp32 -> tf32 stream (n % 4 == 0).
// ---------------------------------------------------------------------------
__global__ void conv_tf32_kernel(const float* __restrict__ src,
                                 u32* __restrict__ dst, int n4)
{
    int i = blockIdx.x * blockDim.x + threadIdx.x;
    if (i >= n4) return;
    float4 v = *(const float4*)(src + (size_t)i * 4);
    uint4 t;
    t.x = to_tf32(v.x); t.y = to_tf32(v.y);
    t.z = to_tf32(v.z); t.w = to_tf32(v.w);
    *(uint4*)(dst + (size_t)i * 4) = t;
}

// ---------------------------------------------------------------------------
// wcat: W_heads [8,133,64] -> g_Wcat [133, 512] tf32
// ---------------------------------------------------------------------------
__global__ void wcat_kernel(const float* __restrict__ W_heads)
{
    int idx = blockIdx.x * blockDim.x + threadIdx.x;
    if (idx >= NHEADS * F_IN * NHID) return;
    int h = idx / (F_IN * NHID);
    int rem = idx - h * (F_IN * NHID);
    int f = rem / NHID;
    int d = rem - f * NHID;
    g_Wcat[f * HID + h * NHID + d] = to_tf32(W_heads[idx]);
}

// ---------------------------------------------------------------------------
// Big tf32 GEMM, all-u32 I/O: C(tf32) = A(tf32)[M,K] @ B(tf32)[K,N].
// BM=128, BN=256, BK=16; 8 warps (2x4), warp tile 64x64. Zero CVT mainloop.
// smode: 1 = per-head (64-col) dots; 2 = per-CTA 256-col partials.
// ---------------------------------------------------------------------------
#define SA_STRIDE 20
#define SB_STRIDE 264
#define SGEMM_SMEM ((2 * 128 * SA_STRIDE + 2 * 16 * SB_STRIDE) * 4)

__global__ __launch_bounds__(256) void sgemm_tc_kernel(
    const u32* __restrict__ A, const u32* __restrict__ B,
    u32* __restrict__ C, int M, int N, int K,
    int smode, const float* __restrict__ av1, const float* __restrict__ av2,
    float* __restrict__ so1, float* __restrict__ so2)
{
    extern __shared__ u32 dsm[];
    u32* sAb = dsm;
    u32* sBb = dsm + 2 * 128 * SA_STRIDE;

    int tid = threadIdx.x;
    int warp = tid >> 5, lane = tid & 31;
    int wr = warp >> 2, wc = warp & 3;
    int bm = blockIdx.y * 128;
    int bn = blockIdx.x * 256;
    int lr4 = lane >> 2, lc4 = lane & 3;

    float acc[4][8][4];
#pragma unroll
    for (int mt = 0; mt < 4; mt++)
#pragma unroll
        for (int nt = 0; nt < 8; nt++)
#pragma unroll
            for (int i = 0; i < 4; i++) acc[mt][nt][i] = 0.f;

    const int Ktiles = (K + 15) / 16;
    int aRow0 = tid >> 2,         aK0 = (tid & 3) * 4;
    int aRow1 = (tid + 256) >> 2, aK1 = ((tid + 256) & 3) * 4;
    int bK = tid >> 4;
    int bC = (tid & 15) * 4;

    u32 ar[2][4];
    uint4 br[4];

    {
#pragma unroll
        for (int i = 0; i < 4; i++) {
            int k = aK0 + i;
            ar[0][i] = (k < K) ? A[(size_t)(bm + aRow0) * K + k] : 0u;
            k = aK1 + i;
            ar[1][i] = (k < K) ? A[(size_t)(bm + aRow1) * K + k] : 0u;
        }
#pragma unroll
        for (int q = 0; q < 4; q++) {
            if (bK < K) br[q] = *(const uint4*)(B + (size_t)bK * N + bn + q * 64 + bC);
            else br[q] = make_uint4(0u, 0u, 0u, 0u);
        }
    }
#pragma unroll
    for (int i = 0; i < 4; i++) {
        sAb[aRow0 * SA_STRIDE + aK0 + i] = ar[0][i];
        sAb[aRow1 * SA_STRIDE + aK1 + i] = ar[1][i];
    }
#pragma unroll
    for (int q = 0; q < 4; q++)
        *(uint4*)&sBb[bK * SB_STRIDE + q * 64 + bC] = br[q];
    __syncthreads();

    int buf = 0;
    for (int t = 0; t < Ktiles; t++) {
        bool has_next = (t + 1 < Ktiles);
        if (has_next) {
            int k0 = (t + 1) * 16;
#pragma unroll
            for (int i = 0; i < 4; i++) {
                int k = k0 + aK0 + i;
                ar[0][i] = (k < K) ? A[(size_t)(bm + aRow0) * K + k] : 0u;
                k = k0 + aK1 + i;
                ar[1][i] = (k < K) ? A[(size_t)(bm + aRow1) * K + k] : 0u;
            }
            int k = k0 + bK;
#pragma unroll
            for (int q = 0; q < 4; q++) {
                if (k < K) br[q] = *(const uint4*)(B + (size_t)k * N + bn + q * 64 + bC);
                else br[q] = make_uint4(0u, 0u, 0u, 0u);
            }
        }

        const u32* cA = sAb + buf * 128 * SA_STRIDE;
        const u32* cB = sBb + buf * 16 * SB_STRIDE;
#pragma unroll
        for (int kk = 0; kk < 16; kk += 8) {
            u32 afr[4][4], bfr[8][2];
#pragma unroll
            for (int mt = 0; mt < 4; mt++) {
                int r0 = wr * 64 + mt * 16 + lr4;
                int c0 = kk + lc4;
                afr[mt][0] = cA[r0 * SA_STRIDE + c0];
                afr[mt][1] = cA[(r0 + 8) * SA_STRIDE + c0];
                afr[mt][2] = cA[r0 * SA_STRIDE + c0 + 4];
                afr[mt][3] = cA[(r0 + 8) * SA_STRIDE + c0 + 4];
            }
#pragma unroll
            for (int nt = 0; nt < 8; nt++) {
                int col = wc * 64 + nt * 8 + lr4;
                bfr[nt][0] = cB[(kk + lc4) * SB_STRIDE + col];
                bfr[nt][1] = cB[(kk + lc4 + 4) * SB_STRIDE + col];
            }
#pragma unroll
            for (int mt = 0; mt < 4; mt++)
#pragma unroll
                for (int nt = 0; nt < 8; nt++)
                    mma_tf32(acc[mt][nt], afr[mt], bfr[nt]);
        }

        if (has_next) {
            u32* nA = sAb + (buf ^ 1) * 128 * SA_STRIDE;
            u32* nB = sBb + (buf ^ 1) * 16 * SB_STRIDE;
#pragma unroll
            for (int i = 0; i < 4; i++) {
                nA[aRow0 * SA_STRIDE + aK0 + i] = ar[0][i];
                nA[aRow1 * SA_STRIDE + aK1 + i] = ar[1][i];
            }
#pragma unroll
            for (int q = 0; q < 4; q++)
                *(uint4*)&sBb[(buf ^ 1) * 16 * SB_STRIDE + bK * SB_STRIDE + q * 64 + bC] = br[q];
        }
        __syncthreads();
        buf ^= 1;
    }

    // ---- C write (tf32) ----
#pragma unroll
    for (int mt = 0; mt < 4; mt++) {
#pragma unroll
        for (int nt = 0; nt < 8; nt++) {
            int col = bn + wc * 64 + nt * 8 + lc4 * 2;
#pragma unroll
            for (int half = 0; half < 2; half++) {
                int row = bm + wr * 64 + mt * 16 + lr4 + half * 8;
                uint2 v;
                v.x = to_tf32(acc[mt][nt][half * 2]);
                v.y = to_tf32(acc[mt][nt][half * 2 + 1]);
                *(uint2*)&C[(size_t)row * N + col] = v;
            }
        }
    }

    // ---- fused score epilogue (fp32 acc) ----
    if (smode == 1) {
        int head = (bn >> 6) + wc;
        float a1c[8][2], a2c[8][2];
#pragma unroll
        for (int nt = 0; nt < 8; nt++) {
            int col = bn + wc * 64 + nt * 8 + lc4 * 2;
            a1c[nt][0] = av1[col]; a1c[nt][1] = av1[col + 1];
            a2c[nt][0] = av2[col]; a2c[nt][1] = av2[col + 1];
        }
#pragma unroll
        for (int mt = 0; mt < 4; mt++) {
#pragma unroll
            for (int half = 0; half < 2; half++) {
                float p1 = 0.f, p2 = 0.f;
#pragma unroll
                for (int nt = 0; nt < 8; nt++) {
                    p1 += acc[mt][nt][half*2] * a1c[nt][0] + acc[mt][nt][half*2+1] * a1c[nt][1];
                    p2 += acc[mt][nt][half*2] * a2c[nt][0] + acc[mt][nt][half*2+1] * a2c[nt][1];
                }
                p1 += __shfl_xor_sync(0xffffffffu, p1, 1);
                p1 += __shfl_xor_sync(0xffffffffu, p1, 2);
                p2 += __shfl_xor_sync(0xffffffffu, p2, 1);
                p2 += __shfl_xor_sync(0xffffffffu, p2, 2);
                if (lc4 == 0) {
                    int rg = bm + wr * 64 + mt * 16 + lr4 + half * 8;
                    int bb = rg >> 7, nn2 = rg & 127;
                    size_t o = ((size_t)bb * NHEADS + head) * Nn + nn2;
                    so1[o] = p1;
                    so2[o] = p2;
                }
            }
        }
    } else if (smode == 2) {
        float a1c[8][2], a2c[8][2];
#pragma unroll
        for (int nt = 0; nt < 8; nt++) {
            int col = bn + wc * 64 + nt * 8 + lc4 * 2;
            a1c[nt][0] = av1[col]; a1c[nt][1] = av1[col + 1];
            a2c[nt][0] = av2[col]; a2c[nt][1] = av2[col + 1];
        }
        float* sc1 = (float*)dsm;
        float* sc2 = sc1 + 512;
#pragma unroll
        for (int mt = 0; mt < 4; mt++) {
#pragma unroll
            for (int half = 0; half < 2; half++) {
                float p1 = 0.f, p2 = 0.f;
#pragma unroll
                for (int nt = 0; nt < 8; nt++) {
                    p1 += acc[mt][nt][half*2] * a1c[nt][0] + acc[mt][nt][half*2+1] * a1c[nt][1];
                    p2 += acc[mt][nt][half*2] * a2c[nt][0] + acc[mt][nt][half*2+1] * a2c[nt][1];
                }
                p1 += __shfl_xor_sync(0xffffffffu, p1, 1);
                p1 += __shfl_xor_sync(0xffffffffu, p1, 2);
                p2 += __shfl_xor_sync(0xffffffffu, p2, 1);
                p2 += __shfl_xor_sync(0xffffffffu, p2, 2);
                if (lc4 == 0) {
                    int rl = wr * 64 + mt * 16 + lr4 + half * 8;
                    sc1[wc * 128 + rl] = p1;
                    sc2[wc * 128 + rl] = p2;
                }
            }
        }
        __syncthreads();
        if (tid < 128) {
            float v1 = sc1[tid] + sc1[128 + tid] + sc1[256 + tid] + sc1[384 + tid];
            float v2 = sc2[tid] + sc2[128 + tid] + sc2[256 + tid] + sc2[384 + tid];
            so1[(size_t)blockIdx.x * M + bm + tid] = v1;
            so2[(size_t)blockIdx.x * M + bm + tid] = v2;
        }
    }
}

// ---------------------------------------------------------------------------
// av2: batched tf32 GEMM D[b] = att2[b] @ Wx[b][:, bn..+127] (both u32 tf32),
// fused ELU + column-mean -> g_gat.
// ---------------------------------------------------------------------------
#define AV_SA 20
#define AV_SB 136

__global__ __launch_bounds__(256) void av2_kernel()
{
    __shared__ u32 sA[2][128 * AV_SA];
    __shared__ u32 sB[2][16 * AV_SB];

    int tid = threadIdx.x;
    int warp = tid >> 5, lane = tid & 31;
    int wr = warp >> 2, wc = warp & 3;
    int b = blockIdx.y;
    int bn = blockIdx.x * 128;
    int lr4 = lane >> 2, lc4 = lane & 3;

    const u32* Ab = g_att2 + (size_t)b * Nn * Nn;
    const u32* Bb = g_Wx + (size_t)b * Nn * HID;

    float acc[4][4][4];
#pragma unroll
    for (int mt = 0; mt < 4; mt++)
#pragma unroll
        for (int nt = 0; nt < 4; nt++)
#pragma unroll
            for (int i = 0; i < 4; i++) acc[mt][nt][i] = 0.f;

    int aRow0 = tid >> 2,         aK0 = (tid & 3) * 4;
    int aRow1 = (tid + 256) >> 2, aK1 = ((tid + 256) & 3) * 4;
    int bK0 = tid >> 5,           bN0 = (tid & 31) * 4;
    int bK1 = (tid + 256) >> 5,   bN1 = ((tid + 256) & 31) * 4;

    {
        *(uint4*)&sA[0][aRow0 * AV_SA + aK0] = *(const uint4*)(Ab + (size_t)aRow0 * Nn + aK0);
        *(uint4*)&sA[0][aRow1 * AV_SA + aK1] = *(const uint4*)(Ab + (size_t)aRow1 * Nn + aK1);
        *(uint4*)&sB[0][bK0 * AV_SB + bN0] = *(const uint4*)(Bb + (size_t)bK0 * HID + bn + bN0);
        *(uint4*)&sB[0][bK1 * AV_SB + bN1] = *(const uint4*)(Bb + (size_t)bK1 * HID + bn + bN1);
    }
    __syncthreads();

    int buf = 0;
    for (int t = 0; t < 8; t++) {
        bool has_next = (t + 1 < 8);
        uint4 an0, an1, bv0, bv1;
        if (has_next) {
            int k0 = (t + 1) * 16;
            an0 = *(const uint4*)(Ab + (size_t)aRow0 * Nn + k0 + aK0);
            an1 = *(const uint4*)(Ab + (size_t)aRow1 * Nn + k0 + aK1);
            bv0 = *(const uint4*)(Bb + (size_t)(k0 + bK0) * HID + bn + bN0);
            bv1 = *(const uint4*)(Bb + (size_t)(k0 + bK1) * HID + bn + bN1);
        }

        const u32* cA = sA[buf];
        const u32* cB = sB[buf];
#pragma unroll
        for (int kk = 0; kk < 16; kk += 8) {
            u32 afr[4][4], bfr[4][2];
#pragma unroll
            for (int mt = 0; mt < 4; mt++) {
                int r0 = wr * 64 + mt * 16 + lr4;
                int c0 = kk + lc4;
                afr[mt][0] = cA[r0 * AV_SA + c0];
                afr[mt][1] = cA[(r0 + 8) * AV_SA + c0];
                afr[mt][2] = cA[r0 * AV_SA + c0 + 4];
                afr[mt][3] = cA[(r0 + 8) * AV_SA + c0 + 4];
            }
#pragma unroll
            for (int nt = 0; nt < 4; nt++) {
                int col = wc * 32 + nt * 8 + lr4;
                bfr[nt][0] = cB[(kk + lc4) * AV_SB + col];
                bfr[nt][1] = cB[(kk + lc4 + 4) * AV_SB + col];
            }
#pragma unroll
            for (int mt = 0; mt < 4; mt++)
#pragma unroll
                for (int nt = 0; nt < 4; nt++)
                    mma_tf32(acc[mt][nt], afr[mt], bfr[nt]);
        }

        if (has_next) {
            *(uint4*)&sA[buf ^ 1][aRow0 * AV_SA + aK0] = an0;
            *(uint4*)&sA[buf ^ 1][aRow1 * AV_SA + aK1] = an1;
            *(uint4*)&sB[buf ^ 1][bK0 * AV_SB + bN0] = bv0;
            *(uint4*)&sB[buf ^ 1][bK1 * AV_SB + bN1] = bv1;
        }
        __syncthreads();
        buf ^= 1;
    }

    float cs[4][2];
#pragma unroll
    for (int nt = 0; nt < 4; nt++) {
        cs[nt][0] = 0.f; cs[nt][1] = 0.f;
#pragma unroll
        for (int mt = 0; mt < 4; mt++) {
            cs[nt][0] += elu1(acc[mt][nt][0]) + elu1(acc[mt][nt][2]);
            cs[nt][1] += elu1(acc[mt][nt][1]) + elu1(acc[mt][nt][3]);
        }
    }
#pragma unroll
    for (int o = 4; o <= 16; o <<= 1) {
#pragma unroll
        for (int nt = 0; nt < 4; nt++) {
            cs[nt][0] += __shfl_xor_sync(0xffffffffu, cs[nt][0], o);
            cs[nt][1] += __shfl_xor_sync(0xffffffffu, cs[nt][1], o);
        }
    }
    float* scratch = (float*)sA;
    if (lr4 == 0) {
#pragma unroll
        for (int nt = 0; nt < 4; nt++) {
            int col = wc * 32 + nt * 8 + lc4 * 2;
            scratch[wr * 128 + col]     = cs[nt][0];
            scratch[wr * 128 + col + 1] = cs[nt][1];
        }
    }
    __syncthreads();
    if (tid < 128)
        g_gat[(size_t)b * HID + bn + tid] =
            (scratch[tid] + scratch[128 + tid]) * (1.f / 128.f);
}

// ---------------------------------------------------------------------------
// softmax2 (no-max): sums 2 t-partials inline, writes tf32 att rows.
// ---------------------------------------------------------------------------
__global__ __launch_bounds__(256) void softmax2_kernel(
    const float* __restrict__ ae_out, const int* __restrict__ adj,
    const float* __restrict__ edge)
{
    __shared__ float st1[64];
    __shared__ float st2[128];

    int tid = threadIdx.x;
    int blk = blockIdx.x;
    int hb = blk & 1;
    int b = blk >> 1;
    int i0 = hb * 64;
    float ae = ae_out[0];
    const int M = Bq * Nn;

    if (tid < 64) {
        int r = b * Nn + i0 + tid;
        st1[tid] = g_t1p[r] + g_t1p[M + r];
    } else if (tid < 192) {
        int r = b * Nn + (tid - 64);
        st2[tid - 64] = g_t2p[r] + g_t2p[M + r];
    }
    __syncthreads();

    int warp = tid >> 5, lane = tid & 31;
    for (int i = warp; i < 64; i += 8) {
        int row = i0 + i;
        float4 ef = ((const float4*)(edge + ((size_t)b * Nn + row) * Nn))[lane];
        int4  av  = ((const int4*)(adj  + ((size_t)b * Nn + row) * Nn))[lane];
        float si = st1[i];
        int j0 = lane * 4;
        float v0 = si + st2[j0 + 0] + ef.x * ae; v0 = v0 >= 0.f ? v0 : 0.2f * v0; v0 = av.x > 0 ? v0 : -9e15f;
        float v1 = si + st2[j0 + 1] + ef.y * ae; v1 = v1 >= 0.f ? v1 : 0.2f * v1; v1 = av.y > 0 ? v1 : -9e15f;
        float v2 = si + st2[j0 + 2] + ef.z * ae; v2 = v2 >= 0.f ? v2 : 0.2f * v2; v2 = av.z > 0 ? v2 : -9e15f;
        float v3 = si + st2[j0 + 3] + ef.w * ae; v3 = v3 >= 0.f ? v3 : 0.2f * v3; v3 = av.w > 0 ? v3 : -9e15f;
        float e0 = __expf(v0), e1 = __expf(v1), e2 = __expf(v2), e3 = __expf(v3);
        float s = e0 + e1 + e2 + e3;
#pragma unroll
        for (int o = 16; o; o >>= 1) s += __shfl_xor_sync(0xffffffffu, s, o);
        float inv = 1.f / s;
        uint4 o4;
        o4.x = to_tf32(e0 * inv); o4.y = to_tf32(e1 * inv);
        o4.z = to_tf32(e2 * inv); o4.w = to_tf32(e3 * inv);
        *(uint4*)(g_att2 + ((size_t)b * Nn + row) * Nn + j0) = o4;
    }
}

// ---------------------------------------------------------------------------
// Tail fp32 GEMM (exact), with optional concat mode. Validated R15.
// flags: 1 = bias, 2 = relu, 4 = accumulate
// ---------------------------------------------------------------------------
__global__ __launch_bounds__(256) void tail_gemm_kernel(
    const float* __restrict__ A, const float* __restrict__ A2,
    const float* __restrict__ B, const float* __restrict__ B2,
    const float* __restrict__ bias, const float* __restrict__ bias2,
    float* __restrict__ C, int M, int N, int K, int Ksplit, int flags)
{
    __shared__ float As[2][16][64];
    __shared__ float Bs[2][16][64];

    int tid = threadIdx.x;
    int bm = blockIdx.y * 64;
    int bn = blockIdx.x * 64;
    int tx = tid & 15;
    int ty = tid >> 4;

    int aRow = tid >> 2, aK = (tid & 3) * 4;
    int bK = tid >> 4, bN = (tid & 15) * 4;

    u64 acc[4][2];
#pragma unroll
    for (int i = 0; i < 4; i++) { acc[i][0] = 0ull; acc[i][1] = 0ull; }

    const int Ktiles = (K + 15) / 16;
    const float* Arow1 = A + (size_t)(bm + aRow) * Ksplit;
    const float* Arow2 = A2 ? A2 + (size_t)(bm + aRow) * Ksplit : A;

    {
#pragma unroll
        for (int i = 0; i < 4; i++) {
            int k = aK + i;
            float v = 0.f;
            if (k < K) v = (k < Ksplit) ? Arow1[k] : Arow2[k - Ksplit];
            As[0][aK + i][aRow] = v;
        }
        float4 v = make_float4(0.f, 0.f, 0.f, 0.f);
        if (bK < K) {
            v = (bK < Ksplit) ? *(const float4*)(B + (size_t)bK * N + bn + bN)
                              : *(const float4*)(B2 + (size_t)(bK - Ksplit) * N + bn + bN);
        }
        *(float4*)&Bs[0][bK][bN] = v;
    }
    __syncthreads();

    int buf = 0;
    for (int t = 0; t < Ktiles; t++) {
        float ap[4];
        float4 bp = make_float4(0.f, 0.f, 0.f, 0.f);
        bool has_next = (t + 1 < Ktiles);
        if (has_next) {
            int k0 = (t + 1) * 16;
#pragma unroll
            for (int i = 0; i < 4; i++) {
                int k = k0 + aK + i;
                float v = 0.f;
                if (k < K) v = (k < Ksplit) ? Arow1[k] : Arow2[k - Ksplit];
                ap[i] = v;
            }
            int k = k0 + bK;
            if (k < K) {
                bp = (k < Ksplit) ? *(const float4*)(B + (size_t)k * N + bn + bN)
                                  : *(const float4*)(B2 + (size_t)(k - Ksplit) * N + bn + bN);
            }
        }

#pragma unroll
        for (int kk = 0; kk < 16; kk++) {
            u64 b0 = *(const u64*)&Bs[buf][kk][tx * 4];
            u64 b1 = *(const u64*)&Bs[buf][kk][tx * 4 + 2];
            float a0 = As[buf][kk][ty * 4];
            float a1 = As[buf][kk][ty * 4 + 1];
            float a2 = As[buf][kk][ty * 4 + 2];
            float a3 = As[buf][kk][ty * 4 + 3];
            u64 d0 = dup2(a0), d1 = dup2(a1), d2 = dup2(a2), d3 = dup2(a3);
            fma2(acc[0][0], d0, b0); fma2(acc[0][1], d0, b1);
            fma2(acc[1][0], d1, b0); fma2(acc[1][1], d1, b1);
            fma2(acc[2][0], d2, b0); fma2(acc[2][1], d2, b1);
            fma2(acc[3][0], d3, b0); fma2(acc[3][1], d3, b1);
        }

        if (has_next) {
#pragma unroll
            for (int i = 0; i < 4; i++) As[buf ^ 1][aK + i][aRow] = ap[i];
            *(float4*)&Bs[buf ^ 1][bK][bN] = bp;
        }
        __syncthreads();
        buf ^= 1;
    }

#pragma unroll
    for (int i = 0; i < 4; i++) {
        int row = bm + ty * 4 + i;
#pragma unroll
        for (int j = 0; j < 2; j++) {
            int col = bn + tx * 4 + j * 2;
            float2 v = upk2(acc[i][j]);
            if (flags & 4) {
                float2 c = *(const float2*)&C[(size_t)row * N + col];
                v.x += c.x; v.y += c.y;
            }
            if (flags & 1) { v.x += bias[col]; v.y += bias[col + 1]; }
            if (bias2)     { v.x += bias2[col]; v.y += bias2[col + 1]; }
            if (flags & 2) { v.x = fmaxf(v.x, 0.f); v.y = fmaxf(v.y, 0.f); }
            *(float2*)&C[(size_t)row * N + col] = v;
        }
    }
}

// ---------------------------------------------------------------------------
// attn1 (tf32 mma, 32-col B-chunks, no-max softmax). Reads g_Wh u32,
// writes g_x u32 (tf32). Zero CVT on Wh loads.
// ---------------------------------------------------------------------------
#define WCH_STR 40
#define AT_STR 132

__global__ __launch_bounds__(256) void attn1_kernel(
    const float* __restrict__ ae_heads, const int* __restrict__ adj,
    const float* __restrict__ edge)
{
    extern __shared__ u32 smu[];
    u32* sWh  = smu;                        // 128*40
    u32* sAtt = smu + 128 * WCH_STR;        // 64*132
    float* ss1 = (float*)(smu + 128 * WCH_STR + 64 * AT_STR);  // 64
    float* ss2 = ss1 + 64;                                      // 128

    int tid = threadIdx.x;
    int blk = blockIdx.x;
    int hb = blk & 1;
    int bh = blk >> 1;
    int hh = bh & 7, b = bh >> 3;
    int i0 = hb * 64;
    float ae = ae_heads[hh];

    const u32* whp = g_Wh + (size_t)b * Nn * HID + hh * NHID;

    for (int i = tid; i < 128 * 8; i += 256) {
        int r = i >> 3, c = (i & 7) * 4;
        *(uint4*)&sWh[r * WCH_STR + c] = *(const uint4*)(whp + (size_t)r * HID + c);
    }
    if (tid < 64)  ss1[tid] = g_s1[bh * Nn + i0 + tid];
    if (tid < 128) ss2[tid] = g_s2[bh * Nn + tid];
    __syncthreads();

    int warp = tid >> 5, lane = tid & 31;
    for (int i = warp; i < 64; i += 8) {
        int row = i0 + i;
        float4 ef = ((const float4*)(edge + ((size_t)b * Nn + row) * Nn))[lane];
        int4  av  = ((const int4*)(adj  + ((size_t)b * Nn + row) * Nn))[lane];
        float si = ss1[i];
        int j0 = lane * 4;
        float v0 = si + ss2[j0 + 0] + ef.x * ae; v0 = v0 >= 0.f ? v0 : 0.2f * v0; v0 = av.x > 0 ? v0 : -9e15f;
        float v1 = si + ss2[j0 + 1] + ef.y * ae; v1 = v1 >= 0.f ? v1 : 0.2f * v1; v1 = av.y > 0 ? v1 : -9e15f;
        float v2 = si + ss2[j0 + 2] + ef.z * ae; v2 = v2 >= 0.f ? v2 : 0.2f * v2; v2 = av.z > 0 ? v2 : -9e15f;
        float v3 = si + ss2[j0 + 3] + ef.w * ae; v3 = v3 >= 0.f ? v3 : 0.2f * v3; v3 = av.w > 0 ? v3 : -9e15f;
        float e0 = __expf(v0), e1 = __expf(v1), e2 = __expf(v2), e3 = __expf(v3);
        float s = e0 + e1 + e2 + e3;
#pragma unroll
        for (int o = 16; o; o >>= 1) s += __shfl_xor_sync(0xffffffffu, s, o);
        float inv = 1.f / s;
        uint4 o4;
        o4.x = to_tf32(e0 * inv); o4.y = to_tf32(e1 * inv);
        o4.z = to_tf32(e2 * inv); o4.w = to_tf32(e3 * inv);
        *(uint4*)&sAtt[i * AT_STR + lane * 4] = o4;
    }
    __syncthreads();

    int wr = warp >> 2, wc = warp & 3;
    int lr4 = lane >> 2, lc4 = lane & 3;

#pragma unroll
    for (int ch = 0; ch < 2; ch++) {
        if (ch == 1) {
            __syncthreads();
            for (int i = tid; i < 128 * 8; i += 256) {
                int r = i >> 3, c = (i & 7) * 4;
                *(uint4*)&sWh[r * WCH_STR + c] = *(const uint4*)(whp + (size_t)r * HID + 32 + c);
            }
            __syncthreads();
        }

        float acc[2][4];
#pragma unroll
        for (int mt = 0; mt < 2; mt++)
#pragma unroll
            for (int i = 0; i < 4; i++) acc[mt][i] = 0.f;

#pragma unroll
        for (int kk = 0; kk < 128; kk += 8) {
            u32 afr[2][4], bfr[2];
#pragma unroll
            for (int mt = 0; mt < 2; mt++) {
                int r0 = wr * 32 + mt * 16 + lr4;
                int c0 = kk + lc4;
                afr[mt][0] = sAtt[r0 * AT_STR + c0];
                afr[mt][1] = sAtt[(r0 + 8) * AT_STR + c0];
                afr[mt][2] = sAtt[r0 * AT_STR + c0 + 4];
                afr[mt][3] = sAtt[(r0 + 8) * AT_STR + c0 + 4];
            }
            {
                int col = wc * 8 + lr4;
                bfr[0] = sWh[(kk + lc4) * WCH_STR + col];
                bfr[1] = sWh[(kk + lc4 + 4) * WCH_STR + col];
            }
#pragma unroll
            for (int mt = 0; mt < 2; mt++)
                mma_tf32(acc[mt], afr[mt], bfr);
        }

#pragma unroll
        for (int mt = 0; mt < 2; mt++) {
            int col = ch * 32 + wc * 8 + lc4 * 2;
#pragma unroll
            for (int half = 0; half < 2; half++) {
                int i = i0 + wr * 32 + mt * 16 + lr4 + half * 8;
                uint2 v;
                v.x = to_tf32(elu1(acc[mt][half * 2]));
                v.y = to_tf32(elu1(acc[mt][half * 2 + 1]));
                *(uint2*)(g_x + ((size_t)b * Nn + i) * HID + hh * NHID + col) = v;
            }
        }
    }
}

// ---------------------------------------------------------------------------
// final: warp per (b,t).
// ---------------------------------------------------------------------------
__global__ __launch_bounds__(256) void final_kernel(
    const float* __restrict__ X, const float* __restrict__ W,
    const float* __restrict__ bias, float* __restrict__ out)
{
    int gw = (blockIdx.x * blockDim.x + threadIdx.x) >> 5;
    int lane = threadIdx.x & 31;
    if (gw >= Bq * TASKS) return;
    int b = gw / TASKS, t = gw - b * TASKS;
    const float* x = X + (size_t)b * HID;
    float s = 0.f;
#pragma unroll
    for (int i = 0; i < 16; i++) {
        int d = lane + i * 32;
        s += x[d] * W[d * TASKS + t];
    }
#pragma unroll
    for (int o = 16; o; o >>= 1) s += __shfl_xor_sync(0xffffffffu, s, o);
    if (lane == 0) out[gw] = s + bias[t];
}

// ---------------------------------------------------------------------------
extern "C" void kernel_launch(void* const* d_in, const int* in_sizes, int n_in,
                              void* d_out, int out_size)
{
    const float* h        = (const float*)d_in[0];
    const int*   adj      = (const int*)d_in[1];
    const float* edge     = (const float*)d_in[2];
    const float* fp       = (const float*)d_in[3];
    const float* W_heads  = (const float*)d_in[4];
    const float* a1_heads = (const float*)d_in[5];
    const float* a2_heads = (const float*)d_in[6];
    const float* ae_heads = (const float*)d_in[7];
    const float* W_out    = (const float*)d_in[8];
    const float* a1_out   = (const float*)d_in[9];
    const float* a2_out   = (const float*)d_in[10];
    const float* ae_out   = (const float*)d_in[11];
    const float* fc1_w    = (const float*)d_in[12];
    const float* fc1_b    = (const float*)d_in[13];
    const float* fc2_w    = (const float*)d_in[14];
    const float* fc2_b    = (const float*)d_in[15];
    const float* q_w      = (const float*)d_in[16];
    const float* q_b      = (const float*)d_in[17];
    // k_w (18), k_b (19) unused: softmax over size-1 axis == 1 -> fused = q+v
    const float* v_w      = (const float*)d_in[20];
    const float* v_b      = (const float*)d_in[21];
    const float* o_w      = (const float*)d_in[22];
    const float* o_b      = (const float*)d_in[23];
    const float* ffn1_w   = (const float*)d_in[24];
    const float* ffn1_b   = (const float*)d_in[25];
    const float* ffn2_w   = (const float*)d_in[26];
    const float* ffn2_b   = (const float*)d_in[27];
    float* out = (float*)d_out;

    float *gat, *fpnh, *fpn, *buf1, *buf2;
    float *s1p, *s2p, *t1p, *t2p;
    u32 *hc, *Wcat, *Wo, *Wh, *x, *Wx;
    cudaGetSymbolAddress((void**)&hc, g_hc);
    cudaGetSymbolAddress((void**)&Wcat, g_Wcat);
    cudaGetSymbolAddress((void**)&Wo, g_Wo);
    cudaGetSymbolAddress((void**)&Wh, g_Wh);
    cudaGetSymbolAddress((void**)&x, g_x);
    cudaGetSymbolAddress((void**)&Wx, g_Wx);
    cudaGetSymbolAddress((void**)&gat, g_gat);
    cudaGetSymbolAddress((void**)&fpnh, g_fpnh);
    cudaGetSymbolAddress((void**)&fpn, g_fpn);
    cudaGetSymbolAddress((void**)&buf1, g_buf1);
    cudaGetSymbolAddress((void**)&buf2, g_buf2);
    cudaGetSymbolAddress((void**)&s1p, g_s1);
    cudaGetSymbolAddress((void**)&s2p, g_s2);
    cudaGetSymbolAddress((void**)&t1p, g_t1p);
    cudaGetSymbolAddress((void**)&t2p, g_t2p);

    const int ATT1_SMEM = (128 * WCH_STR + 64 * AT_STR + 192) * 4;
    cudaFuncSetAttribute(attn1_kernel, cudaFuncAttributeMaxDynamicSharedMemorySize, ATT1_SMEM);
    cudaFuncSetAttribute(sgemm_tc_kernel, cudaFuncAttributeMaxDynamicSharedMemorySize, SGEMM_SMEM);

    const int M1 = Bq * Nn;  // 65536

    // 1. preconversions (all independent)
    wcat_kernel<<<(NHEADS * F_IN * NHID + 255) / 256, 256>>>(W_heads);
    conv_tf32_kernel<<<(M1 * F_IN / 4 + 255) / 256, 256>>>(h, hc, M1 * F_IN / 4);
    conv_tf32_kernel<<<(HID * HID / 4 + 255) / 256, 256>>>(W_out, Wo, HID * HID / 4);

    // 2. Wh = hc @ Wcat (all-tf32) + fused s1/s2 epilogue
    {
        dim3 grid(HID / 256, M1 / 128);
        sgemm_tc_kernel<<<grid, 256, SGEMM_SMEM>>>(hc, Wcat, Wh, M1, HID, F_IN,
                                                   1, a1_heads, a2_heads, s1p, s2p);
    }

    // 3. attn1 (u32 Wh in, u32 x out)
    attn1_kernel<<<Bq * NHEADS * 2, 256, ATT1_SMEM>>>(ae_heads, adj, edge);

    // 4. Wx = x @ Wo (all-tf32) + fused t1/t2 partials
    {
        dim3 grid(HID / 256, M1 / 128);
        sgemm_tc_kernel<<<grid, 256, SGEMM_SMEM>>>(x, Wo, Wx, M1, HID, HID,
                                                   2, a1_out, a2_out, t1p, t2p);
    }

    // 5. attn2 split
    softmax2_kernel<<<Bq * 2, 256>>>(ae_out, adj, edge);
    {
        dim3 grid(HID / 128, Bq);
        av2_kernel<<<grid, 256>>>();
    }

    // 6. FPN (exact fp32 tails)
    {
        dim3 grid(HID / 64, Bq / 64);
        tail_gemm_kernel<<<grid, 256>>>(fp, nullptr, fc1_w, nullptr, fc1_b, nullptr,
                                        fpnh, Bq, HID, FP_DIM, FP_DIM, 1 | 2);
        tail_gemm_kernel<<<grid, 256>>>(fpnh, nullptr, fc2_w, nullptr, fc2_b, nullptr,
                                        fpn, Bq, HID, HID, HID, 1);
    }

    // 7. fusion + FFN
    {
        dim3 grid(HID / 64, Bq / 64);
        tail_gemm_kernel<<<grid, 256>>>(gat, fpn, q_w, v_w, q_b, v_b,
                                        buf1, Bq, HID, 2 * HID, HID, 1);
        tail_gemm_kernel<<<grid, 256>>>(buf1, nullptr, o_w, nullptr, o_b, nullptr,
                                        buf2, Bq, HID, HID, HID, 1 | 2);
        tail_gemm_kernel<<<grid, 256>>>(buf2, nullptr, ffn1_w, nullptr, ffn1_b, nullptr,
                                        buf1, Bq, HID, HID, HID, 1 | 2);
    }

    // 8. final projection
    final_kernel<<<(Bq * TASKS * 32 + 255) / 256, 256>>>(buf1, ffn2_w, ffn2_b, out);
}